// round 6
// baseline (speedup 1.0000x reference)
#include <cuda_runtime.h>
#include <cstdint>

#define N_NODES 50000
#define N_EDGES 800000
#define NFEAT   256
#define NHID    128
#define ZDIM    32
#define NPAIRS  10000

// ---- scratch (static device globals; no allocation at runtime) ----
__device__ float g_buf_h [(size_t)N_NODES * NHID];
__device__ float g_buf_x0[(size_t)N_NODES * NHID];
__device__ float g_buf_x1[(size_t)N_NODES * NHID];
__device__ int   g_rowptr[N_NODES + 1];
__device__ float g_feat[(size_t)NPAIRS * ZDIM];

// ------------------------------------------------------------------
__global__ void rowptr_kernel(const int* __restrict__ row) {
    int r = blockIdx.x * blockDim.x + threadIdx.x;
    if (r > N_NODES) return;
    int lo = 0, hi = N_EDGES;
    while (lo < hi) {
        int mid = (lo + hi) >> 1;
        if (row[mid] < r) lo = mid + 1; else hi = mid;
    }
    g_rowptr[r] = lo;
}

// ------------------------------------------------------------------
// bf16 split helpers
// ------------------------------------------------------------------
__device__ __forceinline__ uint32_t pack2bf(float lo, float hi) {
    uint32_t r;
    asm("cvt.rn.bf16x2.f32 %0, %1, %2;" : "=r"(r) : "f"(hi), "f"(lo));
    return r;
}
__device__ __forceinline__ float2 unpack_bf(uint32_t p) {
    return make_float2(__uint_as_float(p << 16),
                       __uint_as_float(p & 0xffff0000u));
}

__device__ __forceinline__ void mma_bf16(
    float* d, uint32_t a0, uint32_t a1, uint32_t a2, uint32_t a3,
    uint32_t b0, uint32_t b1)
{
    asm volatile(
        "mma.sync.aligned.m16n8k16.row.col.f32.bf16.bf16.f32 "
        "{%0,%1,%2,%3}, {%4,%5,%6,%7}, {%8,%9}, {%0,%1,%2,%3};\n"
        : "+f"(d[0]), "+f"(d[1]), "+f"(d[2]), "+f"(d[3])
        : "r"(a0), "r"(a1), "r"(a2), "r"(a3), "r"(b0), "r"(b1));
}

// fragment position remap: column e -> (e&7)*16 + (e>>3)   (pad 132 words)
__device__ __forceinline__ int fragpos(int e) {
    return (e & 7) * 16 + (e >> 3);
}

// ------------------------------------------------------------------
// Encoder GEMM: C[M,128] = A[M,K] @ B[K,128], split-bf16 3-MMA.
// BM=128, BK=32, 256 threads, 8 warps x 16 rows x full N=128.
// B planes stored in transposed-fragment layout for uint4 LDS.
// ------------------------------------------------------------------
__global__ __launch_bounds__(256, 2) void gemm_bf16_n128(
    const float* __restrict__ A, const float* __restrict__ B,
    float* __restrict__ C, int M, int K)
{
    __shared__ uint32_t sAb[128][17], sAs[128][17];   // [row][kpair]
    __shared__ uint32_t sBb[16 * 132], sBs[16 * 132]; // [kpair][fragpos]

    int tid  = threadIdx.x;
    int lane = tid & 31, warp = tid >> 5;
    int g = lane >> 2, t4 = lane & 3;
    int r0 = warp * 16 + g;
    int row0 = blockIdx.x * 128;

    float acc[16][4];
#pragma unroll
    for (int nt = 0; nt < 16; nt++)
#pragma unroll
        for (int j = 0; j < 4; j++) acc[nt][j] = 0.f;

    for (int k0 = 0; k0 < K; k0 += 32) {
        __syncthreads();
        // A tile: 128 rows x 32 k, split+pack along k
#pragma unroll
        for (int u = 0; u < 4; u++) {
            int i = tid + u * 256;
            int r = i >> 3, q = i & 7;
            int gr = row0 + r;
            float4 v = (gr < M)
                ? __ldg((const float4*)(A + (size_t)gr * K + k0 + 4 * q))
                : make_float4(0.f, 0.f, 0.f, 0.f);
            uint32_t p0 = pack2bf(v.x, v.y);
            uint32_t p1 = pack2bf(v.z, v.w);
            float2 f0 = unpack_bf(p0), f1 = unpack_bf(p1);
            sAb[r][2 * q]     = p0;
            sAb[r][2 * q + 1] = p1;
            sAs[r][2 * q]     = pack2bf(v.x - f0.x, v.y - f0.y);
            sAs[r][2 * q + 1] = pack2bf(v.z - f1.x, v.w - f1.y);
        }
        // B tile: 32 k x 128 cols, pack pairs along k, remapped layout
#pragma unroll
        for (int u = 0; u < 2; u++) {
            int i = tid + u * 256;
            int kp = i >> 5, c4 = (i & 31) * 4;
            float4 w0 = __ldg((const float4*)(B + (size_t)(k0 + 2 * kp) * 128 + c4));
            float4 w1 = __ldg((const float4*)(B + (size_t)(k0 + 2 * kp + 1) * 128 + c4));
            float lo[4] = {w0.x, w0.y, w0.z, w0.w};
            float hi[4] = {w1.x, w1.y, w1.z, w1.w};
#pragma unroll
            for (int j = 0; j < 4; j++) {
                int pos = kp * 132 + fragpos(c4 + j);
                uint32_t pb = pack2bf(lo[j], hi[j]);
                float2 f = unpack_bf(pb);
                sBb[pos] = pb;
                sBs[pos] = pack2bf(lo[j] - f.x, hi[j] - f.y);
            }
        }
        __syncthreads();

#pragma unroll
        for (int ks = 0; ks < 2; ks++) {
            int kp0 = ks * 8;
            uint32_t ab0 = sAb[r0    ][kp0 + t4];
            uint32_t ab1 = sAb[r0 + 8][kp0 + t4];
            uint32_t ab2 = sAb[r0    ][kp0 + t4 + 4];
            uint32_t ab3 = sAb[r0 + 8][kp0 + t4 + 4];
            uint32_t as0 = sAs[r0    ][kp0 + t4];
            uint32_t as1 = sAs[r0 + 8][kp0 + t4];
            uint32_t as2 = sAs[r0    ][kp0 + t4 + 4];
            uint32_t as3 = sAs[r0 + 8][kp0 + t4 + 4];
            const uint4* rb0 = (const uint4*)&sBb[(kp0 + t4    ) * 132 + g * 16];
            const uint4* rb1 = (const uint4*)&sBb[(kp0 + t4 + 4) * 132 + g * 16];
            const uint4* rs0 = (const uint4*)&sBs[(kp0 + t4    ) * 132 + g * 16];
            const uint4* rs1 = (const uint4*)&sBs[(kp0 + t4 + 4) * 132 + g * 16];
#pragma unroll
            for (int nt4 = 0; nt4 < 4; nt4++) {
                uint4 b0 = rb0[nt4], b1 = rb1[nt4];
                uint4 s0 = rs0[nt4], s1 = rs1[nt4];
                uint32_t bb0[4] = {b0.x, b0.y, b0.z, b0.w};
                uint32_t bb1[4] = {b1.x, b1.y, b1.z, b1.w};
                uint32_t bs0[4] = {s0.x, s0.y, s0.z, s0.w};
                uint32_t bs1[4] = {s1.x, s1.y, s1.z, s1.w};
#pragma unroll
                for (int q = 0; q < 4; q++) {
                    int nt = nt4 * 4 + q;
                    mma_bf16(acc[nt], ab0, ab1, ab2, ab3, bb0[q], bb1[q]);
                    mma_bf16(acc[nt], as0, as1, as2, as3, bb0[q], bb1[q]);
                    mma_bf16(acc[nt], ab0, ab1, ab2, ab3, bs0[q], bs1[q]);
                }
            }
        }
    }

#pragma unroll
    for (int nt = 0; nt < 16; nt++) {
        int c = nt * 8 + 2 * t4;
        int gr0 = row0 + r0, gr1 = gr0 + 8;
        if (gr0 < M)
            *(float2*)(C + (size_t)gr0 * 128 + c) = make_float2(acc[nt][0], acc[nt][1]);
        if (gr1 < M)
            *(float2*)(C + (size_t)gr1 * 128 + c) = make_float2(acc[nt][2], acc[nt][3]);
    }
}

// ------------------------------------------------------------------
// SpMM: one warp per destination row, 4-edge unroll, L1-bypass gathers
// ------------------------------------------------------------------
__device__ __forceinline__ float4 ldcg4(const float4* p) {
    float4 v;
    asm volatile("ld.global.cg.v4.f32 {%0,%1,%2,%3}, [%4];"
                 : "=f"(v.x), "=f"(v.y), "=f"(v.z), "=f"(v.w) : "l"(p));
    return v;
}

__global__ __launch_bounds__(256) void spmm_kernel(
    const float* __restrict__ H, const int* __restrict__ col,
    const float* __restrict__ val, const float* __restrict__ bias,
    const float* __restrict__ res, float* __restrict__ out)
{
    int w = (blockIdx.x * blockDim.x + threadIdx.x) >> 5;
    if (w >= N_NODES) return;
    int lane = threadIdx.x & 31;

    const float4* Hv = (const float4*)H;
    float4 acc = make_float4(0.f, 0.f, 0.f, 0.f);
    int s = g_rowptr[w], e = g_rowptr[w + 1];
    int i = s;
    for (; i + 3 < e; i += 4) {
        int   c0 = __ldg(&col[i]),     c1 = __ldg(&col[i + 1]);
        int   c2 = __ldg(&col[i + 2]), c3 = __ldg(&col[i + 3]);
        float v0 = __ldg(&val[i]),     v1 = __ldg(&val[i + 1]);
        float v2 = __ldg(&val[i + 2]), v3 = __ldg(&val[i + 3]);
        float4 h0 = ldcg4(&Hv[(size_t)c0 * 32 + lane]);
        float4 h1 = ldcg4(&Hv[(size_t)c1 * 32 + lane]);
        float4 h2 = ldcg4(&Hv[(size_t)c2 * 32 + lane]);
        float4 h3 = ldcg4(&Hv[(size_t)c3 * 32 + lane]);
        acc.x = fmaf(v0, h0.x, acc.x); acc.y = fmaf(v0, h0.y, acc.y);
        acc.z = fmaf(v0, h0.z, acc.z); acc.w = fmaf(v0, h0.w, acc.w);
        acc.x = fmaf(v1, h1.x, acc.x); acc.y = fmaf(v1, h1.y, acc.y);
        acc.z = fmaf(v1, h1.z, acc.z); acc.w = fmaf(v1, h1.w, acc.w);
        acc.x = fmaf(v2, h2.x, acc.x); acc.y = fmaf(v2, h2.y, acc.y);
        acc.z = fmaf(v2, h2.z, acc.z); acc.w = fmaf(v2, h2.w, acc.w);
        acc.x = fmaf(v3, h3.x, acc.x); acc.y = fmaf(v3, h3.y, acc.y);
        acc.z = fmaf(v3, h3.z, acc.z); acc.w = fmaf(v3, h3.w, acc.w);
    }
    for (; i < e; i++) {
        int   c0 = __ldg(&col[i]);
        float v0 = __ldg(&val[i]);
        float4 h0 = ldcg4(&Hv[(size_t)c0 * 32 + lane]);
        acc.x = fmaf(v0, h0.x, acc.x); acc.y = fmaf(v0, h0.y, acc.y);
        acc.z = fmaf(v0, h0.z, acc.z); acc.w = fmaf(v0, h0.w, acc.w);
    }

    float4 bb = __ldg(&((const float4*)bias)[lane]);
    float4 o;
    o.x = fmaxf(acc.x + bb.x, 0.f);
    o.y = fmaxf(acc.y + bb.y, 0.f);
    o.z = fmaxf(acc.z + bb.z, 0.f);
    o.w = fmaxf(acc.w + bb.w, 0.f);
    size_t vbase = (size_t)w * 32 + lane;
    if (res) {
        float4 rv = __ldg(&((const float4*)res)[vbase]);
        o.x += rv.x; o.y += rv.y; o.z += rv.z; o.w += rv.w;
    }
    ((float4*)out)[vbase] = o;
}

// ------------------------------------------------------------------
// Bilinear stage 1: tile = 128 pairs x (KC k-slices), split-bf16 3-MMA.
// W planes in transposed-fragment layout for uint4 LDS.
// ------------------------------------------------------------------
#define KC 4
#define BIL_SMEM_WORDS (128 * 132 + 128 * 132 + 2 * 16 * 132)
#define BIL_SMEM_BYTES (BIL_SMEM_WORDS * 4)

__global__ __launch_bounds__(256, 1) void bilinear_kernel(
    const float* __restrict__ latent, const int* __restrict__ idx,
    const float* __restrict__ bilw, float* __restrict__ feat)
{
    extern __shared__ float smem[];
    float*    sA  = smem;                          // [128][132] fp32 a rows
    float*    sB  = sA + 128 * 132;                // [128][132] fp32 b rows
    uint32_t* sWb = (uint32_t*)(sB + 128 * 132);   // [16 kpair][132 fragpos]
    uint32_t* sWs = sWb + 16 * 132;

    int tid  = threadIdx.x;
    int lane = tid & 31, warp = tid >> 5;
    int p0 = blockIdx.x * 128;
    int g = lane >> 2, t4 = lane & 3;
    int r0 = warp * 16 + g;                        // warps 0..7 cover rows 0..127

    // gather A and B pair rows (fp32)
    for (int i = tid; i < 128 * 32; i += 256) {
        int p = i >> 5, c8 = (i & 31) * 4;
        int pg = p0 + p; if (pg >= NPAIRS) pg = NPAIRS - 1;
        int na = __ldg(&idx[pg]);
        int nb = __ldg(&idx[NPAIRS + pg]);
        float4 va = __ldg((const float4*)(latent + (size_t)na * 128 + c8));
        float4 vb = __ldg((const float4*)(latent + (size_t)nb * 128 + c8));
        *(float4*)&sA[p * 132 + c8] = va;
        *(float4*)&sB[p * 132 + c8] = vb;
    }

    for (int kk = 0; kk < KC; kk++) {
        int k = blockIdx.y * KC + kk;

        float acc[16][4];
#pragma unroll
        for (int nt = 0; nt < 16; nt++)
#pragma unroll
            for (int j = 0; j < 4; j++) acc[nt][j] = 0.f;

        for (int k0 = 0; k0 < 128; k0 += 32) {
            __syncthreads();   // sA/sB ready (1st iter); sW planes free (later)
#pragma unroll
            for (int u = 0; u < 2; u++) {
                int i = tid + u * 256;
                int kp = i >> 5, c4 = (i & 31) * 4;
                const float* wp0 = bilw + ((size_t)k * 128 + k0 + 2 * kp) * 128 + c4;
                float4 w0 = __ldg((const float4*)wp0);
                float4 w1 = __ldg((const float4*)(wp0 + 128));
                float lo[4] = {w0.x, w0.y, w0.z, w0.w};
                float hi[4] = {w1.x, w1.y, w1.z, w1.w};
#pragma unroll
                for (int j = 0; j < 4; j++) {
                    int pos = kp * 132 + fragpos(c4 + j);
                    uint32_t pb = pack2bf(lo[j], hi[j]);
                    float2 f = unpack_bf(pb);
                    sWb[pos] = pb;
                    sWs[pos] = pack2bf(lo[j] - f.x, hi[j] - f.y);
                }
            }
            __syncthreads();

#pragma unroll
            for (int ks = 0; ks < 2; ks++) {
                int cb = k0 + ks * 16 + 2 * t4;
                float xl0 = sA[(r0    ) * 132 + cb],     xh0 = sA[(r0    ) * 132 + cb + 1];
                float xl1 = sA[(r0 + 8) * 132 + cb],     xh1 = sA[(r0 + 8) * 132 + cb + 1];
                float xl2 = sA[(r0    ) * 132 + cb + 8], xh2 = sA[(r0    ) * 132 + cb + 9];
                float xl3 = sA[(r0 + 8) * 132 + cb + 8], xh3 = sA[(r0 + 8) * 132 + cb + 9];
                uint32_t ab0 = pack2bf(xl0, xh0);
                uint32_t ab1 = pack2bf(xl1, xh1);
                uint32_t ab2 = pack2bf(xl2, xh2);
                uint32_t ab3 = pack2bf(xl3, xh3);
                float2 f0 = unpack_bf(ab0), f1 = unpack_bf(ab1);
                float2 f2 = unpack_bf(ab2), f3 = unpack_bf(ab3);
                uint32_t as0 = pack2bf(xl0 - f0.x, xh0 - f0.y);
                uint32_t as1 = pack2bf(xl1 - f1.x, xh1 - f1.y);
                uint32_t as2 = pack2bf(xl2 - f2.x, xh2 - f2.y);
                uint32_t as3 = pack2bf(xl3 - f3.x, xh3 - f3.y);
                int kp0 = ks * 8;
                const uint4* rb0 = (const uint4*)&sWb[(kp0 + t4    ) * 132 + g * 16];
                const uint4* rb1 = (const uint4*)&sWb[(kp0 + t4 + 4) * 132 + g * 16];
                const uint4* rs0 = (const uint4*)&sWs[(kp0 + t4    ) * 132 + g * 16];
                const uint4* rs1 = (const uint4*)&sWs[(kp0 + t4 + 4) * 132 + g * 16];
#pragma unroll
                for (int nt4 = 0; nt4 < 4; nt4++) {
                    uint4 b0 = rb0[nt4], b1 = rb1[nt4];
                    uint4 s0 = rs0[nt4], s1 = rs1[nt4];
                    uint32_t bb0[4] = {b0.x, b0.y, b0.z, b0.w};
                    uint32_t bb1[4] = {b1.x, b1.y, b1.z, b1.w};
                    uint32_t bs0[4] = {s0.x, s0.y, s0.z, s0.w};
                    uint32_t bs1[4] = {s1.x, s1.y, s1.z, s1.w};
#pragma unroll
                    for (int q = 0; q < 4; q++) {
                        int nt = nt4 * 4 + q;
                        mma_bf16(acc[nt], ab0, ab1, ab2, ab3, bb0[q], bb1[q]);
                        mma_bf16(acc[nt], as0, as1, as2, as3, bb0[q], bb1[q]);
                        mma_bf16(acc[nt], ab0, ab1, ab2, ab3, bs0[q], bs1[q]);
                    }
                }
            }
        }

        // epilogue: each warp fully owns rows r0 / r0+8 -> plain reduce
        float plo = 0.f, phi = 0.f;
#pragma unroll
        for (int nt = 0; nt < 16; nt++) {
            int c = nt * 8 + 2 * t4;
            plo = fmaf(acc[nt][0], sB[(r0    ) * 132 + c    ], plo);
            plo = fmaf(acc[nt][1], sB[(r0    ) * 132 + c + 1], plo);
            phi = fmaf(acc[nt][2], sB[(r0 + 8) * 132 + c    ], phi);
            phi = fmaf(acc[nt][3], sB[(r0 + 8) * 132 + c + 1], phi);
        }
        plo += __shfl_xor_sync(0xffffffffu, plo, 1);
        plo += __shfl_xor_sync(0xffffffffu, plo, 2);
        phi += __shfl_xor_sync(0xffffffffu, phi, 1);
        phi += __shfl_xor_sync(0xffffffffu, phi, 2);
        if (t4 == 0) {
            int pg0 = p0 + r0;
            int pg1 = p0 + r0 + 8;
            if (pg0 < NPAIRS) feat[(size_t)pg0 * ZDIM + k] = plo;
            if (pg1 < NPAIRS) feat[(size_t)pg1 * ZDIM + k] = phi;
        }
    }
}

// ------------------------------------------------------------------
// Stage 2: tiny MLP on feat -> predictions
// ------------------------------------------------------------------
__device__ __forceinline__ float elu1(float x) {
    return x > 0.f ? x : expm1f(x);
}

__global__ __launch_bounds__(256) void mlp_kernel(
    const float* __restrict__ feat, const float* __restrict__ bilb,
    const float* __restrict__ dw1, const float* __restrict__ db1,
    const float* __restrict__ dw2, const float* __restrict__ db2,
    float* __restrict__ pred)
{
    int p = blockIdx.x * blockDim.x + threadIdx.x;
    if (p >= NPAIRS) return;

    float f[ZDIM];
#pragma unroll
    for (int k = 0; k < ZDIM; k++)
        f[k] = elu1(feat[(size_t)p * ZDIM + k] + __ldg(&bilb[k]));

    float o = __ldg(&db2[0]);
#pragma unroll
    for (int kk = 0; kk < ZDIM; kk++) {
        float s = __ldg(&db1[kk]);
#pragma unroll
        for (int j = 0; j < ZDIM; j++)
            s = fmaf(f[j], __ldg(&dw1[j * ZDIM + kk]), s);
        o = fmaf(elu1(s), __ldg(&dw2[kk]), o);
    }
    pred[p] = o;
}

// ------------------------------------------------------------------
extern "C" void kernel_launch(void* const* d_in, const int* in_sizes, int n_in,
                              void* d_out, int out_size)
{
    const float* features = (const float*)d_in[0];
    const int*   adj_row  = (const int*)  d_in[1];
    const int*   adj_col  = (const int*)  d_in[2];
    const float* adj_val  = (const float*)d_in[3];
    const int*   idx      = (const int*)  d_in[4];
    const float* W0   = (const float*)d_in[5];
    const float* b0   = (const float*)d_in[6];
    const float* W1   = (const float*)d_in[7];
    const float* b1   = (const float*)d_in[8];
    const float* W2   = (const float*)d_in[9];
    const float* b2   = (const float*)d_in[10];
    const float* bilw = (const float*)d_in[11];
    const float* bilb = (const float*)d_in[12];
    const float* dw1  = (const float*)d_in[13];
    const float* db1  = (const float*)d_in[14];
    const float* dw2  = (const float*)d_in[15];
    const float* db2  = (const float*)d_in[16];

    float* out    = (float*)d_out;
    float* pred   = out;            // [NPAIRS]
    float* latent = out + NPAIRS;   // [N_NODES * NHID]

    float* h;  cudaGetSymbolAddress((void**)&h,  g_buf_h);
    float* x0; cudaGetSymbolAddress((void**)&x0, g_buf_x0);
    float* x1; cudaGetSymbolAddress((void**)&x1, g_buf_x1);
    float* ft; cudaGetSymbolAddress((void**)&ft, g_feat);

    static int smem_set = 0;
    if (!smem_set) {
        cudaFuncSetAttribute(bilinear_kernel,
                             cudaFuncAttributeMaxDynamicSharedMemorySize,
                             BIL_SMEM_BYTES);
        smem_set = 1;
    }

    rowptr_kernel<<<(N_NODES + 1 + 255) / 256, 256>>>(adj_row);

    const int gemm_grid = (N_NODES + 127) / 128;
    const int spmm_grid = (N_NODES * 32 + 255) / 256;

    gemm_bf16_n128<<<gemm_grid, 256>>>(features, W0, h, N_NODES, NFEAT);
    spmm_kernel<<<spmm_grid, 256>>>(h, adj_col, adj_val, b0, nullptr, x0);

    gemm_bf16_n128<<<gemm_grid, 256>>>(x0, W1, h, N_NODES, NHID);
    spmm_kernel<<<spmm_grid, 256>>>(h, adj_col, adj_val, b1, x0, x1);

    gemm_bf16_n128<<<gemm_grid, 256>>>(x1, W2, h, N_NODES, NHID);
    spmm_kernel<<<spmm_grid, 256>>>(h, adj_col, adj_val, b2, x1, latent);

    dim3 bil_grid((NPAIRS + 127) / 128, ZDIM / KC);
    bilinear_kernel<<<bil_grid, 256, BIL_SMEM_BYTES>>>(latent, idx, bilw, ft);
    mlp_kernel<<<(NPAIRS + 255) / 256, 256>>>(ft, bilb, dw1, db1, dw2, db2, pred);
}

// round 7
// speedup vs baseline: 1.0011x; 1.0011x over previous
#include <cuda_runtime.h>
#include <cstdint>

#define N_NODES 50000
#define N_EDGES 800000
#define NFEAT   256
#define NHID    128
#define ZDIM    32
#define NPAIRS  10000

// ---- scratch (static device globals; no allocation at runtime) ----
__device__ float g_buf_h [(size_t)N_NODES * NHID];
__device__ float g_buf_x0[(size_t)N_NODES * NHID];
__device__ float g_buf_x1[(size_t)N_NODES * NHID];
__device__ int   g_rowptr[N_NODES + 1];
__device__ float g_feat[(size_t)NPAIRS * ZDIM];

// ------------------------------------------------------------------
__global__ void rowptr_kernel(const int* __restrict__ row) {
    int r = blockIdx.x * blockDim.x + threadIdx.x;
    if (r > N_NODES) return;
    int lo = 0, hi = N_EDGES;
    while (lo < hi) {
        int mid = (lo + hi) >> 1;
        if (row[mid] < r) lo = mid + 1; else hi = mid;
    }
    g_rowptr[r] = lo;
}

// ------------------------------------------------------------------
// bf16 split helpers
// ------------------------------------------------------------------
__device__ __forceinline__ uint32_t pack2bf(float lo, float hi) {
    uint32_t r;
    asm("cvt.rn.bf16x2.f32 %0, %1, %2;" : "=r"(r) : "f"(hi), "f"(lo));
    return r;
}
__device__ __forceinline__ float2 unpack_bf(uint32_t p) {
    return make_float2(__uint_as_float(p << 16),
                       __uint_as_float(p & 0xffff0000u));
}

__device__ __forceinline__ void mma_bf16(
    float* d, uint32_t a0, uint32_t a1, uint32_t a2, uint32_t a3,
    uint32_t b0, uint32_t b1)
{
    asm volatile(
        "mma.sync.aligned.m16n8k16.row.col.f32.bf16.bf16.f32 "
        "{%0,%1,%2,%3}, {%4,%5,%6,%7}, {%8,%9}, {%0,%1,%2,%3};\n"
        : "+f"(d[0]), "+f"(d[1]), "+f"(d[2]), "+f"(d[3])
        : "r"(a0), "r"(a1), "r"(a2), "r"(a3), "r"(b0), "r"(b1));
}

// ------------------------------------------------------------------
// Encoder GEMM: C[M,128] = A[M,K] @ B[K,128], split-bf16 3-MMA.
// BM=64, BK=32, 128 threads (4 warps x 16 rows x full N=128).
// 4 CTAs/SM (regfile-exact) for latency hiding.
// ------------------------------------------------------------------
__global__ __launch_bounds__(128, 4) void gemm_bf16_n128(
    const float* __restrict__ A, const float* __restrict__ B,
    float* __restrict__ C, int M, int K)
{
    __shared__ uint32_t sAb[64][17], sAs[64][17];     // [row][kpair]
    __shared__ uint32_t sBb[16][136], sBs[16][136];   // [kpair][col]

    int tid  = threadIdx.x;
    int lane = tid & 31, warp = tid >> 5;
    int g = lane >> 2, t4 = lane & 3;
    int r0 = warp * 16 + g;                 // warps 0..3 cover rows 0..63
    int row0 = blockIdx.x * 64;

    float acc[16][4];
#pragma unroll
    for (int nt = 0; nt < 16; nt++)
#pragma unroll
        for (int j = 0; j < 4; j++) acc[nt][j] = 0.f;

    for (int k0 = 0; k0 < K; k0 += 32) {
        __syncthreads();
        // A tile: 64 rows x 32 k, split+pack along k
#pragma unroll
        for (int u = 0; u < 4; u++) {
            int i = tid + u * 128;
            int r = i >> 3, q = i & 7;
            int gr = row0 + r;
            float4 v = (gr < M)
                ? __ldg((const float4*)(A + (size_t)gr * K + k0 + 4 * q))
                : make_float4(0.f, 0.f, 0.f, 0.f);
            uint32_t p0 = pack2bf(v.x, v.y);
            uint32_t p1 = pack2bf(v.z, v.w);
            float2 f0 = unpack_bf(p0), f1 = unpack_bf(p1);
            sAb[r][2 * q]     = p0;
            sAb[r][2 * q + 1] = p1;
            sAs[r][2 * q]     = pack2bf(v.x - f0.x, v.y - f0.y);
            sAs[r][2 * q + 1] = pack2bf(v.z - f1.x, v.w - f1.y);
        }
        // B tile: 32 k x 128 cols, pack pairs along k
#pragma unroll
        for (int u = 0; u < 4; u++) {
            int i = tid + u * 128;
            int kp = i >> 5, c4 = (i & 31) * 4;
            float4 w0 = __ldg((const float4*)(B + (size_t)(k0 + 2 * kp) * 128 + c4));
            float4 w1 = __ldg((const float4*)(B + (size_t)(k0 + 2 * kp + 1) * 128 + c4));
            float lo[4] = {w0.x, w0.y, w0.z, w0.w};
            float hi[4] = {w1.x, w1.y, w1.z, w1.w};
#pragma unroll
            for (int j = 0; j < 4; j++) {
                uint32_t pb = pack2bf(lo[j], hi[j]);
                float2 f = unpack_bf(pb);
                sBb[kp][c4 + j] = pb;
                sBs[kp][c4 + j] = pack2bf(lo[j] - f.x, hi[j] - f.y);
            }
        }
        __syncthreads();

#pragma unroll
        for (int ks = 0; ks < 2; ks++) {
            int kp0 = ks * 8;
            uint32_t ab0 = sAb[r0    ][kp0 + t4];
            uint32_t ab1 = sAb[r0 + 8][kp0 + t4];
            uint32_t ab2 = sAb[r0    ][kp0 + t4 + 4];
            uint32_t ab3 = sAb[r0 + 8][kp0 + t4 + 4];
            uint32_t as0 = sAs[r0    ][kp0 + t4];
            uint32_t as1 = sAs[r0 + 8][kp0 + t4];
            uint32_t as2 = sAs[r0    ][kp0 + t4 + 4];
            uint32_t as3 = sAs[r0 + 8][kp0 + t4 + 4];
#pragma unroll
            for (int nt = 0; nt < 16; nt++) {
                int e = nt * 8 + g;
                uint32_t bb0 = sBb[kp0 + t4    ][e];
                uint32_t bb1 = sBb[kp0 + t4 + 4][e];
                uint32_t bs0 = sBs[kp0 + t4    ][e];
                uint32_t bs1 = sBs[kp0 + t4 + 4][e];
                mma_bf16(acc[nt], ab0, ab1, ab2, ab3, bb0, bb1);
                mma_bf16(acc[nt], as0, as1, as2, as3, bb0, bb1);
                mma_bf16(acc[nt], ab0, ab1, ab2, ab3, bs0, bs1);
            }
        }
    }

#pragma unroll
    for (int nt = 0; nt < 16; nt++) {
        int c = nt * 8 + 2 * t4;
        int gr0 = row0 + r0, gr1 = gr0 + 8;
        if (gr0 < M)
            *(float2*)(C + (size_t)gr0 * 128 + c) = make_float2(acc[nt][0], acc[nt][1]);
        if (gr1 < M)
            *(float2*)(C + (size_t)gr1 * 128 + c) = make_float2(acc[nt][2], acc[nt][3]);
    }
}

// ------------------------------------------------------------------
// SpMM: one warp per destination row, 4-edge unroll, L1-cached gathers
// ------------------------------------------------------------------
__global__ __launch_bounds__(256) void spmm_kernel(
    const float* __restrict__ H, const int* __restrict__ col,
    const float* __restrict__ val, const float* __restrict__ bias,
    const float* __restrict__ res, float* __restrict__ out)
{
    int w = (blockIdx.x * blockDim.x + threadIdx.x) >> 5;
    if (w >= N_NODES) return;
    int lane = threadIdx.x & 31;

    const float4* Hv = (const float4*)H;
    float4 acc = make_float4(0.f, 0.f, 0.f, 0.f);
    int s = g_rowptr[w], e = g_rowptr[w + 1];
    int i = s;
    for (; i + 3 < e; i += 4) {
        int   c0 = __ldg(&col[i]),     c1 = __ldg(&col[i + 1]);
        int   c2 = __ldg(&col[i + 2]), c3 = __ldg(&col[i + 3]);
        float v0 = __ldg(&val[i]),     v1 = __ldg(&val[i + 1]);
        float v2 = __ldg(&val[i + 2]), v3 = __ldg(&val[i + 3]);
        float4 h0 = __ldg(&Hv[(size_t)c0 * 32 + lane]);
        float4 h1 = __ldg(&Hv[(size_t)c1 * 32 + lane]);
        float4 h2 = __ldg(&Hv[(size_t)c2 * 32 + lane]);
        float4 h3 = __ldg(&Hv[(size_t)c3 * 32 + lane]);
        acc.x = fmaf(v0, h0.x, acc.x); acc.y = fmaf(v0, h0.y, acc.y);
        acc.z = fmaf(v0, h0.z, acc.z); acc.w = fmaf(v0, h0.w, acc.w);
        acc.x = fmaf(v1, h1.x, acc.x); acc.y = fmaf(v1, h1.y, acc.y);
        acc.z = fmaf(v1, h1.z, acc.z); acc.w = fmaf(v1, h1.w, acc.w);
        acc.x = fmaf(v2, h2.x, acc.x); acc.y = fmaf(v2, h2.y, acc.y);
        acc.z = fmaf(v2, h2.z, acc.z); acc.w = fmaf(v2, h2.w, acc.w);
        acc.x = fmaf(v3, h3.x, acc.x); acc.y = fmaf(v3, h3.y, acc.y);
        acc.z = fmaf(v3, h3.z, acc.z); acc.w = fmaf(v3, h3.w, acc.w);
    }
    for (; i < e; i++) {
        int   c0 = __ldg(&col[i]);
        float v0 = __ldg(&val[i]);
        float4 h0 = __ldg(&Hv[(size_t)c0 * 32 + lane]);
        acc.x = fmaf(v0, h0.x, acc.x); acc.y = fmaf(v0, h0.y, acc.y);
        acc.z = fmaf(v0, h0.z, acc.z); acc.w = fmaf(v0, h0.w, acc.w);
    }

    float4 bb = __ldg(&((const float4*)bias)[lane]);
    float4 o;
    o.x = fmaxf(acc.x + bb.x, 0.f);
    o.y = fmaxf(acc.y + bb.y, 0.f);
    o.z = fmaxf(acc.z + bb.z, 0.f);
    o.w = fmaxf(acc.w + bb.w, 0.f);
    size_t vbase = (size_t)w * 32 + lane;
    if (res) {
        float4 rv = __ldg(&((const float4*)res)[vbase]);
        o.x += rv.x; o.y += rv.y; o.z += rv.z; o.w += rv.w;
    }
    ((float4*)out)[vbase] = o;
}

// ------------------------------------------------------------------
// Bilinear stage 1: tile = 128 pairs x (KC k-slices), split-bf16 3-MMA.
// (R5 layout — straight [kp][col] planes, scalar fragment LDS)
// ------------------------------------------------------------------
#define KC 4
#define BIL_SMEM_WORDS (128 * 132 + 128 * 132 + 2 * 16 * 136)
#define BIL_SMEM_BYTES (BIL_SMEM_WORDS * 4)

__global__ __launch_bounds__(256, 1) void bilinear_kernel(
    const float* __restrict__ latent, const int* __restrict__ idx,
    const float* __restrict__ bilw, float* __restrict__ feat)
{
    extern __shared__ float smem[];
    float*    sA  = smem;                          // [128][132] fp32 a rows
    float*    sB  = sA + 128 * 132;                // [128][132] fp32 b rows
    uint32_t* sWb = (uint32_t*)(sB + 128 * 132);   // [16 kpair][136] big
    uint32_t* sWs = sWb + 16 * 136;                // [16 kpair][136] small

    int tid  = threadIdx.x;
    int lane = tid & 31, warp = tid >> 5;
    int p0 = blockIdx.x * 128;
    int g = lane >> 2, t4 = lane & 3;
    int r0 = warp * 16 + g;                        // warps 0..7 cover rows 0..127

    // gather A and B pair rows (fp32)
    for (int i = tid; i < 128 * 32; i += 256) {
        int p = i >> 5, c8 = (i & 31) * 4;
        int pg = p0 + p; if (pg >= NPAIRS) pg = NPAIRS - 1;
        int na = __ldg(&idx[pg]);
        int nb = __ldg(&idx[NPAIRS + pg]);
        float4 va = __ldg((const float4*)(latent + (size_t)na * 128 + c8));
        float4 vb = __ldg((const float4*)(latent + (size_t)nb * 128 + c8));
        *(float4*)&sA[p * 132 + c8] = va;
        *(float4*)&sB[p * 132 + c8] = vb;
    }

    for (int kk = 0; kk < KC; kk++) {
        int k = blockIdx.y * KC + kk;

        float acc[16][4];
#pragma unroll
        for (int nt = 0; nt < 16; nt++)
#pragma unroll
            for (int j = 0; j < 4; j++) acc[nt][j] = 0.f;

        for (int k0 = 0; k0 < 128; k0 += 32) {
            __syncthreads();   // sA/sB ready (1st iter); sW planes free (later)
#pragma unroll
            for (int u = 0; u < 2; u++) {
                int i = tid + u * 256;
                int kp = i >> 5, c4 = (i & 31) * 4;
                const float* wp0 = bilw + ((size_t)k * 128 + k0 + 2 * kp) * 128 + c4;
                float4 w0 = __ldg((const float4*)wp0);
                float4 w1 = __ldg((const float4*)(wp0 + 128));
                float lo[4] = {w0.x, w0.y, w0.z, w0.w};
                float hi[4] = {w1.x, w1.y, w1.z, w1.w};
#pragma unroll
                for (int j = 0; j < 4; j++) {
                    uint32_t pb = pack2bf(lo[j], hi[j]);
                    float2 f = unpack_bf(pb);
                    sWb[kp * 136 + c4 + j] = pb;
                    sWs[kp * 136 + c4 + j] = pack2bf(lo[j] - f.x, hi[j] - f.y);
                }
            }
            __syncthreads();

#pragma unroll
            for (int ks = 0; ks < 2; ks++) {
                int cb = k0 + ks * 16 + 2 * t4;
                float xl0 = sA[(r0    ) * 132 + cb],     xh0 = sA[(r0    ) * 132 + cb + 1];
                float xl1 = sA[(r0 + 8) * 132 + cb],     xh1 = sA[(r0 + 8) * 132 + cb + 1];
                float xl2 = sA[(r0    ) * 132 + cb + 8], xh2 = sA[(r0    ) * 132 + cb + 9];
                float xl3 = sA[(r0 + 8) * 132 + cb + 8], xh3 = sA[(r0 + 8) * 132 + cb + 9];
                uint32_t ab0 = pack2bf(xl0, xh0);
                uint32_t ab1 = pack2bf(xl1, xh1);
                uint32_t ab2 = pack2bf(xl2, xh2);
                uint32_t ab3 = pack2bf(xl3, xh3);
                float2 f0 = unpack_bf(ab0), f1 = unpack_bf(ab1);
                float2 f2 = unpack_bf(ab2), f3 = unpack_bf(ab3);
                uint32_t as0 = pack2bf(xl0 - f0.x, xh0 - f0.y);
                uint32_t as1 = pack2bf(xl1 - f1.x, xh1 - f1.y);
                uint32_t as2 = pack2bf(xl2 - f2.x, xh2 - f2.y);
                uint32_t as3 = pack2bf(xl3 - f3.x, xh3 - f3.y);
                int kp0 = ks * 8;
#pragma unroll
                for (int nt = 0; nt < 16; nt++) {
                    int e = nt * 8 + g;
                    uint32_t bb0 = sWb[(kp0 + t4    ) * 136 + e];
                    uint32_t bb1 = sWb[(kp0 + t4 + 4) * 136 + e];
                    uint32_t bs0 = sWs[(kp0 + t4    ) * 136 + e];
                    uint32_t bs1 = sWs[(kp0 + t4 + 4) * 136 + e];
                    mma_bf16(acc[nt], ab0, ab1, ab2, ab3, bb0, bb1);
                    mma_bf16(acc[nt], as0, as1, as2, as3, bb0, bb1);
                    mma_bf16(acc[nt], ab0, ab1, ab2, ab3, bs0, bs1);
                }
            }
        }

        // epilogue: each warp fully owns rows r0 / r0+8 -> plain reduce
        float plo = 0.f, phi = 0.f;
#pragma unroll
        for (int nt = 0; nt < 16; nt++) {
            int c = nt * 8 + 2 * t4;
            plo = fmaf(acc[nt][0], sB[(r0    ) * 132 + c    ], plo);
            plo = fmaf(acc[nt][1], sB[(r0    ) * 132 + c + 1], plo);
            phi = fmaf(acc[nt][2], sB[(r0 + 8) * 132 + c    ], phi);
            phi = fmaf(acc[nt][3], sB[(r0 + 8) * 132 + c + 1], phi);
        }
        plo += __shfl_xor_sync(0xffffffffu, plo, 1);
        plo += __shfl_xor_sync(0xffffffffu, plo, 2);
        phi += __shfl_xor_sync(0xffffffffu, phi, 1);
        phi += __shfl_xor_sync(0xffffffffu, phi, 2);
        if (t4 == 0) {
            int pg0 = p0 + r0;
            int pg1 = p0 + r0 + 8;
            if (pg0 < NPAIRS) feat[(size_t)pg0 * ZDIM + k] = plo;
            if (pg1 < NPAIRS) feat[(size_t)pg1 * ZDIM + k] = phi;
        }
    }
}

// ------------------------------------------------------------------
// Stage 2: tiny MLP on feat -> predictions
// ------------------------------------------------------------------
__device__ __forceinline__ float elu1(float x) {
    return x > 0.f ? x : expm1f(x);
}

__global__ __launch_bounds__(256) void mlp_kernel(
    const float* __restrict__ feat, const float* __restrict__ bilb,
    const float* __restrict__ dw1, const float* __restrict__ db1,
    const float* __restrict__ dw2, const float* __restrict__ db2,
    float* __restrict__ pred)
{
    int p = blockIdx.x * blockDim.x + threadIdx.x;
    if (p >= NPAIRS) return;

    float f[ZDIM];
#pragma unroll
    for (int k = 0; k < ZDIM; k++)
        f[k] = elu1(feat[(size_t)p * ZDIM + k] + __ldg(&bilb[k]));

    float o = __ldg(&db2[0]);
#pragma unroll
    for (int kk = 0; kk < ZDIM; kk++) {
        float s = __ldg(&db1[kk]);
#pragma unroll
        for (int j = 0; j < ZDIM; j++)
            s = fmaf(f[j], __ldg(&dw1[j * ZDIM + kk]), s);
        o = fmaf(elu1(s), __ldg(&dw2[kk]), o);
    }
    pred[p] = o;
}

// ------------------------------------------------------------------
extern "C" void kernel_launch(void* const* d_in, const int* in_sizes, int n_in,
                              void* d_out, int out_size)
{
    const float* features = (const float*)d_in[0];
    const int*   adj_row  = (const int*)  d_in[1];
    const int*   adj_col  = (const int*)  d_in[2];
    const float* adj_val  = (const float*)d_in[3];
    const int*   idx      = (const int*)  d_in[4];
    const float* W0   = (const float*)d_in[5];
    const float* b0   = (const float*)d_in[6];
    const float* W1   = (const float*)d_in[7];
    const float* b1   = (const float*)d_in[8];
    const float* W2   = (const float*)d_in[9];
    const float* b2   = (const float*)d_in[10];
    const float* bilw = (const float*)d_in[11];
    const float* bilb = (const float*)d_in[12];
    const float* dw1  = (const float*)d_in[13];
    const float* db1  = (const float*)d_in[14];
    const float* dw2  = (const float*)d_in[15];
    const float* db2  = (const float*)d_in[16];

    float* out    = (float*)d_out;
    float* pred   = out;            // [NPAIRS]
    float* latent = out + NPAIRS;   // [N_NODES * NHID]

    float* h;  cudaGetSymbolAddress((void**)&h,  g_buf_h);
    float* x0; cudaGetSymbolAddress((void**)&x0, g_buf_x0);
    float* x1; cudaGetSymbolAddress((void**)&x1, g_buf_x1);
    float* ft; cudaGetSymbolAddress((void**)&ft, g_feat);

    static int smem_set = 0;
    if (!smem_set) {
        cudaFuncSetAttribute(bilinear_kernel,
                             cudaFuncAttributeMaxDynamicSharedMemorySize,
                             BIL_SMEM_BYTES);
        smem_set = 1;
    }

    rowptr_kernel<<<(N_NODES + 1 + 255) / 256, 256>>>(adj_row);

    const int gemm_grid = (N_NODES + 63) / 64;
    const int spmm_grid = (N_NODES * 32 + 255) / 256;

    gemm_bf16_n128<<<gemm_grid, 128>>>(features, W0, h, N_NODES, NFEAT);
    spmm_kernel<<<spmm_grid, 256>>>(h, adj_col, adj_val, b0, nullptr, x0);

    gemm_bf16_n128<<<gemm_grid, 128>>>(x0, W1, h, N_NODES, NHID);
    spmm_kernel<<<spmm_grid, 256>>>(h, adj_col, adj_val, b1, x0, x1);

    gemm_bf16_n128<<<gemm_grid, 128>>>(x1, W2, h, N_NODES, NHID);
    spmm_kernel<<<spmm_grid, 256>>>(h, adj_col, adj_val, b2, x1, latent);

    dim3 bil_grid((NPAIRS + 127) / 128, ZDIM / KC);
    bilinear_kernel<<<bil_grid, 256, BIL_SMEM_BYTES>>>(latent, idx, bilw, ft);
    mlp_kernel<<<(NPAIRS + 255) / 256, 256>>>(ft, bilb, dw1, db1, dw2, db2, pred);
}

// round 8
// speedup vs baseline: 1.0155x; 1.0144x over previous
#include <cuda_runtime.h>
#include <cstdint>

#define N_NODES 50000
#define N_EDGES 800000
#define NFEAT   256
#define NHID    128
#define ZDIM    32
#define NPAIRS  10000

// ---- scratch (static device globals; no allocation at runtime) ----
__device__ float    g_buf_h [(size_t)N_NODES * NHID];
__device__ float    g_buf_x0[(size_t)N_NODES * NHID];
__device__ float    g_buf_x1[(size_t)N_NODES * NHID];
__device__ int      g_rowptr[N_NODES + 1];
__device__ float    g_feat[(size_t)NPAIRS * ZDIM];
// pre-split weight planes (bf16x2 pairs along k): W0 kp-rows 0..127,
// W1 128..191, W2 192..255
__device__ uint32_t g_Wb[256 * 128], g_Ws[256 * 128];
__device__ uint32_t g_bilWb[(size_t)ZDIM * 64 * 128];
__device__ uint32_t g_bilWs[(size_t)ZDIM * 64 * 128];

// ------------------------------------------------------------------
// bf16 split helpers
// ------------------------------------------------------------------
__device__ __forceinline__ uint32_t pack2bf(float lo, float hi) {
    uint32_t r;
    asm("cvt.rn.bf16x2.f32 %0, %1, %2;" : "=r"(r) : "f"(hi), "f"(lo));
    return r;
}
__device__ __forceinline__ float2 unpack_bf(uint32_t p) {
    return make_float2(__uint_as_float(p << 16),
                       __uint_as_float(p & 0xffff0000u));
}

__device__ __forceinline__ void mma_bf16(
    float* d, uint32_t a0, uint32_t a1, uint32_t a2, uint32_t a3,
    uint32_t b0, uint32_t b1)
{
    asm volatile(
        "mma.sync.aligned.m16n8k16.row.col.f32.bf16.bf16.f32 "
        "{%0,%1,%2,%3}, {%4,%5,%6,%7}, {%8,%9}, {%0,%1,%2,%3};\n"
        : "+f"(d[0]), "+f"(d[1]), "+f"(d[2]), "+f"(d[3])
        : "r"(a0), "r"(a1), "r"(a2), "r"(a3), "r"(b0), "r"(b1));
}

// ------------------------------------------------------------------
// One-shot weight pre-split: fp32 [2*kp_rows][128] -> bf16x2 planes
// pair (kp, c): lo = W[kp*256 + c], hi = W[kp*256 + 128 + c]
// Ranges: W0 16384 | W1 8192 | W2 8192 | bilw 262144
// ------------------------------------------------------------------
__global__ void presplit_kernel(const float* __restrict__ W0,
                                const float* __restrict__ W1,
                                const float* __restrict__ W2,
                                const float* __restrict__ bilw)
{
    int i = blockIdx.x * blockDim.x + threadIdx.x;
    const float* src; uint32_t* dstB; uint32_t* dstS; int j;
    if (i < 16384)        { src = W0;   dstB = g_Wb;              dstS = g_Ws;              j = i; }
    else if (i < 24576)   { src = W1;   dstB = g_Wb + 128 * 128;  dstS = g_Ws + 128 * 128;  j = i - 16384; }
    else if (i < 32768)   { src = W2;   dstB = g_Wb + 192 * 128;  dstS = g_Ws + 192 * 128;  j = i - 24576; }
    else if (i < 294912)  { src = bilw; dstB = g_bilWb;           dstS = g_bilWs;           j = i - 32768; }
    else return;
    int kp = j >> 7, c = j & 127;
    float lo = src[(size_t)kp * 256 + c];
    float hi = src[(size_t)kp * 256 + 128 + c];
    uint32_t pb = pack2bf(lo, hi);
    float2 f = unpack_bf(pb);
    dstB[j] = pb;
    dstS[j] = pack2bf(lo - f.x, hi - f.y);
}

// ------------------------------------------------------------------
__global__ void rowptr_kernel(const int* __restrict__ row) {
    int r = blockIdx.x * blockDim.x + threadIdx.x;
    if (r > N_NODES) return;
    int lo = 0, hi = N_EDGES;
    while (lo < hi) {
        int mid = (lo + hi) >> 1;
        if (row[mid] < r) lo = mid + 1; else hi = mid;
    }
    g_rowptr[r] = lo;
}

// ------------------------------------------------------------------
// Encoder GEMM: C[M,128] = A[M,K] @ Wsplit[K,128], split-bf16 3-MMA.
// BM=128, BK=32, 256 threads, 8 warps x 16 rows x full N=128.
// B planes pre-split in gmem -> pure uint4 ldg/sts staging.
// ------------------------------------------------------------------
__global__ __launch_bounds__(256, 2) void gemm_bf16_n128(
    const float* __restrict__ A,
    const uint32_t* __restrict__ Wb, const uint32_t* __restrict__ Ws,
    float* __restrict__ C, int M, int K)
{
    __shared__ uint32_t sAb[128][17], sAs[128][17];   // [row][kpair]
    __shared__ uint32_t sBb[16][136], sBs[16][136];   // [kpair][col]

    int tid  = threadIdx.x;
    int lane = tid & 31, warp = tid >> 5;
    int g = lane >> 2, t4 = lane & 3;
    int r0 = warp * 16 + g;
    int row0 = blockIdx.x * 128;

    float acc[16][4];
#pragma unroll
    for (int nt = 0; nt < 16; nt++)
#pragma unroll
        for (int j = 0; j < 4; j++) acc[nt][j] = 0.f;

    for (int k0 = 0; k0 < K; k0 += 32) {
        __syncthreads();
        // A tile: 128 rows x 32 k, split+pack along k (runtime data)
#pragma unroll
        for (int u = 0; u < 4; u++) {
            int i = tid + u * 256;
            int r = i >> 3, q = i & 7;
            int gr = row0 + r;
            float4 v = (gr < M)
                ? __ldg((const float4*)(A + (size_t)gr * K + k0 + 4 * q))
                : make_float4(0.f, 0.f, 0.f, 0.f);
            uint32_t p0 = pack2bf(v.x, v.y);
            uint32_t p1 = pack2bf(v.z, v.w);
            float2 f0 = unpack_bf(p0), f1 = unpack_bf(p1);
            sAb[r][2 * q]     = p0;
            sAb[r][2 * q + 1] = p1;
            sAs[r][2 * q]     = pack2bf(v.x - f0.x, v.y - f0.y);
            sAs[r][2 * q + 1] = pack2bf(v.z - f1.x, v.w - f1.y);
        }
        // B tile: pre-split planes, contiguous 16 kp x 128 cols
        {
            const uint32_t* srcB = Wb + (size_t)(k0 >> 1) * 128;
            const uint32_t* srcS = Ws + (size_t)(k0 >> 1) * 128;
#pragma unroll
            for (int u = 0; u < 2; u++) {
                int i = tid + u * 256;
                int kp = i >> 5, c4 = (i & 31) * 4;
                uint4 vb = __ldg((const uint4*)(srcB + kp * 128 + c4));
                uint4 vs = __ldg((const uint4*)(srcS + kp * 128 + c4));
                *(uint4*)&sBb[kp][c4] = vb;
                *(uint4*)&sBs[kp][c4] = vs;
            }
        }
        __syncthreads();

#pragma unroll
        for (int ks = 0; ks < 2; ks++) {
            int kp0 = ks * 8;
            uint32_t ab0 = sAb[r0    ][kp0 + t4];
            uint32_t ab1 = sAb[r0 + 8][kp0 + t4];
            uint32_t ab2 = sAb[r0    ][kp0 + t4 + 4];
            uint32_t ab3 = sAb[r0 + 8][kp0 + t4 + 4];
            uint32_t as0 = sAs[r0    ][kp0 + t4];
            uint32_t as1 = sAs[r0 + 8][kp0 + t4];
            uint32_t as2 = sAs[r0    ][kp0 + t4 + 4];
            uint32_t as3 = sAs[r0 + 8][kp0 + t4 + 4];
#pragma unroll
            for (int nt = 0; nt < 16; nt++) {
                int e = nt * 8 + g;
                uint32_t bb0 = sBb[kp0 + t4    ][e];
                uint32_t bb1 = sBb[kp0 + t4 + 4][e];
                uint32_t bs0 = sBs[kp0 + t4    ][e];
                uint32_t bs1 = sBs[kp0 + t4 + 4][e];
                mma_bf16(acc[nt], ab0, ab1, ab2, ab3, bb0, bb1);
                mma_bf16(acc[nt], as0, as1, as2, as3, bb0, bb1);
                mma_bf16(acc[nt], ab0, ab1, ab2, ab3, bs0, bs1);
            }
        }
    }

#pragma unroll
    for (int nt = 0; nt < 16; nt++) {
        int c = nt * 8 + 2 * t4;
        int gr0 = row0 + r0, gr1 = gr0 + 8;
        if (gr0 < M)
            *(float2*)(C + (size_t)gr0 * 128 + c) = make_float2(acc[nt][0], acc[nt][1]);
        if (gr1 < M)
            *(float2*)(C + (size_t)gr1 * 128 + c) = make_float2(acc[nt][2], acc[nt][3]);
    }
}

// ------------------------------------------------------------------
// SpMM: one warp per destination row, 2-edge unroll (R5 config)
// ------------------------------------------------------------------
__global__ __launch_bounds__(256) void spmm_kernel(
    const float* __restrict__ H, const int* __restrict__ col,
    const float* __restrict__ val, const float* __restrict__ bias,
    const float* __restrict__ res, float* __restrict__ out)
{
    int w = (blockIdx.x * blockDim.x + threadIdx.x) >> 5;
    if (w >= N_NODES) return;
    int lane = threadIdx.x & 31;

    const float4* Hv = (const float4*)H;
    float4 acc = make_float4(0.f, 0.f, 0.f, 0.f);
    int s = g_rowptr[w], e = g_rowptr[w + 1];
    int i = s;
    for (; i + 1 < e; i += 2) {
        int   c0 = __ldg(&col[i]);
        int   c1 = __ldg(&col[i + 1]);
        float v0 = __ldg(&val[i]);
        float v1 = __ldg(&val[i + 1]);
        float4 h0 = __ldg(&Hv[(size_t)c0 * 32 + lane]);
        float4 h1 = __ldg(&Hv[(size_t)c1 * 32 + lane]);
        acc.x = fmaf(v0, h0.x, acc.x); acc.y = fmaf(v0, h0.y, acc.y);
        acc.z = fmaf(v0, h0.z, acc.z); acc.w = fmaf(v0, h0.w, acc.w);
        acc.x = fmaf(v1, h1.x, acc.x); acc.y = fmaf(v1, h1.y, acc.y);
        acc.z = fmaf(v1, h1.z, acc.z); acc.w = fmaf(v1, h1.w, acc.w);
    }
    if (i < e) {
        int   c0 = __ldg(&col[i]);
        float v0 = __ldg(&val[i]);
        float4 h0 = __ldg(&Hv[(size_t)c0 * 32 + lane]);
        acc.x = fmaf(v0, h0.x, acc.x); acc.y = fmaf(v0, h0.y, acc.y);
        acc.z = fmaf(v0, h0.z, acc.z); acc.w = fmaf(v0, h0.w, acc.w);
    }

    float4 bb = __ldg(&((const float4*)bias)[lane]);
    float4 o;
    o.x = fmaxf(acc.x + bb.x, 0.f);
    o.y = fmaxf(acc.y + bb.y, 0.f);
    o.z = fmaxf(acc.z + bb.z, 0.f);
    o.w = fmaxf(acc.w + bb.w, 0.f);
    size_t vbase = (size_t)w * 32 + lane;
    if (res) {
        float4 rv = __ldg(&((const float4*)res)[vbase]);
        o.x += rv.x; o.y += rv.y; o.z += rv.z; o.w += rv.w;
    }
    ((float4*)out)[vbase] = o;
}

// ------------------------------------------------------------------
// Bilinear stage 1: tile = 128 pairs x (KC k-slices), split-bf16 3-MMA.
// W chunks from pre-split planes (uint4 ldg/sts staging).
// ------------------------------------------------------------------
#define KC 4
#define BIL_SMEM_WORDS (128 * 132 + 128 * 132 + 2 * 16 * 136)
#define BIL_SMEM_BYTES (BIL_SMEM_WORDS * 4)

__global__ __launch_bounds__(256, 1) void bilinear_kernel(
    const float* __restrict__ latent, const int* __restrict__ idx,
    const uint32_t* __restrict__ bilWb, const uint32_t* __restrict__ bilWs,
    float* __restrict__ feat)
{
    extern __shared__ float smem[];
    float*    sA  = smem;                          // [128][132] fp32 a rows
    float*    sB  = sA + 128 * 132;                // [128][132] fp32 b rows
    uint32_t* sWb = (uint32_t*)(sB + 128 * 132);   // [16 kpair][136] big
    uint32_t* sWs = sWb + 16 * 136;                // [16 kpair][136] small

    int tid  = threadIdx.x;
    int lane = tid & 31, warp = tid >> 5;
    int p0 = blockIdx.x * 128;
    int g = lane >> 2, t4 = lane & 3;
    int r0 = warp * 16 + g;                        // warps 0..7 cover rows 0..127

    // gather A and B pair rows (fp32)
    for (int i = tid; i < 128 * 32; i += 256) {
        int p = i >> 5, c8 = (i & 31) * 4;
        int pg = p0 + p; if (pg >= NPAIRS) pg = NPAIRS - 1;
        int na = __ldg(&idx[pg]);
        int nb = __ldg(&idx[NPAIRS + pg]);
        float4 va = __ldg((const float4*)(latent + (size_t)na * 128 + c8));
        float4 vb = __ldg((const float4*)(latent + (size_t)nb * 128 + c8));
        *(float4*)&sA[p * 132 + c8] = va;
        *(float4*)&sB[p * 132 + c8] = vb;
    }

    for (int kk = 0; kk < KC; kk++) {
        int k = blockIdx.y * KC + kk;

        float acc[16][4];
#pragma unroll
        for (int nt = 0; nt < 16; nt++)
#pragma unroll
            for (int j = 0; j < 4; j++) acc[nt][j] = 0.f;

        for (int k0 = 0; k0 < 128; k0 += 32) {
            __syncthreads();   // sA/sB ready (1st iter); sW planes free (later)
            {
                const uint32_t* srcB = bilWb + ((size_t)k * 64 + (k0 >> 1)) * 128;
                const uint32_t* srcS = bilWs + ((size_t)k * 64 + (k0 >> 1)) * 128;
#pragma unroll
                for (int u = 0; u < 2; u++) {
                    int i = tid + u * 256;
                    int kp = i >> 5, c4 = (i & 31) * 4;
                    uint4 vb = __ldg((const uint4*)(srcB + kp * 128 + c4));
                    uint4 vs = __ldg((const uint4*)(srcS + kp * 128 + c4));
                    *(uint4*)&sWb[kp * 136 + c4] = vb;
                    *(uint4*)&sWs[kp * 136 + c4] = vs;
                }
            }
            __syncthreads();

#pragma unroll
            for (int ks = 0; ks < 2; ks++) {
                int cb = k0 + ks * 16 + 2 * t4;
                float xl0 = sA[(r0    ) * 132 + cb],     xh0 = sA[(r0    ) * 132 + cb + 1];
                float xl1 = sA[(r0 + 8) * 132 + cb],     xh1 = sA[(r0 + 8) * 132 + cb + 1];
                float xl2 = sA[(r0    ) * 132 + cb + 8], xh2 = sA[(r0    ) * 132 + cb + 9];
                float xl3 = sA[(r0 + 8) * 132 + cb + 8], xh3 = sA[(r0 + 8) * 132 + cb + 9];
                uint32_t ab0 = pack2bf(xl0, xh0);
                uint32_t ab1 = pack2bf(xl1, xh1);
                uint32_t ab2 = pack2bf(xl2, xh2);
                uint32_t ab3 = pack2bf(xl3, xh3);
                float2 f0 = unpack_bf(ab0), f1 = unpack_bf(ab1);
                float2 f2 = unpack_bf(ab2), f3 = unpack_bf(ab3);
                uint32_t as0 = pack2bf(xl0 - f0.x, xh0 - f0.y);
                uint32_t as1 = pack2bf(xl1 - f1.x, xh1 - f1.y);
                uint32_t as2 = pack2bf(xl2 - f2.x, xh2 - f2.y);
                uint32_t as3 = pack2bf(xl3 - f3.x, xh3 - f3.y);
                int kp0 = ks * 8;
#pragma unroll
                for (int nt = 0; nt < 16; nt++) {
                    int e = nt * 8 + g;
                    uint32_t bb0 = sWb[(kp0 + t4    ) * 136 + e];
                    uint32_t bb1 = sWb[(kp0 + t4 + 4) * 136 + e];
                    uint32_t bs0 = sWs[(kp0 + t4    ) * 136 + e];
                    uint32_t bs1 = sWs[(kp0 + t4 + 4) * 136 + e];
                    mma_bf16(acc[nt], ab0, ab1, ab2, ab3, bb0, bb1);
                    mma_bf16(acc[nt], as0, as1, as2, as3, bb0, bb1);
                    mma_bf16(acc[nt], ab0, ab1, ab2, ab3, bs0, bs1);
                }
            }
        }

        // epilogue: each warp fully owns rows r0 / r0+8 -> plain reduce
        float plo = 0.f, phi = 0.f;
#pragma unroll
        for (int nt = 0; nt < 16; nt++) {
            int c = nt * 8 + 2 * t4;
            plo = fmaf(acc[nt][0], sB[(r0    ) * 132 + c    ], plo);
            plo = fmaf(acc[nt][1], sB[(r0    ) * 132 + c + 1], plo);
            phi = fmaf(acc[nt][2], sB[(r0 + 8) * 132 + c    ], phi);
            phi = fmaf(acc[nt][3], sB[(r0 + 8) * 132 + c + 1], phi);
        }
        plo += __shfl_xor_sync(0xffffffffu, plo, 1);
        plo += __shfl_xor_sync(0xffffffffu, plo, 2);
        phi += __shfl_xor_sync(0xffffffffu, phi, 1);
        phi += __shfl_xor_sync(0xffffffffu, phi, 2);
        if (t4 == 0) {
            int pg0 = p0 + r0;
            int pg1 = p0 + r0 + 8;
            if (pg0 < NPAIRS) feat[(size_t)pg0 * ZDIM + k] = plo;
            if (pg1 < NPAIRS) feat[(size_t)pg1 * ZDIM + k] = phi;
        }
    }
}

// ------------------------------------------------------------------
// Stage 2: tiny MLP on feat -> predictions
// ------------------------------------------------------------------
__device__ __forceinline__ float elu1(float x) {
    return x > 0.f ? x : expm1f(x);
}

__global__ __launch_bounds__(256) void mlp_kernel(
    const float* __restrict__ feat, const float* __restrict__ bilb,
    const float* __restrict__ dw1, const float* __restrict__ db1,
    const float* __restrict__ dw2, const float* __restrict__ db2,
    float* __restrict__ pred)
{
    int p = blockIdx.x * blockDim.x + threadIdx.x;
    if (p >= NPAIRS) return;

    float f[ZDIM];
#pragma unroll
    for (int k = 0; k < ZDIM; k++)
        f[k] = elu1(feat[(size_t)p * ZDIM + k] + __ldg(&bilb[k]));

    float o = __ldg(&db2[0]);
#pragma unroll
    for (int kk = 0; kk < ZDIM; kk++) {
        float s = __ldg(&db1[kk]);
#pragma unroll
        for (int j = 0; j < ZDIM; j++)
            s = fmaf(f[j], __ldg(&dw1[j * ZDIM + kk]), s);
        o = fmaf(elu1(s), __ldg(&dw2[kk]), o);
    }
    pred[p] = o;
}

// ------------------------------------------------------------------
extern "C" void kernel_launch(void* const* d_in, const int* in_sizes, int n_in,
                              void* d_out, int out_size)
{
    const float* features = (const float*)d_in[0];
    const int*   adj_row  = (const int*)  d_in[1];
    const int*   adj_col  = (const int*)  d_in[2];
    const float* adj_val  = (const float*)d_in[3];
    const int*   idx      = (const int*)  d_in[4];
    const float* W0   = (const float*)d_in[5];
    const float* b0   = (const float*)d_in[6];
    const float* W1   = (const float*)d_in[7];
    const float* b1   = (const float*)d_in[8];
    const float* W2   = (const float*)d_in[9];
    const float* b2   = (const float*)d_in[10];
    const float* bilw = (const float*)d_in[11];
    const float* bilb = (const float*)d_in[12];
    const float* dw1  = (const float*)d_in[13];
    const float* db1  = (const float*)d_in[14];
    const float* dw2  = (const float*)d_in[15];
    const float* db2  = (const float*)d_in[16];

    float* out    = (float*)d_out;
    float* pred   = out;            // [NPAIRS]
    float* latent = out + NPAIRS;   // [N_NODES * NHID]

    float* h;  cudaGetSymbolAddress((void**)&h,  g_buf_h);
    float* x0; cudaGetSymbolAddress((void**)&x0, g_buf_x0);
    float* x1; cudaGetSymbolAddress((void**)&x1, g_buf_x1);
    float* ft; cudaGetSymbolAddress((void**)&ft, g_feat);
    uint32_t* wb;  cudaGetSymbolAddress((void**)&wb,  g_Wb);
    uint32_t* ws;  cudaGetSymbolAddress((void**)&ws,  g_Ws);
    uint32_t* bwb; cudaGetSymbolAddress((void**)&bwb, g_bilWb);
    uint32_t* bws; cudaGetSymbolAddress((void**)&bws, g_bilWs);

    static int smem_set = 0;
    if (!smem_set) {
        cudaFuncSetAttribute(bilinear_kernel,
                             cudaFuncAttributeMaxDynamicSharedMemorySize,
                             BIL_SMEM_BYTES);
        smem_set = 1;
    }

    // launch 1: weight pre-split (also shifts ncu -s 5 window onto spmm1)
    presplit_kernel<<<(294912 + 255) / 256, 256>>>(W0, W1, W2, bilw);
    // launch 2
    rowptr_kernel<<<(N_NODES + 1 + 255) / 256, 256>>>(adj_row);

    const int gemm_grid = (N_NODES + 127) / 128;
    const int spmm_grid = (N_NODES * 32 + 255) / 256;

    // 3,4
    gemm_bf16_n128<<<gemm_grid, 256>>>(features, wb, ws, h, N_NODES, NFEAT);
    spmm_kernel<<<spmm_grid, 256>>>(h, adj_col, adj_val, b0, nullptr, x0);
    // 5,6  (launch 6 = spmm -> profiled by ncu -s 5 -c 1)
    gemm_bf16_n128<<<gemm_grid, 256>>>(x0, wb + 128 * 128, ws + 128 * 128, h, N_NODES, NHID);
    spmm_kernel<<<spmm_grid, 256>>>(h, adj_col, adj_val, b1, x0, x1);
    // 7,8
    gemm_bf16_n128<<<gemm_grid, 256>>>(x1, wb + 192 * 128, ws + 192 * 128, h, N_NODES, NHID);
    spmm_kernel<<<spmm_grid, 256>>>(h, adj_col, adj_val, b2, x1, latent);
    // 9,10
    dim3 bil_grid((NPAIRS + 127) / 128, ZDIM / KC);
    bilinear_kernel<<<bil_grid, 256, BIL_SMEM_BYTES>>>(latent, idx, bwb, bws, ft);
    mlp_kernel<<<(NPAIRS + 255) / 256, 256>>>(ft, bilb, dw1, db1, dw2, db2, pred);
}

// round 9
// speedup vs baseline: 1.1210x; 1.1039x over previous
#include <cuda_runtime.h>
#include <cstdint>

#define N_NODES 50000
#define N_EDGES 800000
#define NFEAT   256
#define NHID    128
#define ZDIM    32
#define NPAIRS  10000

// ---- scratch (static device globals; no allocation at runtime) ----
__device__ float    g_buf_h [(size_t)N_NODES * NHID];
__device__ float    g_buf_x0[(size_t)N_NODES * NHID];
__device__ float    g_buf_x1[(size_t)N_NODES * NHID];
__device__ int      g_rowptr[N_NODES + 1];
__device__ float    g_feat[(size_t)NPAIRS * ZDIM];
// pre-split weight planes (bf16x2 pairs along k): W0 kp-rows 0..127,
// W1 128..191, W2 192..255
__device__ uint32_t g_Wb[256 * 128], g_Ws[256 * 128];
__device__ uint32_t g_bilWb[(size_t)ZDIM * 64 * 128];
__device__ uint32_t g_bilWs[(size_t)ZDIM * 64 * 128];

// ------------------------------------------------------------------
// bf16 split helpers
// ------------------------------------------------------------------
__device__ __forceinline__ uint32_t pack2bf(float lo, float hi) {
    uint32_t r;
    asm("cvt.rn.bf16x2.f32 %0, %1, %2;" : "=r"(r) : "f"(hi), "f"(lo));
    return r;
}
__device__ __forceinline__ float2 unpack_bf(uint32_t p) {
    return make_float2(__uint_as_float(p << 16),
                       __uint_as_float(p & 0xffff0000u));
}

__device__ __forceinline__ void mma_bf16(
    float* d, uint32_t a0, uint32_t a1, uint32_t a2, uint32_t a3,
    uint32_t b0, uint32_t b1)
{
    asm volatile(
        "mma.sync.aligned.m16n8k16.row.col.f32.bf16.bf16.f32 "
        "{%0,%1,%2,%3}, {%4,%5,%6,%7}, {%8,%9}, {%0,%1,%2,%3};\n"
        : "+f"(d[0]), "+f"(d[1]), "+f"(d[2]), "+f"(d[3])
        : "r"(a0), "r"(a1), "r"(a2), "r"(a3), "r"(b0), "r"(b1));
}

// ------------------------------------------------------------------
// One-shot weight pre-split: fp32 [2*kp_rows][128] -> bf16x2 planes
// pair (kp, c): lo = W[kp*256 + c], hi = W[kp*256 + 128 + c]
// ------------------------------------------------------------------
__global__ void presplit_kernel(const float* __restrict__ W0,
                                const float* __restrict__ W1,
                                const float* __restrict__ W2,
                                const float* __restrict__ bilw)
{
    int i = blockIdx.x * blockDim.x + threadIdx.x;
    const float* src; uint32_t* dstB; uint32_t* dstS; int j;
    if (i < 16384)        { src = W0;   dstB = g_Wb;              dstS = g_Ws;              j = i; }
    else if (i < 24576)   { src = W1;   dstB = g_Wb + 128 * 128;  dstS = g_Ws + 128 * 128;  j = i - 16384; }
    else if (i < 32768)   { src = W2;   dstB = g_Wb + 192 * 128;  dstS = g_Ws + 192 * 128;  j = i - 24576; }
    else if (i < 294912)  { src = bilw; dstB = g_bilWb;           dstS = g_bilWs;           j = i - 32768; }
    else return;
    int kp = j >> 7, c = j & 127;
    float lo = src[(size_t)kp * 256 + c];
    float hi = src[(size_t)kp * 256 + 128 + c];
    uint32_t pb = pack2bf(lo, hi);
    float2 f = unpack_bf(pb);
    dstB[j] = pb;
    dstS[j] = pack2bf(lo - f.x, hi - f.y);
}

// ------------------------------------------------------------------
__global__ void rowptr_kernel(const int* __restrict__ row) {
    int r = blockIdx.x * blockDim.x + threadIdx.x;
    if (r > N_NODES) return;
    int lo = 0, hi = N_EDGES;
    while (lo < hi) {
        int mid = (lo + hi) >> 1;
        if (row[mid] < r) lo = mid + 1; else hi = mid;
    }
    g_rowptr[r] = lo;
}

// ------------------------------------------------------------------
// Encoder GEMM: C[M,128] = A[M,K] @ Wsplit[K,128], split-bf16 3-MMA.
// BM=128, BK=32, 256 threads, 8 warps x 16 rows x full N=128.
// ------------------------------------------------------------------
__global__ __launch_bounds__(256, 2) void gemm_bf16_n128(
    const float* __restrict__ A,
    const uint32_t* __restrict__ Wb, const uint32_t* __restrict__ Ws,
    float* __restrict__ C, int M, int K)
{
    __shared__ uint32_t sAb[128][17], sAs[128][17];   // [row][kpair]
    __shared__ uint32_t sBb[16][136], sBs[16][136];   // [kpair][col]

    int tid  = threadIdx.x;
    int lane = tid & 31, warp = tid >> 5;
    int g = lane >> 2, t4 = lane & 3;
    int r0 = warp * 16 + g;
    int row0 = blockIdx.x * 128;

    float acc[16][4];
#pragma unroll
    for (int nt = 0; nt < 16; nt++)
#pragma unroll
        for (int j = 0; j < 4; j++) acc[nt][j] = 0.f;

    for (int k0 = 0; k0 < K; k0 += 32) {
        __syncthreads();
#pragma unroll
        for (int u = 0; u < 4; u++) {
            int i = tid + u * 256;
            int r = i >> 3, q = i & 7;
            int gr = row0 + r;
            float4 v = (gr < M)
                ? __ldg((const float4*)(A + (size_t)gr * K + k0 + 4 * q))
                : make_float4(0.f, 0.f, 0.f, 0.f);
            uint32_t p0 = pack2bf(v.x, v.y);
            uint32_t p1 = pack2bf(v.z, v.w);
            float2 f0 = unpack_bf(p0), f1 = unpack_bf(p1);
            sAb[r][2 * q]     = p0;
            sAb[r][2 * q + 1] = p1;
            sAs[r][2 * q]     = pack2bf(v.x - f0.x, v.y - f0.y);
            sAs[r][2 * q + 1] = pack2bf(v.z - f1.x, v.w - f1.y);
        }
        {
            const uint32_t* srcB = Wb + (size_t)(k0 >> 1) * 128;
            const uint32_t* srcS = Ws + (size_t)(k0 >> 1) * 128;
#pragma unroll
            for (int u = 0; u < 2; u++) {
                int i = tid + u * 256;
                int kp = i >> 5, c4 = (i & 31) * 4;
                uint4 vb = __ldg((const uint4*)(srcB + kp * 128 + c4));
                uint4 vs = __ldg((const uint4*)(srcS + kp * 128 + c4));
                *(uint4*)&sBb[kp][c4] = vb;
                *(uint4*)&sBs[kp][c4] = vs;
            }
        }
        __syncthreads();

#pragma unroll
        for (int ks = 0; ks < 2; ks++) {
            int kp0 = ks * 8;
            uint32_t ab0 = sAb[r0    ][kp0 + t4];
            uint32_t ab1 = sAb[r0 + 8][kp0 + t4];
            uint32_t ab2 = sAb[r0    ][kp0 + t4 + 4];
            uint32_t ab3 = sAb[r0 + 8][kp0 + t4 + 4];
            uint32_t as0 = sAs[r0    ][kp0 + t4];
            uint32_t as1 = sAs[r0 + 8][kp0 + t4];
            uint32_t as2 = sAs[r0    ][kp0 + t4 + 4];
            uint32_t as3 = sAs[r0 + 8][kp0 + t4 + 4];
#pragma unroll
            for (int nt = 0; nt < 16; nt++) {
                int e = nt * 8 + g;
                uint32_t bb0 = sBb[kp0 + t4    ][e];
                uint32_t bb1 = sBb[kp0 + t4 + 4][e];
                uint32_t bs0 = sBs[kp0 + t4    ][e];
                uint32_t bs1 = sBs[kp0 + t4 + 4][e];
                mma_bf16(acc[nt], ab0, ab1, ab2, ab3, bb0, bb1);
                mma_bf16(acc[nt], as0, as1, as2, as3, bb0, bb1);
                mma_bf16(acc[nt], ab0, ab1, ab2, ab3, bs0, bs1);
            }
        }
    }

#pragma unroll
    for (int nt = 0; nt < 16; nt++) {
        int c = nt * 8 + 2 * t4;
        int gr0 = row0 + r0, gr1 = gr0 + 8;
        if (gr0 < M)
            *(float2*)(C + (size_t)gr0 * 128 + c) = make_float2(acc[nt][0], acc[nt][1]);
        if (gr1 < M)
            *(float2*)(C + (size_t)gr1 * 128 + c) = make_float2(acc[nt][2], acc[nt][3]);
    }
}

// ------------------------------------------------------------------
// SpMM: one warp per destination row, 4-edge unroll, __ldg gathers
// ------------------------------------------------------------------
__global__ __launch_bounds__(256) void spmm_kernel(
    const float* __restrict__ H, const int* __restrict__ col,
    const float* __restrict__ val, const float* __restrict__ bias,
    const float* __restrict__ res, float* __restrict__ out)
{
    int w = (blockIdx.x * blockDim.x + threadIdx.x) >> 5;
    if (w >= N_NODES) return;
    int lane = threadIdx.x & 31;

    const float4* Hv = (const float4*)H;
    float4 acc = make_float4(0.f, 0.f, 0.f, 0.f);
    int s = g_rowptr[w], e = g_rowptr[w + 1];
    int i = s;
    for (; i + 3 < e; i += 4) {
        int   c0 = __ldg(&col[i]),     c1 = __ldg(&col[i + 1]);
        int   c2 = __ldg(&col[i + 2]), c3 = __ldg(&col[i + 3]);
        float v0 = __ldg(&val[i]),     v1 = __ldg(&val[i + 1]);
        float v2 = __ldg(&val[i + 2]), v3 = __ldg(&val[i + 3]);
        float4 h0 = __ldg(&Hv[(size_t)c0 * 32 + lane]);
        float4 h1 = __ldg(&Hv[(size_t)c1 * 32 + lane]);
        float4 h2 = __ldg(&Hv[(size_t)c2 * 32 + lane]);
        float4 h3 = __ldg(&Hv[(size_t)c3 * 32 + lane]);
        acc.x = fmaf(v0, h0.x, acc.x); acc.y = fmaf(v0, h0.y, acc.y);
        acc.z = fmaf(v0, h0.z, acc.z); acc.w = fmaf(v0, h0.w, acc.w);
        acc.x = fmaf(v1, h1.x, acc.x); acc.y = fmaf(v1, h1.y, acc.y);
        acc.z = fmaf(v1, h1.z, acc.z); acc.w = fmaf(v1, h1.w, acc.w);
        acc.x = fmaf(v2, h2.x, acc.x); acc.y = fmaf(v2, h2.y, acc.y);
        acc.z = fmaf(v2, h2.z, acc.z); acc.w = fmaf(v2, h2.w, acc.w);
        acc.x = fmaf(v3, h3.x, acc.x); acc.y = fmaf(v3, h3.y, acc.y);
        acc.z = fmaf(v3, h3.z, acc.z); acc.w = fmaf(v3, h3.w, acc.w);
    }
    for (; i < e; i++) {
        int   c0 = __ldg(&col[i]);
        float v0 = __ldg(&val[i]);
        float4 h0 = __ldg(&Hv[(size_t)c0 * 32 + lane]);
        acc.x = fmaf(v0, h0.x, acc.x); acc.y = fmaf(v0, h0.y, acc.y);
        acc.z = fmaf(v0, h0.z, acc.z); acc.w = fmaf(v0, h0.w, acc.w);
    }

    float4 bb = __ldg(&((const float4*)bias)[lane]);
    float4 o;
    o.x = fmaxf(acc.x + bb.x, 0.f);
    o.y = fmaxf(acc.y + bb.y, 0.f);
    o.z = fmaxf(acc.z + bb.z, 0.f);
    o.w = fmaxf(acc.w + bb.w, 0.f);
    size_t vbase = (size_t)w * 32 + lane;
    if (res) {
        float4 rv = __ldg(&((const float4*)res)[vbase]);
        o.x += rv.x; o.y += rv.y; o.z += rv.z; o.w += rv.w;
    }
    ((float4*)out)[vbase] = o;
}

// ------------------------------------------------------------------
// Bilinear stage 1: tile = 128 pairs x (KC k-slices), split-bf16 3-MMA.
// No sB: epilogue reads B rows straight from gmem latent.
// smem = sA[128][132] fp32 + W planes -> ~85KB -> 2 CTAs/SM.
// ------------------------------------------------------------------
#define KC 4
#define BIL_SMEM_WORDS (128 * 132 + 2 * 16 * 136)
#define BIL_SMEM_BYTES (BIL_SMEM_WORDS * 4)

__global__ __launch_bounds__(256, 2) void bilinear_kernel(
    const float* __restrict__ latent, const int* __restrict__ idx,
    const uint32_t* __restrict__ bilWb, const uint32_t* __restrict__ bilWs,
    float* __restrict__ feat)
{
    extern __shared__ float smem[];
    float*    sA  = smem;                          // [128][132] fp32 a rows
    uint32_t* sWb = (uint32_t*)(sA + 128 * 132);   // [16 kpair][136] big
    uint32_t* sWs = sWb + 16 * 136;                // [16 kpair][136] small

    int tid  = threadIdx.x;
    int lane = tid & 31, warp = tid >> 5;
    int p0 = blockIdx.x * 128;
    int g = lane >> 2, t4 = lane & 3;
    int r0 = warp * 16 + g;                        // warps 0..7 cover rows 0..127

    // B-row node ids for this thread's two pairs (clamped for tail)
    int pg0 = p0 + r0, pg1 = p0 + r0 + 8;
    int pc0 = pg0 < NPAIRS ? pg0 : NPAIRS - 1;
    int pc1 = pg1 < NPAIRS ? pg1 : NPAIRS - 1;
    const float* Brow0 = latent + (size_t)__ldg(&idx[NPAIRS + pc0]) * 128;
    const float* Brow1 = latent + (size_t)__ldg(&idx[NPAIRS + pc1]) * 128;

    // gather A pair rows (fp32)
    for (int i = tid; i < 128 * 32; i += 256) {
        int p = i >> 5, c8 = (i & 31) * 4;
        int pg = p0 + p; if (pg >= NPAIRS) pg = NPAIRS - 1;
        int na = __ldg(&idx[pg]);
        float4 va = __ldg((const float4*)(latent + (size_t)na * 128 + c8));
        *(float4*)&sA[p * 132 + c8] = va;
    }

    for (int kk = 0; kk < KC; kk++) {
        int k = blockIdx.y * KC + kk;

        float acc[16][4];
#pragma unroll
        for (int nt = 0; nt < 16; nt++)
#pragma unroll
            for (int j = 0; j < 4; j++) acc[nt][j] = 0.f;

        for (int k0 = 0; k0 < 128; k0 += 32) {
            __syncthreads();   // sA ready (1st iter); sW planes free (later)
            {
                const uint32_t* srcB = bilWb + ((size_t)k * 64 + (k0 >> 1)) * 128;
                const uint32_t* srcS = bilWs + ((size_t)k * 64 + (k0 >> 1)) * 128;
#pragma unroll
                for (int u = 0; u < 2; u++) {
                    int i = tid + u * 256;
                    int kp = i >> 5, c4 = (i & 31) * 4;
                    uint4 vb = __ldg((const uint4*)(srcB + kp * 128 + c4));
                    uint4 vs = __ldg((const uint4*)(srcS + kp * 128 + c4));
                    *(uint4*)&sWb[kp * 136 + c4] = vb;
                    *(uint4*)&sWs[kp * 136 + c4] = vs;
                }
            }
            __syncthreads();

#pragma unroll
            for (int ks = 0; ks < 2; ks++) {
                int cb = k0 + ks * 16 + 2 * t4;
                float xl0 = sA[(r0    ) * 132 + cb],     xh0 = sA[(r0    ) * 132 + cb + 1];
                float xl1 = sA[(r0 + 8) * 132 + cb],     xh1 = sA[(r0 + 8) * 132 + cb + 1];
                float xl2 = sA[(r0    ) * 132 + cb + 8], xh2 = sA[(r0    ) * 132 + cb + 9];
                float xl3 = sA[(r0 + 8) * 132 + cb + 8], xh3 = sA[(r0 + 8) * 132 + cb + 9];
                uint32_t ab0 = pack2bf(xl0, xh0);
                uint32_t ab1 = pack2bf(xl1, xh1);
                uint32_t ab2 = pack2bf(xl2, xh2);
                uint32_t ab3 = pack2bf(xl3, xh3);
                float2 f0 = unpack_bf(ab0), f1 = unpack_bf(ab1);
                float2 f2 = unpack_bf(ab2), f3 = unpack_bf(ab3);
                uint32_t as0 = pack2bf(xl0 - f0.x, xh0 - f0.y);
                uint32_t as1 = pack2bf(xl1 - f1.x, xh1 - f1.y);
                uint32_t as2 = pack2bf(xl2 - f2.x, xh2 - f2.y);
                uint32_t as3 = pack2bf(xl3 - f3.x, xh3 - f3.y);
                int kp0 = ks * 8;
#pragma unroll
                for (int nt = 0; nt < 16; nt++) {
                    int e = nt * 8 + g;
                    uint32_t bb0 = sWb[(kp0 + t4    ) * 136 + e];
                    uint32_t bb1 = sWb[(kp0 + t4 + 4) * 136 + e];
                    uint32_t bs0 = sWs[(kp0 + t4    ) * 136 + e];
                    uint32_t bs1 = sWs[(kp0 + t4 + 4) * 136 + e];
                    mma_bf16(acc[nt], ab0, ab1, ab2, ab3, bb0, bb1);
                    mma_bf16(acc[nt], as0, as1, as2, as3, bb0, bb1);
                    mma_bf16(acc[nt], ab0, ab1, ab2, ab3, bs0, bs1);
                }
            }
        }

        // epilogue: dot with B rows read from gmem (L1/L2 resident)
        float plo = 0.f, phi = 0.f;
#pragma unroll
        for (int nt = 0; nt < 16; nt++) {
            int c = nt * 8 + 2 * t4;
            float2 b0 = __ldg((const float2*)(Brow0 + c));
            float2 b1 = __ldg((const float2*)(Brow1 + c));
            plo = fmaf(acc[nt][0], b0.x, plo);
            plo = fmaf(acc[nt][1], b0.y, plo);
            phi = fmaf(acc[nt][2], b1.x, phi);
            phi = fmaf(acc[nt][3], b1.y, phi);
        }
        plo += __shfl_xor_sync(0xffffffffu, plo, 1);
        plo += __shfl_xor_sync(0xffffffffu, plo, 2);
        phi += __shfl_xor_sync(0xffffffffu, phi, 1);
        phi += __shfl_xor_sync(0xffffffffu, phi, 2);
        if (t4 == 0) {
            if (pg0 < NPAIRS) feat[(size_t)pg0 * ZDIM + k] = plo;
            if (pg1 < NPAIRS) feat[(size_t)pg1 * ZDIM + k] = phi;
        }
    }
}

// ------------------------------------------------------------------
// Stage 2: tiny MLP on feat -> predictions
// ------------------------------------------------------------------
__device__ __forceinline__ float elu1(float x) {
    return x > 0.f ? x : expm1f(x);
}

__global__ __launch_bounds__(256) void mlp_kernel(
    const float* __restrict__ feat, const float* __restrict__ bilb,
    const float* __restrict__ dw1, const float* __restrict__ db1,
    const float* __restrict__ dw2, const float* __restrict__ db2,
    float* __restrict__ pred)
{
    int p = blockIdx.x * blockDim.x + threadIdx.x;
    if (p >= NPAIRS) return;

    float f[ZDIM];
#pragma unroll
    for (int k = 0; k < ZDIM; k++)
        f[k] = elu1(feat[(size_t)p * ZDIM + k] + __ldg(&bilb[k]));

    float o = __ldg(&db2[0]);
#pragma unroll
    for (int kk = 0; kk < ZDIM; kk++) {
        float s = __ldg(&db1[kk]);
#pragma unroll
        for (int j = 0; j < ZDIM; j++)
            s = fmaf(f[j], __ldg(&dw1[j * ZDIM + kk]), s);
        o = fmaf(elu1(s), __ldg(&dw2[kk]), o);
    }
    pred[p] = o;
}

// ------------------------------------------------------------------
extern "C" void kernel_launch(void* const* d_in, const int* in_sizes, int n_in,
                              void* d_out, int out_size)
{
    const float* features = (const float*)d_in[0];
    const int*   adj_row  = (const int*)  d_in[1];
    const int*   adj_col  = (const int*)  d_in[2];
    const float* adj_val  = (const float*)d_in[3];
    const int*   idx      = (const int*)  d_in[4];
    const float* W0   = (const float*)d_in[5];
    const float* b0   = (const float*)d_in[6];
    const float* W1   = (const float*)d_in[7];
    const float* b1   = (const float*)d_in[8];
    const float* W2   = (const float*)d_in[9];
    const float* b2   = (const float*)d_in[10];
    const float* bilw = (const float*)d_in[11];
    const float* bilb = (const float*)d_in[12];
    const float* dw1  = (const float*)d_in[13];
    const float* db1  = (const float*)d_in[14];
    const float* dw2  = (const float*)d_in[15];
    const float* db2  = (const float*)d_in[16];

    float* out    = (float*)d_out;
    float* pred   = out;            // [NPAIRS]
    float* latent = out + NPAIRS;   // [N_NODES * NHID]

    float* h;  cudaGetSymbolAddress((void**)&h,  g_buf_h);
    float* x0; cudaGetSymbolAddress((void**)&x0, g_buf_x0);
    float* x1; cudaGetSymbolAddress((void**)&x1, g_buf_x1);
    float* ft; cudaGetSymbolAddress((void**)&ft, g_feat);
    uint32_t* wb;  cudaGetSymbolAddress((void**)&wb,  g_Wb);
    uint32_t* ws;  cudaGetSymbolAddress((void**)&ws,  g_Ws);
    uint32_t* bwb; cudaGetSymbolAddress((void**)&bwb, g_bilWb);
    uint32_t* bws; cudaGetSymbolAddress((void**)&bws, g_bilWs);

    static int smem_set = 0;
    if (!smem_set) {
        cudaFuncSetAttribute(bilinear_kernel,
                             cudaFuncAttributeMaxDynamicSharedMemorySize,
                             BIL_SMEM_BYTES);
        smem_set = 1;
    }

    presplit_kernel<<<(294912 + 255) / 256, 256>>>(W0, W1, W2, bilw);
    rowptr_kernel<<<(N_NODES + 1 + 255) / 256, 256>>>(adj_row);

    const int gemm_grid = (N_NODES + 127) / 128;
    const int spmm_grid = (N_NODES * 32 + 255) / 256;

    gemm_bf16_n128<<<gemm_grid, 256>>>(features, wb, ws, h, N_NODES, NFEAT);
    spmm_kernel<<<spmm_grid, 256>>>(h, adj_col, adj_val, b0, nullptr, x0);

    gemm_bf16_n128<<<gemm_grid, 256>>>(x0, wb + 128 * 128, ws + 128 * 128, h, N_NODES, NHID);
    spmm_kernel<<<spmm_grid, 256>>>(h, adj_col, adj_val, b1, x0, x1);

    gemm_bf16_n128<<<gemm_grid, 256>>>(x1, wb + 192 * 128, ws + 192 * 128, h, N_NODES, NHID);
    spmm_kernel<<<spmm_grid, 256>>>(h, adj_col, adj_val, b2, x1, latent);

    dim3 bil_grid((NPAIRS + 127) / 128, ZDIM / KC);
    bilinear_kernel<<<bil_grid, 256, BIL_SMEM_BYTES>>>(latent, idx, bwb, bws, ft);
    mlp_kernel<<<(NPAIRS + 255) / 256, 256>>>(ft, bilb, dw1, db1, dw2, db2, pred);
}

// round 10
// speedup vs baseline: 1.1635x; 1.0379x over previous
#include <cuda_runtime.h>
#include <cstdint>

#define N_NODES 50000
#define N_EDGES 800000
#define NFEAT   256
#define NHID    128
#define ZDIM    32
#define NPAIRS  10000

// ---- scratch (static device globals; no allocation at runtime) ----
__device__ float    g_buf_h [(size_t)N_NODES * NHID];
__device__ float    g_buf_x0[(size_t)N_NODES * NHID];
__device__ float    g_buf_x1[(size_t)N_NODES * NHID];
__device__ int      g_rowptr[N_NODES + 1];
__device__ float    g_feat[(size_t)NPAIRS * ZDIM];
// pre-split weight planes (bf16x2 pairs along k), FRAGMENT-REMAPPED rows:
// within each 128-word row, word position = (e&7)*16 + (e>>3).
// W0 kp-rows 0..127, W1 128..191, W2 192..255
__device__ uint32_t g_Wb[256 * 128], g_Ws[256 * 128];
__device__ uint32_t g_bilWb[(size_t)ZDIM * 64 * 128];
__device__ uint32_t g_bilWs[(size_t)ZDIM * 64 * 128];

// ------------------------------------------------------------------
// bf16 split helpers
// ------------------------------------------------------------------
__device__ __forceinline__ uint32_t pack2bf(float lo, float hi) {
    uint32_t r;
    asm("cvt.rn.bf16x2.f32 %0, %1, %2;" : "=r"(r) : "f"(hi), "f"(lo));
    return r;
}
__device__ __forceinline__ float2 unpack_bf(uint32_t p) {
    return make_float2(__uint_as_float(p << 16),
                       __uint_as_float(p & 0xffff0000u));
}

__device__ __forceinline__ void mma_bf16(
    float* d, uint32_t a0, uint32_t a1, uint32_t a2, uint32_t a3,
    uint32_t b0, uint32_t b1)
{
    asm volatile(
        "mma.sync.aligned.m16n8k16.row.col.f32.bf16.bf16.f32 "
        "{%0,%1,%2,%3}, {%4,%5,%6,%7}, {%8,%9}, {%0,%1,%2,%3};\n"
        : "+f"(d[0]), "+f"(d[1]), "+f"(d[2]), "+f"(d[3])
        : "r"(a0), "r"(a1), "r"(a2), "r"(a3), "r"(b0), "r"(b1));
}

// ------------------------------------------------------------------
// One-shot weight pre-split + fragment remap.
// pair (kp, c): lo = W[kp*256 + c], hi = W[kp*256 + 128 + c]
// output word index: kp*128 + (c&7)*16 + (c>>3)
// ------------------------------------------------------------------
__global__ void presplit_kernel(const float* __restrict__ W0,
                                const float* __restrict__ W1,
                                const float* __restrict__ W2,
                                const float* __restrict__ bilw)
{
    int i = blockIdx.x * blockDim.x + threadIdx.x;
    const float* src; uint32_t* dstB; uint32_t* dstS; int j;
    if (i < 16384)        { src = W0;   dstB = g_Wb;              dstS = g_Ws;              j = i; }
    else if (i < 24576)   { src = W1;   dstB = g_Wb + 128 * 128;  dstS = g_Ws + 128 * 128;  j = i - 16384; }
    else if (i < 32768)   { src = W2;   dstB = g_Wb + 192 * 128;  dstS = g_Ws + 192 * 128;  j = i - 24576; }
    else if (i < 294912)  { src = bilw; dstB = g_bilWb;           dstS = g_bilWs;           j = i - 32768; }
    else return;
    int kp = j >> 7, c = j & 127;
    float lo = src[(size_t)kp * 256 + c];
    float hi = src[(size_t)kp * 256 + 128 + c];
    uint32_t pb = pack2bf(lo, hi);
    float2 f = unpack_bf(pb);
    int jr = kp * 128 + (c & 7) * 16 + (c >> 3);   // fragment remap
    dstB[jr] = pb;
    dstS[jr] = pack2bf(lo - f.x, hi - f.y);
}

// ------------------------------------------------------------------
__global__ void rowptr_kernel(const int* __restrict__ row) {
    int r = blockIdx.x * blockDim.x + threadIdx.x;
    if (r > N_NODES) return;
    int lo = 0, hi = N_EDGES;
    while (lo < hi) {
        int mid = (lo + hi) >> 1;
        if (row[mid] < r) lo = mid + 1; else hi = mid;
    }
    g_rowptr[r] = lo;
}

// ------------------------------------------------------------------
// Encoder GEMM: C[M,128] = A[M,K] @ Wsplit[K,128], split-bf16 3-MMA.
// BM=128, BK=32, 256 threads. W fragments read as uint4.
// ------------------------------------------------------------------
__global__ __launch_bounds__(256, 2) void gemm_bf16_n128(
    const float* __restrict__ A,
    const uint32_t* __restrict__ Wb, const uint32_t* __restrict__ Ws,
    float* __restrict__ C, int M, int K)
{
    __shared__ uint32_t sAb[128][17], sAs[128][17];   // [row][kpair]
    __shared__ uint32_t sBb[16 * 132], sBs[16 * 132]; // [kpair][fragpos], pad 132

    int tid  = threadIdx.x;
    int lane = tid & 31, warp = tid >> 5;
    int g = lane >> 2, t4 = lane & 3;
    int r0 = warp * 16 + g;
    int row0 = blockIdx.x * 128;

    float acc[16][4];
#pragma unroll
    for (int nt = 0; nt < 16; nt++)
#pragma unroll
        for (int j = 0; j < 4; j++) acc[nt][j] = 0.f;

    for (int k0 = 0; k0 < K; k0 += 32) {
        __syncthreads();
        // A tile: 128 rows x 32 k, split+pack along k (runtime data)
#pragma unroll
        for (int u = 0; u < 4; u++) {
            int i = tid + u * 256;
            int r = i >> 3, q = i & 7;
            int gr = row0 + r;
            float4 v = (gr < M)
                ? __ldg((const float4*)(A + (size_t)gr * K + k0 + 4 * q))
                : make_float4(0.f, 0.f, 0.f, 0.f);
            uint32_t p0 = pack2bf(v.x, v.y);
            uint32_t p1 = pack2bf(v.z, v.w);
            float2 f0 = unpack_bf(p0), f1 = unpack_bf(p1);
            sAb[r][2 * q]     = p0;
            sAb[r][2 * q + 1] = p1;
            sAs[r][2 * q]     = pack2bf(v.x - f0.x, v.y - f0.y);
            sAs[r][2 * q + 1] = pack2bf(v.z - f1.x, v.w - f1.y);
        }
        // B tile: pre-split+remapped planes -> contiguous uint4 copy
        {
            const uint32_t* srcB = Wb + (size_t)(k0 >> 1) * 128;
            const uint32_t* srcS = Ws + (size_t)(k0 >> 1) * 128;
#pragma unroll
            for (int u = 0; u < 2; u++) {
                int i = tid + u * 256;
                int kp = i >> 5, c4 = (i & 31) * 4;
                uint4 vb = __ldg((const uint4*)(srcB + kp * 128 + c4));
                uint4 vs = __ldg((const uint4*)(srcS + kp * 128 + c4));
                *(uint4*)&sBb[kp * 132 + c4] = vb;
                *(uint4*)&sBs[kp * 132 + c4] = vs;
            }
        }
        __syncthreads();

#pragma unroll
        for (int ks = 0; ks < 2; ks++) {
            int kp0 = ks * 8;
            uint32_t ab0 = sAb[r0    ][kp0 + t4];
            uint32_t ab1 = sAb[r0 + 8][kp0 + t4];
            uint32_t ab2 = sAb[r0    ][kp0 + t4 + 4];
            uint32_t ab3 = sAb[r0 + 8][kp0 + t4 + 4];
            uint32_t as0 = sAs[r0    ][kp0 + t4];
            uint32_t as1 = sAs[r0 + 8][kp0 + t4];
            uint32_t as2 = sAs[r0    ][kp0 + t4 + 4];
            uint32_t as3 = sAs[r0 + 8][kp0 + t4 + 4];
            const uint4* rb0 = (const uint4*)&sBb[(kp0 + t4    ) * 132 + g * 16];
            const uint4* rb1 = (const uint4*)&sBb[(kp0 + t4 + 4) * 132 + g * 16];
            const uint4* rs0 = (const uint4*)&sBs[(kp0 + t4    ) * 132 + g * 16];
            const uint4* rs1 = (const uint4*)&sBs[(kp0 + t4 + 4) * 132 + g * 16];
#pragma unroll
            for (int nt4 = 0; nt4 < 4; nt4++) {
                uint4 b0 = rb0[nt4], b1 = rb1[nt4];
                uint4 s0 = rs0[nt4], s1 = rs1[nt4];
                uint32_t bb0[4] = {b0.x, b0.y, b0.z, b0.w};
                uint32_t bb1[4] = {b1.x, b1.y, b1.z, b1.w};
                uint32_t bs0[4] = {s0.x, s0.y, s0.z, s0.w};
                uint32_t bs1[4] = {s1.x, s1.y, s1.z, s1.w};
#pragma unroll
                for (int q = 0; q < 4; q++) {
                    int nt = nt4 * 4 + q;
                    mma_bf16(acc[nt], ab0, ab1, ab2, ab3, bb0[q], bb1[q]);
                    mma_bf16(acc[nt], as0, as1, as2, as3, bb0[q], bb1[q]);
                    mma_bf16(acc[nt], ab0, ab1, ab2, ab3, bs0[q], bs1[q]);
                }
            }
        }
    }

#pragma unroll
    for (int nt = 0; nt < 16; nt++) {
        int c = nt * 8 + 2 * t4;
        int gr0 = row0 + r0, gr1 = gr0 + 8;
        if (gr0 < M)
            *(float2*)(C + (size_t)gr0 * 128 + c) = make_float2(acc[nt][0], acc[nt][1]);
        if (gr1 < M)
            *(float2*)(C + (size_t)gr1 * 128 + c) = make_float2(acc[nt][2], acc[nt][3]);
    }
}

// ------------------------------------------------------------------
// SpMM: one warp per destination row, 4-edge unroll, __ldg gathers
// ------------------------------------------------------------------
__global__ __launch_bounds__(256) void spmm_kernel(
    const float* __restrict__ H, const int* __restrict__ col,
    const float* __restrict__ val, const float* __restrict__ bias,
    const float* __restrict__ res, float* __restrict__ out)
{
    int w = (blockIdx.x * blockDim.x + threadIdx.x) >> 5;
    if (w >= N_NODES) return;
    int lane = threadIdx.x & 31;

    const float4* Hv = (const float4*)H;
    float4 acc = make_float4(0.f, 0.f, 0.f, 0.f);
    int s = g_rowptr[w], e = g_rowptr[w + 1];
    int i = s;
    for (; i + 3 < e; i += 4) {
        int   c0 = __ldg(&col[i]),     c1 = __ldg(&col[i + 1]);
        int   c2 = __ldg(&col[i + 2]), c3 = __ldg(&col[i + 3]);
        float v0 = __ldg(&val[i]),     v1 = __ldg(&val[i + 1]);
        float v2 = __ldg(&val[i + 2]), v3 = __ldg(&val[i + 3]);
        float4 h0 = __ldg(&Hv[(size_t)c0 * 32 + lane]);
        float4 h1 = __ldg(&Hv[(size_t)c1 * 32 + lane]);
        float4 h2 = __ldg(&Hv[(size_t)c2 * 32 + lane]);
        float4 h3 = __ldg(&Hv[(size_t)c3 * 32 + lane]);
        acc.x = fmaf(v0, h0.x, acc.x); acc.y = fmaf(v0, h0.y, acc.y);
        acc.z = fmaf(v0, h0.z, acc.z); acc.w = fmaf(v0, h0.w, acc.w);
        acc.x = fmaf(v1, h1.x, acc.x); acc.y = fmaf(v1, h1.y, acc.y);
        acc.z = fmaf(v1, h1.z, acc.z); acc.w = fmaf(v1, h1.w, acc.w);
        acc.x = fmaf(v2, h2.x, acc.x); acc.y = fmaf(v2, h2.y, acc.y);
        acc.z = fmaf(v2, h2.z, acc.z); acc.w = fmaf(v2, h2.w, acc.w);
        acc.x = fmaf(v3, h3.x, acc.x); acc.y = fmaf(v3, h3.y, acc.y);
        acc.z = fmaf(v3, h3.z, acc.z); acc.w = fmaf(v3, h3.w, acc.w);
    }
    for (; i < e; i++) {
        int   c0 = __ldg(&col[i]);
        float v0 = __ldg(&val[i]);
        float4 h0 = __ldg(&Hv[(size_t)c0 * 32 + lane]);
        acc.x = fmaf(v0, h0.x, acc.x); acc.y = fmaf(v0, h0.y, acc.y);
        acc.z = fmaf(v0, h0.z, acc.z); acc.w = fmaf(v0, h0.w, acc.w);
    }

    float4 bb = __ldg(&((const float4*)bias)[lane]);
    float4 o;
    o.x = fmaxf(acc.x + bb.x, 0.f);
    o.y = fmaxf(acc.y + bb.y, 0.f);
    o.z = fmaxf(acc.z + bb.z, 0.f);
    o.w = fmaxf(acc.w + bb.w, 0.f);
    size_t vbase = (size_t)w * 32 + lane;
    if (res) {
        float4 rv = __ldg(&((const float4*)res)[vbase]);
        o.x += rv.x; o.y += rv.y; o.z += rv.z; o.w += rv.w;
    }
    ((float4*)out)[vbase] = o;
}

// ------------------------------------------------------------------
// Bilinear stage 1: tile = 128 pairs x (KC k-slices), split-bf16 3-MMA.
// A gathered+split into bf16 planes [128][68] (stride 68 = conflict-free).
// W fragments read as uint4 from remapped planes. B rows from gmem epilogue.
// ------------------------------------------------------------------
#define KC 4
#define BIL_SMEM_WORDS (2 * 128 * 68 + 2 * 16 * 132)
#define BIL_SMEM_BYTES (BIL_SMEM_WORDS * 4)

__global__ __launch_bounds__(256, 2) void bilinear_kernel(
    const float* __restrict__ latent, const int* __restrict__ idx,
    const uint32_t* __restrict__ bilWb, const uint32_t* __restrict__ bilWs,
    float* __restrict__ feat)
{
    extern __shared__ uint32_t smem[];
    uint32_t* sAb = smem;                      // [128][68] big plane (all 64 kp)
    uint32_t* sAs = sAb + 128 * 68;            // [128][68] small plane
    uint32_t* sWb = sAs + 128 * 68;            // [16 kpair][132 fragpos]
    uint32_t* sWs = sWb + 16 * 132;

    int tid  = threadIdx.x;
    int lane = tid & 31, warp = tid >> 5;
    int p0 = blockIdx.x * 128;
    int g = lane >> 2, t4 = lane & 3;
    int r0 = warp * 16 + g;                    // warps 0..7 cover rows 0..127

    // B-row node ids for this thread's two pairs (clamped for tail)
    int pg0 = p0 + r0, pg1 = p0 + r0 + 8;
    int pc0 = pg0 < NPAIRS ? pg0 : NPAIRS - 1;
    int pc1 = pg1 < NPAIRS ? pg1 : NPAIRS - 1;
    const float* Brow0 = latent + (size_t)__ldg(&idx[NPAIRS + pc0]) * 128;
    const float* Brow1 = latent + (size_t)__ldg(&idx[NPAIRS + pc1]) * 128;

    // gather A pair rows, split+pack to bf16 planes
    for (int i = tid; i < 128 * 32; i += 256) {
        int p = i >> 5, l32 = i & 31;
        int c8 = l32 * 4, kp = l32 * 2;
        int pg = p0 + p; if (pg >= NPAIRS) pg = NPAIRS - 1;
        int na = __ldg(&idx[pg]);
        float4 v = __ldg((const float4*)(latent + (size_t)na * 128 + c8));
        uint32_t b0 = pack2bf(v.x, v.y);
        uint32_t b1 = pack2bf(v.z, v.w);
        float2 f0 = unpack_bf(b0), f1 = unpack_bf(b1);
        sAb[p * 68 + kp]     = b0;
        sAb[p * 68 + kp + 1] = b1;
        sAs[p * 68 + kp]     = pack2bf(v.x - f0.x, v.y - f0.y);
        sAs[p * 68 + kp + 1] = pack2bf(v.z - f1.x, v.w - f1.y);
    }

    for (int kk = 0; kk < KC; kk++) {
        int k = blockIdx.y * KC + kk;

        float acc[16][4];
#pragma unroll
        for (int nt = 0; nt < 16; nt++)
#pragma unroll
            for (int j = 0; j < 4; j++) acc[nt][j] = 0.f;

        for (int k0 = 0; k0 < 128; k0 += 32) {
            __syncthreads();   // sA ready (1st iter); sW planes free (later)
            {
                const uint32_t* srcB = bilWb + ((size_t)k * 64 + (k0 >> 1)) * 128;
                const uint32_t* srcS = bilWs + ((size_t)k * 64 + (k0 >> 1)) * 128;
#pragma unroll
                for (int u = 0; u < 2; u++) {
                    int i = tid + u * 256;
                    int kp = i >> 5, c4 = (i & 31) * 4;
                    uint4 vb = __ldg((const uint4*)(srcB + kp * 128 + c4));
                    uint4 vs = __ldg((const uint4*)(srcS + kp * 128 + c4));
                    *(uint4*)&sWb[kp * 132 + c4] = vb;
                    *(uint4*)&sWs[kp * 132 + c4] = vs;
                }
            }
            __syncthreads();

#pragma unroll
            for (int ks = 0; ks < 2; ks++) {
                int kpg = (k0 >> 1) + ks * 8;   // global kpair base in sA planes
                uint32_t ab0 = sAb[(r0    ) * 68 + kpg + t4];
                uint32_t ab1 = sAb[(r0 + 8) * 68 + kpg + t4];
                uint32_t ab2 = sAb[(r0    ) * 68 + kpg + t4 + 4];
                uint32_t ab3 = sAb[(r0 + 8) * 68 + kpg + t4 + 4];
                uint32_t as0 = sAs[(r0    ) * 68 + kpg + t4];
                uint32_t as1 = sAs[(r0 + 8) * 68 + kpg + t4];
                uint32_t as2 = sAs[(r0    ) * 68 + kpg + t4 + 4];
                uint32_t as3 = sAs[(r0 + 8) * 68 + kpg + t4 + 4];
                int kp0 = ks * 8;
                const uint4* rb0 = (const uint4*)&sWb[(kp0 + t4    ) * 132 + g * 16];
                const uint4* rb1 = (const uint4*)&sWb[(kp0 + t4 + 4) * 132 + g * 16];
                const uint4* rs0 = (const uint4*)&sWs[(kp0 + t4    ) * 132 + g * 16];
                const uint4* rs1 = (const uint4*)&sWs[(kp0 + t4 + 4) * 132 + g * 16];
#pragma unroll
                for (int nt4 = 0; nt4 < 4; nt4++) {
                    uint4 b0 = rb0[nt4], b1 = rb1[nt4];
                    uint4 s0 = rs0[nt4], s1 = rs1[nt4];
                    uint32_t bb0[4] = {b0.x, b0.y, b0.z, b0.w};
                    uint32_t bb1[4] = {b1.x, b1.y, b1.z, b1.w};
                    uint32_t bs0[4] = {s0.x, s0.y, s0.z, s0.w};
                    uint32_t bs1[4] = {s1.x, s1.y, s1.z, s1.w};
#pragma unroll
                    for (int q = 0; q < 4; q++) {
                        int nt = nt4 * 4 + q;
                        mma_bf16(acc[nt], ab0, ab1, ab2, ab3, bb0[q], bb1[q]);
                        mma_bf16(acc[nt], as0, as1, as2, as3, bb0[q], bb1[q]);
                        mma_bf16(acc[nt], ab0, ab1, ab2, ab3, bs0[q], bs1[q]);
                    }
                }
            }
        }

        // epilogue: dot with B rows read from gmem (L1/L2 resident)
        float plo = 0.f, phi = 0.f;
#pragma unroll
        for (int nt = 0; nt < 16; nt++) {
            int c = nt * 8 + 2 * t4;
            float2 b0 = __ldg((const float2*)(Brow0 + c));
            float2 b1 = __ldg((const float2*)(Brow1 + c));
            plo = fmaf(acc[nt][0], b0.x, plo);
            plo = fmaf(acc[nt][1], b0.y, plo);
            phi = fmaf(acc[nt][2], b1.x, phi);
            phi = fmaf(acc[nt][3], b1.y, phi);
        }
        plo += __shfl_xor_sync(0xffffffffu, plo, 1);
        plo += __shfl_xor_sync(0xffffffffu, plo, 2);
        phi += __shfl_xor_sync(0xffffffffu, phi, 1);
        phi += __shfl_xor_sync(0xffffffffu, phi, 2);
        if (t4 == 0) {
            if (pg0 < NPAIRS) feat[(size_t)pg0 * ZDIM + k] = plo;
            if (pg1 < NPAIRS) feat[(size_t)pg1 * ZDIM + k] = phi;
        }
    }
}

// ------------------------------------------------------------------
// Stage 2: tiny MLP on feat -> predictions
// ------------------------------------------------------------------
__device__ __forceinline__ float elu1(float x) {
    return x > 0.f ? x : expm1f(x);
}

__global__ __launch_bounds__(256) void mlp_kernel(
    const float* __restrict__ feat, const float* __restrict__ bilb,
    const float* __restrict__ dw1, const float* __restrict__ db1,
    const float* __restrict__ dw2, const float* __restrict__ db2,
    float* __restrict__ pred)
{
    int p = blockIdx.x * blockDim.x + threadIdx.x;
    if (p >= NPAIRS) return;

    float f[ZDIM];
#pragma unroll
    for (int k = 0; k < ZDIM; k++)
        f[k] = elu1(feat[(size_t)p * ZDIM + k] + __ldg(&bilb[k]));

    float o = __ldg(&db2[0]);
#pragma unroll
    for (int kk = 0; kk < ZDIM; kk++) {
        float s = __ldg(&db1[kk]);
#pragma unroll
        for (int j = 0; j < ZDIM; j++)
            s = fmaf(f[j], __ldg(&dw1[j * ZDIM + kk]), s);
        o = fmaf(elu1(s), __ldg(&dw2[kk]), o);
    }
    pred[p] = o;
}

// ------------------------------------------------------------------
extern "C" void kernel_launch(void* const* d_in, const int* in_sizes, int n_in,
                              void* d_out, int out_size)
{
    const float* features = (const float*)d_in[0];
    const int*   adj_row  = (const int*)  d_in[1];
    const int*   adj_col  = (const int*)  d_in[2];
    const float* adj_val  = (const float*)d_in[3];
    const int*   idx      = (const int*)  d_in[4];
    const float* W0   = (const float*)d_in[5];
    const float* b0   = (const float*)d_in[6];
    const float* W1   = (const float*)d_in[7];
    const float* b1   = (const float*)d_in[8];
    const float* W2   = (const float*)d_in[9];
    const float* b2   = (const float*)d_in[10];
    const float* bilw = (const float*)d_in[11];
    const float* bilb = (const float*)d_in[12];
    const float* dw1  = (const float*)d_in[13];
    const float* db1  = (const float*)d_in[14];
    const float* dw2  = (const float*)d_in[15];
    const float* db2  = (const float*)d_in[16];

    float* out    = (float*)d_out;
    float* pred   = out;            // [NPAIRS]
    float* latent = out + NPAIRS;   // [N_NODES * NHID]

    float* h;  cudaGetSymbolAddress((void**)&h,  g_buf_h);
    float* x0; cudaGetSymbolAddress((void**)&x0, g_buf_x0);
    float* x1; cudaGetSymbolAddress((void**)&x1, g_buf_x1);
    float* ft; cudaGetSymbolAddress((void**)&ft, g_feat);
    uint32_t* wb;  cudaGetSymbolAddress((void**)&wb,  g_Wb);
    uint32_t* ws;  cudaGetSymbolAddress((void**)&ws,  g_Ws);
    uint32_t* bwb; cudaGetSymbolAddress((void**)&bwb, g_bilWb);
    uint32_t* bws; cudaGetSymbolAddress((void**)&bws, g_bilWs);

    static int smem_set = 0;
    if (!smem_set) {
        cudaFuncSetAttribute(bilinear_kernel,
                             cudaFuncAttributeMaxDynamicSharedMemorySize,
                             BIL_SMEM_BYTES);
        smem_set = 1;
    }

    presplit_kernel<<<(294912 + 255) / 256, 256>>>(W0, W1, W2, bilw);
    rowptr_kernel<<<(N_NODES + 1 + 255) / 256, 256>>>(adj_row);

    const int gemm_grid = (N_NODES + 127) / 128;
    const int spmm_grid = (N_NODES * 32 + 255) / 256;

    gemm_bf16_n128<<<gemm_grid, 256>>>(features, wb, ws, h, N_NODES, NFEAT);
    spmm_kernel<<<spmm_grid, 256>>>(h, adj_col, adj_val, b0, nullptr, x0);

    gemm_bf16_n128<<<gemm_grid, 256>>>(x0, wb + 128 * 128, ws + 128 * 128, h, N_NODES, NHID);
    spmm_kernel<<<spmm_grid, 256>>>(h, adj_col, adj_val, b1, x0, x1);

    gemm_bf16_n128<<<gemm_grid, 256>>>(x1, wb + 192 * 128, ws + 192 * 128, h, N_NODES, NHID);
    spmm_kernel<<<spmm_grid, 256>>>(h, adj_col, adj_val, b2, x1, latent);

    dim3 bil_grid((NPAIRS + 127) / 128, ZDIM / KC);
    bilinear_kernel<<<bil_grid, 256, BIL_SMEM_BYTES>>>(latent, idx, bwb, bws, ft);
    mlp_kernel<<<(NPAIRS + 255) / 256, 256>>>(ft, bilb, dw1, db1, dw2, db2, pred);
}

// round 11
// speedup vs baseline: 1.1674x; 1.0033x over previous
#include <cuda_runtime.h>
#include <cstdint>

#define N_NODES 50000
#define N_EDGES 800000
#define NFEAT   256
#define NHID    128
#define ZDIM    32
#define NPAIRS  10000

// ---- scratch (static device globals; no allocation at runtime) ----
__device__ float    g_buf_h [(size_t)N_NODES * NHID];
__device__ float    g_buf_x0[(size_t)N_NODES * NHID];
__device__ float    g_buf_x1[(size_t)N_NODES * NHID];
__device__ int      g_rowptr[N_NODES + 1];
__device__ float    g_feat[(size_t)NPAIRS * ZDIM];
// pre-split weight planes (bf16x2 pairs along k), FRAGMENT-REMAPPED rows:
// within each 128-word row, word position = (e&7)*16 + (e>>3).
__device__ uint32_t g_Wb[256 * 128], g_Ws[256 * 128];
__device__ uint32_t g_bilWb[(size_t)ZDIM * 64 * 128];
__device__ uint32_t g_bilWs[(size_t)ZDIM * 64 * 128];

// ------------------------------------------------------------------
// bf16 split helpers
// ------------------------------------------------------------------
__device__ __forceinline__ uint32_t pack2bf(float lo, float hi) {
    uint32_t r;
    asm("cvt.rn.bf16x2.f32 %0, %1, %2;" : "=r"(r) : "f"(hi), "f"(lo));
    return r;
}
__device__ __forceinline__ float2 unpack_bf(uint32_t p) {
    return make_float2(__uint_as_float(p << 16),
                       __uint_as_float(p & 0xffff0000u));
}

__device__ __forceinline__ void mma_bf16(
    float* d, uint32_t a0, uint32_t a1, uint32_t a2, uint32_t a3,
    uint32_t b0, uint32_t b1)
{
    asm volatile(
        "mma.sync.aligned.m16n8k16.row.col.f32.bf16.bf16.f32 "
        "{%0,%1,%2,%3}, {%4,%5,%6,%7}, {%8,%9}, {%0,%1,%2,%3};\n"
        : "+f"(d[0]), "+f"(d[1]), "+f"(d[2]), "+f"(d[3])
        : "r"(a0), "r"(a1), "r"(a2), "r"(a3), "r"(b0), "r"(b1));
}

// cp.async helpers
__device__ __forceinline__ void cp16(uint32_t smem_addr, const void* gptr) {
    asm volatile("cp.async.cg.shared.global [%0], [%1], 16;"
                 :: "r"(smem_addr), "l"(gptr));
}
__device__ __forceinline__ void cp_commit() {
    asm volatile("cp.async.commit_group;");
}

// ------------------------------------------------------------------
// One-shot weight pre-split + fragment remap.
// ------------------------------------------------------------------
__global__ void presplit_kernel(const float* __restrict__ W0,
                                const float* __restrict__ W1,
                                const float* __restrict__ W2,
                                const float* __restrict__ bilw)
{
    int i = blockIdx.x * blockDim.x + threadIdx.x;
    const float* src; uint32_t* dstB; uint32_t* dstS; int j;
    if (i < 16384)        { src = W0;   dstB = g_Wb;              dstS = g_Ws;              j = i; }
    else if (i < 24576)   { src = W1;   dstB = g_Wb + 128 * 128;  dstS = g_Ws + 128 * 128;  j = i - 16384; }
    else if (i < 32768)   { src = W2;   dstB = g_Wb + 192 * 128;  dstS = g_Ws + 192 * 128;  j = i - 24576; }
    else if (i < 294912)  { src = bilw; dstB = g_bilWb;           dstS = g_bilWs;           j = i - 32768; }
    else return;
    int kp = j >> 7, c = j & 127;
    float lo = src[(size_t)kp * 256 + c];
    float hi = src[(size_t)kp * 256 + 128 + c];
    uint32_t pb = pack2bf(lo, hi);
    float2 f = unpack_bf(pb);
    int jr = kp * 128 + (c & 7) * 16 + (c >> 3);   // fragment remap
    dstB[jr] = pb;
    dstS[jr] = pack2bf(lo - f.x, hi - f.y);
}

// ------------------------------------------------------------------
__global__ void rowptr_kernel(const int* __restrict__ row) {
    int r = blockIdx.x * blockDim.x + threadIdx.x;
    if (r > N_NODES) return;
    int lo = 0, hi = N_EDGES;
    while (lo < hi) {
        int mid = (lo + hi) >> 1;
        if (row[mid] < r) lo = mid + 1; else hi = mid;
    }
    g_rowptr[r] = lo;
}

// ------------------------------------------------------------------
// Encoder GEMM: unchanged from R10 (known-good).
// ------------------------------------------------------------------
__global__ __launch_bounds__(256, 2) void gemm_bf16_n128(
    const float* __restrict__ A,
    const uint32_t* __restrict__ Wb, const uint32_t* __restrict__ Ws,
    float* __restrict__ C, int M, int K)
{
    __shared__ uint32_t sAb[128][17], sAs[128][17];
    __shared__ uint32_t sBb[16 * 132], sBs[16 * 132];

    int tid  = threadIdx.x;
    int lane = tid & 31, warp = tid >> 5;
    int g = lane >> 2, t4 = lane & 3;
    int r0 = warp * 16 + g;
    int row0 = blockIdx.x * 128;

    float acc[16][4];
#pragma unroll
    for (int nt = 0; nt < 16; nt++)
#pragma unroll
        for (int j = 0; j < 4; j++) acc[nt][j] = 0.f;

    for (int k0 = 0; k0 < K; k0 += 32) {
        __syncthreads();
#pragma unroll
        for (int u = 0; u < 4; u++) {
            int i = tid + u * 256;
            int r = i >> 3, q = i & 7;
            int gr = row0 + r;
            float4 v = (gr < M)
                ? __ldg((const float4*)(A + (size_t)gr * K + k0 + 4 * q))
                : make_float4(0.f, 0.f, 0.f, 0.f);
            uint32_t p0 = pack2bf(v.x, v.y);
            uint32_t p1 = pack2bf(v.z, v.w);
            float2 f0 = unpack_bf(p0), f1 = unpack_bf(p1);
            sAb[r][2 * q]     = p0;
            sAb[r][2 * q + 1] = p1;
            sAs[r][2 * q]     = pack2bf(v.x - f0.x, v.y - f0.y);
            sAs[r][2 * q + 1] = pack2bf(v.z - f1.x, v.w - f1.y);
        }
        {
            const uint32_t* srcB = Wb + (size_t)(k0 >> 1) * 128;
            const uint32_t* srcS = Ws + (size_t)(k0 >> 1) * 128;
#pragma unroll
            for (int u = 0; u < 2; u++) {
                int i = tid + u * 256;
                int kp = i >> 5, c4 = (i & 31) * 4;
                uint4 vb = __ldg((const uint4*)(srcB + kp * 128 + c4));
                uint4 vs = __ldg((const uint4*)(srcS + kp * 128 + c4));
                *(uint4*)&sBb[kp * 132 + c4] = vb;
                *(uint4*)&sBs[kp * 132 + c4] = vs;
            }
        }
        __syncthreads();

#pragma unroll
        for (int ks = 0; ks < 2; ks++) {
            int kp0 = ks * 8;
            uint32_t ab0 = sAb[r0    ][kp0 + t4];
            uint32_t ab1 = sAb[r0 + 8][kp0 + t4];
            uint32_t ab2 = sAb[r0    ][kp0 + t4 + 4];
            uint32_t ab3 = sAb[r0 + 8][kp0 + t4 + 4];
            uint32_t as0 = sAs[r0    ][kp0 + t4];
            uint32_t as1 = sAs[r0 + 8][kp0 + t4];
            uint32_t as2 = sAs[r0    ][kp0 + t4 + 4];
            uint32_t as3 = sAs[r0 + 8][kp0 + t4 + 4];
            const uint4* rb0 = (const uint4*)&sBb[(kp0 + t4    ) * 132 + g * 16];
            const uint4* rb1 = (const uint4*)&sBb[(kp0 + t4 + 4) * 132 + g * 16];
            const uint4* rs0 = (const uint4*)&sBs[(kp0 + t4    ) * 132 + g * 16];
            const uint4* rs1 = (const uint4*)&sBs[(kp0 + t4 + 4) * 132 + g * 16];
#pragma unroll
            for (int nt4 = 0; nt4 < 4; nt4++) {
                uint4 b0 = rb0[nt4], b1 = rb1[nt4];
                uint4 s0 = rs0[nt4], s1 = rs1[nt4];
                uint32_t bb0[4] = {b0.x, b0.y, b0.z, b0.w};
                uint32_t bb1[4] = {b1.x, b1.y, b1.z, b1.w};
                uint32_t bs0[4] = {s0.x, s0.y, s0.z, s0.w};
                uint32_t bs1[4] = {s1.x, s1.y, s1.z, s1.w};
#pragma unroll
                for (int q = 0; q < 4; q++) {
                    int nt = nt4 * 4 + q;
                    mma_bf16(acc[nt], ab0, ab1, ab2, ab3, bb0[q], bb1[q]);
                    mma_bf16(acc[nt], as0, as1, as2, as3, bb0[q], bb1[q]);
                    mma_bf16(acc[nt], ab0, ab1, ab2, ab3, bs0[q], bs1[q]);
                }
            }
        }
    }

#pragma unroll
    for (int nt = 0; nt < 16; nt++) {
        int c = nt * 8 + 2 * t4;
        int gr0 = row0 + r0, gr1 = gr0 + 8;
        if (gr0 < M)
            *(float2*)(C + (size_t)gr0 * 128 + c) = make_float2(acc[nt][0], acc[nt][1]);
        if (gr1 < M)
            *(float2*)(C + (size_t)gr1 * 128 + c) = make_float2(acc[nt][2], acc[nt][3]);
    }
}

// ------------------------------------------------------------------
// SpMM: one warp per destination row, 8-edge unroll for deeper MLP
// ------------------------------------------------------------------
__global__ __launch_bounds__(256) void spmm_kernel(
    const float* __restrict__ H, const int* __restrict__ col,
    const float* __restrict__ val, const float* __restrict__ bias,
    const float* __restrict__ res, float* __restrict__ out)
{
    int w = (blockIdx.x * blockDim.x + threadIdx.x) >> 5;
    if (w >= N_NODES) return;
    int lane = threadIdx.x & 31;

    const float4* Hv = (const float4*)H;
    float4 acc = make_float4(0.f, 0.f, 0.f, 0.f);
    int s = g_rowptr[w], e = g_rowptr[w + 1];
    int i = s;
    for (; i + 7 < e; i += 8) {
        int cc[8]; float vv[8]; float4 hh[8];
#pragma unroll
        for (int u = 0; u < 8; u++) { cc[u] = __ldg(&col[i + u]); vv[u] = __ldg(&val[i + u]); }
#pragma unroll
        for (int u = 0; u < 8; u++) hh[u] = __ldg(&Hv[(size_t)cc[u] * 32 + lane]);
#pragma unroll
        for (int u = 0; u < 8; u++) {
            acc.x = fmaf(vv[u], hh[u].x, acc.x);
            acc.y = fmaf(vv[u], hh[u].y, acc.y);
            acc.z = fmaf(vv[u], hh[u].z, acc.z);
            acc.w = fmaf(vv[u], hh[u].w, acc.w);
        }
    }
    for (; i + 3 < e; i += 4) {
        int cc[4]; float vv[4]; float4 hh[4];
#pragma unroll
        for (int u = 0; u < 4; u++) { cc[u] = __ldg(&col[i + u]); vv[u] = __ldg(&val[i + u]); }
#pragma unroll
        for (int u = 0; u < 4; u++) hh[u] = __ldg(&Hv[(size_t)cc[u] * 32 + lane]);
#pragma unroll
        for (int u = 0; u < 4; u++) {
            acc.x = fmaf(vv[u], hh[u].x, acc.x);
            acc.y = fmaf(vv[u], hh[u].y, acc.y);
            acc.z = fmaf(vv[u], hh[u].z, acc.z);
            acc.w = fmaf(vv[u], hh[u].w, acc.w);
        }
    }
    for (; i < e; i++) {
        int   c0 = __ldg(&col[i]);
        float v0 = __ldg(&val[i]);
        float4 h0 = __ldg(&Hv[(size_t)c0 * 32 + lane]);
        acc.x = fmaf(v0, h0.x, acc.x); acc.y = fmaf(v0, h0.y, acc.y);
        acc.z = fmaf(v0, h0.z, acc.z); acc.w = fmaf(v0, h0.w, acc.w);
    }

    float4 bb = __ldg(&((const float4*)bias)[lane]);
    float4 o;
    o.x = fmaxf(acc.x + bb.x, 0.f);
    o.y = fmaxf(acc.y + bb.y, 0.f);
    o.z = fmaxf(acc.z + bb.z, 0.f);
    o.w = fmaxf(acc.w + bb.w, 0.f);
    size_t vbase = (size_t)w * 32 + lane;
    if (res) {
        float4 rv = __ldg(&((const float4*)res)[vbase]);
        o.x += rv.x; o.y += rv.y; o.z += rv.z; o.w += rv.w;
    }
    ((float4*)out)[vbase] = o;
}

// ------------------------------------------------------------------
// Bilinear stage 1: split-bf16 3-MMA with cp.async double-buffered W.
// Flattened 16-chunk loop (4 k-slices x 4 k0-chunks), ping-pong W bufs.
// smem: sAb/sAs [128][68] + 2 x (sWb+sWs)[16][132] = ~101KB -> 2 CTA/SM
// ------------------------------------------------------------------
#define KC 4
#define WBUF_WORDS (2 * 16 * 132)
#define BIL_SMEM_WORDS (2 * 128 * 68 + 2 * WBUF_WORDS)
#define BIL_SMEM_BYTES (BIL_SMEM_WORDS * 4)

__global__ __launch_bounds__(256, 2) void bilinear_kernel(
    const float* __restrict__ latent, const int* __restrict__ idx,
    const uint32_t* __restrict__ bilWb, const uint32_t* __restrict__ bilWs,
    float* __restrict__ feat)
{
    extern __shared__ uint32_t smem[];
    uint32_t* sAb = smem;                      // [128][68] big plane
    uint32_t* sAs = sAb + 128 * 68;            // [128][68] small plane
    uint32_t* sWbase = sAs + 128 * 68;         // 2 x {sWb[16*132], sWs[16*132]}

    int tid  = threadIdx.x;
    int lane = tid & 31, warp = tid >> 5;
    int p0 = blockIdx.x * 128;
    int g = lane >> 2, t4 = lane & 3;
    int r0 = warp * 16 + g;

    // B-row pointers for this thread's two pairs
    int pg0 = p0 + r0, pg1 = p0 + r0 + 8;
    int pc0 = pg0 < NPAIRS ? pg0 : NPAIRS - 1;
    int pc1 = pg1 < NPAIRS ? pg1 : NPAIRS - 1;
    const float* Brow0 = latent + (size_t)__ldg(&idx[NPAIRS + pc0]) * 128;
    const float* Brow1 = latent + (size_t)__ldg(&idx[NPAIRS + pc1]) * 128;

    // per-thread cp.async coordinates (2 copies of 16B per plane)
    int cp_kp[2], cp_c4[2];
#pragma unroll
    for (int u = 0; u < 2; u++) {
        int i = tid + u * 256;
        cp_kp[u] = i >> 5; cp_c4[u] = (i & 31) * 4;
    }

    // issue W chunk gch into buffer buf
    auto issue_chunk = [&](int gch, int buf) {
        int k = blockIdx.y * KC + (gch >> 2);
        int kpb = (gch & 3) * 16;              // kpair base within k-slice
        const uint32_t* srcB = bilWb + ((size_t)k * 64 + kpb) * 128;
        const uint32_t* srcS = bilWs + ((size_t)k * 64 + kpb) * 128;
        uint32_t* dWb = sWbase + buf * WBUF_WORDS;
        uint32_t* dWs = dWb + 16 * 132;
        uint32_t ab = (uint32_t)__cvta_generic_to_shared(dWb);
        uint32_t as = (uint32_t)__cvta_generic_to_shared(dWs);
#pragma unroll
        for (int u = 0; u < 2; u++) {
            int off = cp_kp[u] * 132 + cp_c4[u];
            int src = cp_kp[u] * 128 + cp_c4[u];
            cp16(ab + off * 4, srcB + src);
            cp16(as + off * 4, srcS + src);
        }
        cp_commit();
    };

    // gather A pair rows, split+pack to bf16 planes
    for (int i = tid; i < 128 * 32; i += 256) {
        int p = i >> 5, l32 = i & 31;
        int c8 = l32 * 4, kp = l32 * 2;
        int pg = p0 + p; if (pg >= NPAIRS) pg = NPAIRS - 1;
        int na = __ldg(&idx[pg]);
        float4 v = __ldg((const float4*)(latent + (size_t)na * 128 + c8));
        uint32_t b0 = pack2bf(v.x, v.y);
        uint32_t b1 = pack2bf(v.z, v.w);
        float2 f0 = unpack_bf(b0), f1 = unpack_bf(b1);
        sAb[p * 68 + kp]     = b0;
        sAb[p * 68 + kp + 1] = b1;
        sAs[p * 68 + kp]     = pack2bf(v.x - f0.x, v.y - f0.y);
        sAs[p * 68 + kp + 1] = pack2bf(v.z - f1.x, v.w - f1.y);
    }

    issue_chunk(0, 0);   // prologue prefetch

    float acc[16][4];
    for (int gch = 0; gch < 16; gch++) {
        if ((gch & 3) == 0) {
#pragma unroll
            for (int nt = 0; nt < 16; nt++)
#pragma unroll
                for (int j = 0; j < 4; j++) acc[nt][j] = 0.f;
        }
        if (gch + 1 < 16) {
            issue_chunk(gch + 1, (gch + 1) & 1);
            asm volatile("cp.async.wait_group 1;");
        } else {
            asm volatile("cp.async.wait_group 0;");
        }
        __syncthreads();   // chunk gch visible; also covers sA on gch=0

        uint32_t* cWb = sWbase + (gch & 1) * WBUF_WORDS;
        uint32_t* cWs = cWb + 16 * 132;
        int k0 = (gch & 3) * 32;
#pragma unroll
        for (int ks = 0; ks < 2; ks++) {
            int kpg = (k0 >> 1) + ks * 8;
            uint32_t ab0 = sAb[(r0    ) * 68 + kpg + t4];
            uint32_t ab1 = sAb[(r0 + 8) * 68 + kpg + t4];
            uint32_t ab2 = sAb[(r0    ) * 68 + kpg + t4 + 4];
            uint32_t ab3 = sAb[(r0 + 8) * 68 + kpg + t4 + 4];
            uint32_t as0 = sAs[(r0    ) * 68 + kpg + t4];
            uint32_t as1 = sAs[(r0 + 8) * 68 + kpg + t4];
            uint32_t as2 = sAs[(r0    ) * 68 + kpg + t4 + 4];
            uint32_t as3 = sAs[(r0 + 8) * 68 + kpg + t4 + 4];
            int kp0 = ks * 8;
            const uint4* rb0 = (const uint4*)&cWb[(kp0 + t4    ) * 132 + g * 16];
            const uint4* rb1 = (const uint4*)&cWb[(kp0 + t4 + 4) * 132 + g * 16];
            const uint4* rs0 = (const uint4*)&cWs[(kp0 + t4    ) * 132 + g * 16];
            const uint4* rs1 = (const uint4*)&cWs[(kp0 + t4 + 4) * 132 + g * 16];
#pragma unroll
            for (int nt4 = 0; nt4 < 4; nt4++) {
                uint4 b0 = rb0[nt4], b1 = rb1[nt4];
                uint4 s0 = rs0[nt4], s1 = rs1[nt4];
                uint32_t bb0[4] = {b0.x, b0.y, b0.z, b0.w};
                uint32_t bb1[4] = {b1.x, b1.y, b1.z, b1.w};
                uint32_t bs0[4] = {s0.x, s0.y, s0.z, s0.w};
                uint32_t bs1[4] = {s1.x, s1.y, s1.z, s1.w};
#pragma unroll
                for (int q = 0; q < 4; q++) {
                    int nt = nt4 * 4 + q;
                    mma_bf16(acc[nt], ab0, ab1, ab2, ab3, bb0[q], bb1[q]);
                    mma_bf16(acc[nt], as0, as1, as2, as3, bb0[q], bb1[q]);
                    mma_bf16(acc[nt], ab0, ab1, ab2, ab3, bs0[q], bs1[q]);
                }
            }
        }

        if ((gch & 3) == 3) {
            // epilogue for k-slice gch>>2 (regs + gmem only; no smem hazard)
            int k = blockIdx.y * KC + (gch >> 2);
            float plo = 0.f, phi = 0.f;
#pragma unroll
            for (int nt = 0; nt < 16; nt++) {
                int c = nt * 8 + 2 * t4;
                float2 b0 = __ldg((const float2*)(Brow0 + c));
                float2 b1 = __ldg((const float2*)(Brow1 + c));
                plo = fmaf(acc[nt][0], b0.x, plo);
                plo = fmaf(acc[nt][1], b0.y, plo);
                phi = fmaf(acc[nt][2], b1.x, phi);
                phi = fmaf(acc[nt][3], b1.y, phi);
            }
            plo += __shfl_xor_sync(0xffffffffu, plo, 1);
            plo += __shfl_xor_sync(0xffffffffu, plo, 2);
            phi += __shfl_xor_sync(0xffffffffu, phi, 1);
            phi += __shfl_xor_sync(0xffffffffu, phi, 2);
            if (t4 == 0) {
                if (pg0 < NPAIRS) feat[(size_t)pg0 * ZDIM + k] = plo;
                if (pg1 < NPAIRS) feat[(size_t)pg1 * ZDIM + k] = phi;
            }
        }
        __syncthreads();   // protect buf gch&1 before overwrite at gch+2
    }
}

// ------------------------------------------------------------------
// Stage 2: tiny MLP on feat -> predictions
// ------------------------------------------------------------------
__device__ __forceinline__ float elu1(float x) {
    return x > 0.f ? x : expm1f(x);
}

__global__ __launch_bounds__(256) void mlp_kernel(
    const float* __restrict__ feat, const float* __restrict__ bilb,
    const float* __restrict__ dw1, const float* __restrict__ db1,
    const float* __restrict__ dw2, const float* __restrict__ db2,
    float* __restrict__ pred)
{
    int p = blockIdx.x * blockDim.x + threadIdx.x;
    if (p >= NPAIRS) return;

    float f[ZDIM];
#pragma unroll
    for (int k = 0; k < ZDIM; k++)
        f[k] = elu1(feat[(size_t)p * ZDIM + k] + __ldg(&bilb[k]));

    float o = __ldg(&db2[0]);
#pragma unroll
    for (int kk = 0; kk < ZDIM; kk++) {
        float s = __ldg(&db1[kk]);
#pragma unroll
        for (int j = 0; j < ZDIM; j++)
            s = fmaf(f[j], __ldg(&dw1[j * ZDIM + kk]), s);
        o = fmaf(elu1(s), __ldg(&dw2[kk]), o);
    }
    pred[p] = o;
}

// ------------------------------------------------------------------
extern "C" void kernel_launch(void* const* d_in, const int* in_sizes, int n_in,
                              void* d_out, int out_size)
{
    const float* features = (const float*)d_in[0];
    const int*   adj_row  = (const int*)  d_in[1];
    const int*   adj_col  = (const int*)  d_in[2];
    const float* adj_val  = (const float*)d_in[3];
    const int*   idx      = (const int*)  d_in[4];
    const float* W0   = (const float*)d_in[5];
    const float* b0   = (const float*)d_in[6];
    const float* W1   = (const float*)d_in[7];
    const float* b1   = (const float*)d_in[8];
    const float* W2   = (const float*)d_in[9];
    const float* b2   = (const float*)d_in[10];
    const float* bilw = (const float*)d_in[11];
    const float* bilb = (const float*)d_in[12];
    const float* dw1  = (const float*)d_in[13];
    const float* db1  = (const float*)d_in[14];
    const float* dw2  = (const float*)d_in[15];
    const float* db2  = (const float*)d_in[16];

    float* out    = (float*)d_out;
    float* pred   = out;            // [NPAIRS]
    float* latent = out + NPAIRS;   // [N_NODES * NHID]

    float* h;  cudaGetSymbolAddress((void**)&h,  g_buf_h);
    float* x0; cudaGetSymbolAddress((void**)&x0, g_buf_x0);
    float* x1; cudaGetSymbolAddress((void**)&x1, g_buf_x1);
    float* ft; cudaGetSymbolAddress((void**)&ft, g_feat);
    uint32_t* wb;  cudaGetSymbolAddress((void**)&wb,  g_Wb);
    uint32_t* ws;  cudaGetSymbolAddress((void**)&ws,  g_Ws);
    uint32_t* bwb; cudaGetSymbolAddress((void**)&bwb, g_bilWb);
    uint32_t* bws; cudaGetSymbolAddress((void**)&bws, g_bilWs);

    static int smem_set = 0;
    if (!smem_set) {
        cudaFuncSetAttribute(bilinear_kernel,
                             cudaFuncAttributeMaxDynamicSharedMemorySize,
                             BIL_SMEM_BYTES);
        smem_set = 1;
    }

    presplit_kernel<<<(294912 + 255) / 256, 256>>>(W0, W1, W2, bilw);
    rowptr_kernel<<<(N_NODES + 1 + 255) / 256, 256>>>(adj_row);

    const int gemm_grid = (N_NODES + 127) / 128;
    const int spmm_grid = (N_NODES * 32 + 255) / 256;

    gemm_bf16_n128<<<gemm_grid, 256>>>(features, wb, ws, h, N_NODES, NFEAT);
    spmm_kernel<<<spmm_grid, 256>>>(h, adj_col, adj_val, b0, nullptr, x0);

    gemm_bf16_n128<<<gemm_grid, 256>>>(x0, wb + 128 * 128, ws + 128 * 128, h, N_NODES, NHID);
    spmm_kernel<<<spmm_grid, 256>>>(h, adj_col, adj_val, b1, x0, x1);

    gemm_bf16_n128<<<gemm_grid, 256>>>(x1, wb + 192 * 128, ws + 192 * 128, h, N_NODES, NHID);
    spmm_kernel<<<spmm_grid, 256>>>(h, adj_col, adj_val, b2, x1, latent);

    dim3 bil_grid((NPAIRS + 127) / 128, ZDIM / KC);
    bilinear_kernel<<<bil_grid, 256, BIL_SMEM_BYTES>>>(latent, idx, bwb, bws, ft);
    mlp_kernel<<<(NPAIRS + 255) / 256, 256>>>(ft, bilb, dw1, db1, dw2, db2, pred);
}

// round 13
// speedup vs baseline: 1.1911x; 1.0203x over previous
#include <cuda_runtime.h>
#include <cstdint>

#define N_NODES 50000
#define N_EDGES 800000
#define NFEAT   256
#define NHID    128
#define ZDIM    32
#define NPAIRS  10000

// ---- scratch (static device globals; no allocation at runtime) ----
__device__ float    g_buf_h [(size_t)N_NODES * NHID];
__device__ float    g_buf_x0[(size_t)N_NODES * NHID];
__device__ float    g_buf_x1[(size_t)N_NODES * NHID];
__device__ int      g_rowptr[N_NODES + 1];
__device__ float    g_feat[(size_t)NPAIRS * ZDIM];
// pre-split weight planes (bf16x2 pairs along k), FRAGMENT-REMAPPED rows:
// within each 128-word row, word position = (e&7)*16 + (e>>3).
__device__ uint32_t g_Wb[256 * 128], g_Ws[256 * 128];
__device__ uint32_t g_bilWb[(size_t)ZDIM * 64 * 128];
__device__ uint32_t g_bilWs[(size_t)ZDIM * 64 * 128];

// ------------------------------------------------------------------
// bf16 split helpers
// ------------------------------------------------------------------
__device__ __forceinline__ uint32_t pack2bf(float lo, float hi) {
    uint32_t r;
    asm("cvt.rn.bf16x2.f32 %0, %1, %2;" : "=r"(r) : "f"(hi), "f"(lo));
    return r;
}
__device__ __forceinline__ float2 unpack_bf(uint32_t p) {
    return make_float2(__uint_as_float(p << 16),
                       __uint_as_float(p & 0xffff0000u));
}

__device__ __forceinline__ void mma_bf16(
    float* d, uint32_t a0, uint32_t a1, uint32_t a2, uint32_t a3,
    uint32_t b0, uint32_t b1)
{
    asm volatile(
        "mma.sync.aligned.m16n8k16.row.col.f32.bf16.bf16.f32 "
        "{%0,%1,%2,%3}, {%4,%5,%6,%7}, {%8,%9}, {%0,%1,%2,%3};\n"
        : "+f"(d[0]), "+f"(d[1]), "+f"(d[2]), "+f"(d[3])
        : "r"(a0), "r"(a1), "r"(a2), "r"(a3), "r"(b0), "r"(b1));
}

// cp.async helpers
__device__ __forceinline__ void cp16(uint32_t smem_addr, const void* gptr) {
    asm volatile("cp.async.cg.shared.global [%0], [%1], 16;"
                 :: "r"(smem_addr), "l"(gptr));
}
__device__ __forceinline__ void cp_commit() {
    asm volatile("cp.async.commit_group;");
}

// ------------------------------------------------------------------
// One-shot weight pre-split + fragment remap.
// ------------------------------------------------------------------
__global__ void presplit_kernel(const float* __restrict__ W0,
                                const float* __restrict__ W1,
                                const float* __restrict__ W2,
                                const float* __restrict__ bilw)
{
    int i = blockIdx.x * blockDim.x + threadIdx.x;
    const float* src; uint32_t* dstB; uint32_t* dstS; int j;
    if (i < 16384)        { src = W0;   dstB = g_Wb;              dstS = g_Ws;              j = i; }
    else if (i < 24576)   { src = W1;   dstB = g_Wb + 128 * 128;  dstS = g_Ws + 128 * 128;  j = i - 16384; }
    else if (i < 32768)   { src = W2;   dstB = g_Wb + 192 * 128;  dstS = g_Ws + 192 * 128;  j = i - 24576; }
    else if (i < 294912)  { src = bilw; dstB = g_bilWb;           dstS = g_bilWs;           j = i - 32768; }
    else return;
    int kp = j >> 7, c = j & 127;
    float lo = src[(size_t)kp * 256 + c];
    float hi = src[(size_t)kp * 256 + 128 + c];
    uint32_t pb = pack2bf(lo, hi);
    float2 f = unpack_bf(pb);
    int jr = kp * 128 + (c & 7) * 16 + (c >> 3);   // fragment remap
    dstB[jr] = pb;
    dstS[jr] = pack2bf(lo - f.x, hi - f.y);
}

// ------------------------------------------------------------------
__global__ void rowptr_kernel(const int* __restrict__ row) {
    int r = blockIdx.x * blockDim.x + threadIdx.x;
    if (r > N_NODES) return;
    int lo = 0, hi = N_EDGES;
    while (lo < hi) {
        int mid = (lo + hi) >> 1;
        if (row[mid] < r) lo = mid + 1; else hi = mid;
    }
    g_rowptr[r] = lo;
}

// ------------------------------------------------------------------
// Encoder GEMM (unchanged from R10/R11, known-good)
// ------------------------------------------------------------------
__global__ __launch_bounds__(256, 2) void gemm_bf16_n128(
    const float* __restrict__ A,
    const uint32_t* __restrict__ Wb, const uint32_t* __restrict__ Ws,
    float* __restrict__ C, int M, int K)
{
    __shared__ uint32_t sAb[128][17], sAs[128][17];
    __shared__ uint32_t sBb[16 * 132], sBs[16 * 132];

    int tid  = threadIdx.x;
    int lane = tid & 31, warp = tid >> 5;
    int g = lane >> 2, t4 = lane & 3;
    int r0 = warp * 16 + g;
    int row0 = blockIdx.x * 128;

    float acc[16][4];
#pragma unroll
    for (int nt = 0; nt < 16; nt++)
#pragma unroll
        for (int j = 0; j < 4; j++) acc[nt][j] = 0.f;

    for (int k0 = 0; k0 < K; k0 += 32) {
        __syncthreads();
#pragma unroll
        for (int u = 0; u < 4; u++) {
            int i = tid + u * 256;
            int r = i >> 3, q = i & 7;
            int gr = row0 + r;
            float4 v = (gr < M)
                ? __ldg((const float4*)(A + (size_t)gr * K + k0 + 4 * q))
                : make_float4(0.f, 0.f, 0.f, 0.f);
            uint32_t p0 = pack2bf(v.x, v.y);
            uint32_t p1 = pack2bf(v.z, v.w);
            float2 f0 = unpack_bf(p0), f1 = unpack_bf(p1);
            sAb[r][2 * q]     = p0;
            sAb[r][2 * q + 1] = p1;
            sAs[r][2 * q]     = pack2bf(v.x - f0.x, v.y - f0.y);
            sAs[r][2 * q + 1] = pack2bf(v.z - f1.x, v.w - f1.y);
        }
        {
            const uint32_t* srcB = Wb + (size_t)(k0 >> 1) * 128;
            const uint32_t* srcS = Ws + (size_t)(k0 >> 1) * 128;
#pragma unroll
            for (int u = 0; u < 2; u++) {
                int i = tid + u * 256;
                int kp = i >> 5, c4 = (i & 31) * 4;
                uint4 vb = __ldg((const uint4*)(srcB + kp * 128 + c4));
                uint4 vs = __ldg((const uint4*)(srcS + kp * 128 + c4));
                *(uint4*)&sBb[kp * 132 + c4] = vb;
                *(uint4*)&sBs[kp * 132 + c4] = vs;
            }
        }
        __syncthreads();

#pragma unroll
        for (int ks = 0; ks < 2; ks++) {
            int kp0 = ks * 8;
            uint32_t ab0 = sAb[r0    ][kp0 + t4];
            uint32_t ab1 = sAb[r0 + 8][kp0 + t4];
            uint32_t ab2 = sAb[r0    ][kp0 + t4 + 4];
            uint32_t ab3 = sAb[r0 + 8][kp0 + t4 + 4];
            uint32_t as0 = sAs[r0    ][kp0 + t4];
            uint32_t as1 = sAs[r0 + 8][kp0 + t4];
            uint32_t as2 = sAs[r0    ][kp0 + t4 + 4];
            uint32_t as3 = sAs[r0 + 8][kp0 + t4 + 4];
            const uint4* rb0 = (const uint4*)&sBb[(kp0 + t4    ) * 132 + g * 16];
            const uint4* rb1 = (const uint4*)&sBb[(kp0 + t4 + 4) * 132 + g * 16];
            const uint4* rs0 = (const uint4*)&sBs[(kp0 + t4    ) * 132 + g * 16];
            const uint4* rs1 = (const uint4*)&sBs[(kp0 + t4 + 4) * 132 + g * 16];
#pragma unroll
            for (int nt4 = 0; nt4 < 4; nt4++) {
                uint4 b0 = rb0[nt4], b1 = rb1[nt4];
                uint4 s0 = rs0[nt4], s1 = rs1[nt4];
                uint32_t bb0[4] = {b0.x, b0.y, b0.z, b0.w};
                uint32_t bb1[4] = {b1.x, b1.y, b1.z, b1.w};
                uint32_t bs0[4] = {s0.x, s0.y, s0.z, s0.w};
                uint32_t bs1[4] = {s1.x, s1.y, s1.z, s1.w};
#pragma unroll
                for (int q = 0; q < 4; q++) {
                    int nt = nt4 * 4 + q;
                    mma_bf16(acc[nt], ab0, ab1, ab2, ab3, bb0[q], bb1[q]);
                    mma_bf16(acc[nt], as0, as1, as2, as3, bb0[q], bb1[q]);
                    mma_bf16(acc[nt], ab0, ab1, ab2, ab3, bs0[q], bs1[q]);
                }
            }
        }
    }

#pragma unroll
    for (int nt = 0; nt < 16; nt++) {
        int c = nt * 8 + 2 * t4;
        int gr0 = row0 + r0, gr1 = gr0 + 8;
        if (gr0 < M)
            *(float2*)(C + (size_t)gr0 * 128 + c) = make_float2(acc[nt][0], acc[nt][1]);
        if (gr1 < M)
            *(float2*)(C + (size_t)gr1 * 128 + c) = make_float2(acc[nt][2], acc[nt][3]);
    }
}

// ------------------------------------------------------------------
// SpMM: one warp per TWO destination rows (dual gather streams)
// ------------------------------------------------------------------
__global__ __launch_bounds__(256) void spmm_kernel(
    const float* __restrict__ H, const int* __restrict__ col,
    const float* __restrict__ val, const float* __restrict__ bias,
    const float* __restrict__ res, float* __restrict__ out)
{
    int w = (blockIdx.x * blockDim.x + threadIdx.x) >> 5;   // warp id
    int r0 = 2 * w, r1 = 2 * w + 1;
    if (r0 >= N_NODES) return;
    int lane = threadIdx.x & 31;

    const float4* Hv = (const float4*)H;
    float4 acc0 = make_float4(0.f, 0.f, 0.f, 0.f);
    float4 acc1 = make_float4(0.f, 0.f, 0.f, 0.f);
    int i0 = g_rowptr[r0], e0 = g_rowptr[r0 + 1];
    int i1 = e0, e1 = (r1 < N_NODES) ? g_rowptr[r1 + 1] : e0;  // rows contiguous

    // interleaved dual-stream main loop (2 edges per row per iter)
    while (i0 + 1 < e0 && i1 + 1 < e1) {
        int   ca0 = __ldg(&col[i0]),     ca1 = __ldg(&col[i0 + 1]);
        int   cb0 = __ldg(&col[i1]),     cb1 = __ldg(&col[i1 + 1]);
        float va0 = __ldg(&val[i0]),     va1 = __ldg(&val[i0 + 1]);
        float vb0 = __ldg(&val[i1]),     vb1 = __ldg(&val[i1 + 1]);
        float4 ha0 = __ldg(&Hv[(size_t)ca0 * 32 + lane]);
        float4 hb0 = __ldg(&Hv[(size_t)cb0 * 32 + lane]);
        float4 ha1 = __ldg(&Hv[(size_t)ca1 * 32 + lane]);
        float4 hb1 = __ldg(&Hv[(size_t)cb1 * 32 + lane]);
        acc0.x = fmaf(va0, ha0.x, acc0.x); acc0.y = fmaf(va0, ha0.y, acc0.y);
        acc0.z = fmaf(va0, ha0.z, acc0.z); acc0.w = fmaf(va0, ha0.w, acc0.w);
        acc1.x = fmaf(vb0, hb0.x, acc1.x); acc1.y = fmaf(vb0, hb0.y, acc1.y);
        acc1.z = fmaf(vb0, hb0.z, acc1.z); acc1.w = fmaf(vb0, hb0.w, acc1.w);
        acc0.x = fmaf(va1, ha1.x, acc0.x); acc0.y = fmaf(va1, ha1.y, acc0.y);
        acc0.z = fmaf(va1, ha1.z, acc0.z); acc0.w = fmaf(va1, ha1.w, acc0.w);
        acc1.x = fmaf(vb1, hb1.x, acc1.x); acc1.y = fmaf(vb1, hb1.y, acc1.y);
        acc1.z = fmaf(vb1, hb1.z, acc1.z); acc1.w = fmaf(vb1, hb1.w, acc1.w);
        i0 += 2; i1 += 2;
    }
    // tails
    for (; i0 + 1 < e0; i0 += 2) {
        int   c0 = __ldg(&col[i0]), c1 = __ldg(&col[i0 + 1]);
        float v0 = __ldg(&val[i0]), v1 = __ldg(&val[i0 + 1]);
        float4 h0 = __ldg(&Hv[(size_t)c0 * 32 + lane]);
        float4 h1 = __ldg(&Hv[(size_t)c1 * 32 + lane]);
        acc0.x = fmaf(v0, h0.x, acc0.x); acc0.y = fmaf(v0, h0.y, acc0.y);
        acc0.z = fmaf(v0, h0.z, acc0.z); acc0.w = fmaf(v0, h0.w, acc0.w);
        acc0.x = fmaf(v1, h1.x, acc0.x); acc0.y = fmaf(v1, h1.y, acc0.y);
        acc0.z = fmaf(v1, h1.z, acc0.z); acc0.w = fmaf(v1, h1.w, acc0.w);
    }
    if (i0 < e0) {
        int   c0 = __ldg(&col[i0]);
        float v0 = __ldg(&val[i0]);
        float4 h0 = __ldg(&Hv[(size_t)c0 * 32 + lane]);
        acc0.x = fmaf(v0, h0.x, acc0.x); acc0.y = fmaf(v0, h0.y, acc0.y);
        acc0.z = fmaf(v0, h0.z, acc0.z); acc0.w = fmaf(v0, h0.w, acc0.w);
    }
    for (; i1 + 1 < e1; i1 += 2) {
        int   c0 = __ldg(&col[i1]), c1 = __ldg(&col[i1 + 1]);
        float v0 = __ldg(&val[i1]), v1 = __ldg(&val[i1 + 1]);
        float4 h0 = __ldg(&Hv[(size_t)c0 * 32 + lane]);
        float4 h1 = __ldg(&Hv[(size_t)c1 * 32 + lane]);
        acc1.x = fmaf(v0, h0.x, acc1.x); acc1.y = fmaf(v0, h0.y, acc1.y);
        acc1.z = fmaf(v0, h0.z, acc1.z); acc1.w = fmaf(v0, h0.w, acc1.w);
        acc1.x = fmaf(v1, h1.x, acc1.x); acc1.y = fmaf(v1, h1.y, acc1.y);
        acc1.z = fmaf(v1, h1.z, acc1.z); acc1.w = fmaf(v1, h1.w, acc1.w);
    }
    if (i1 < e1) {
        int   c0 = __ldg(&col[i1]);
        float v0 = __ldg(&val[i1]);
        float4 h0 = __ldg(&Hv[(size_t)c0 * 32 + lane]);
        acc1.x = fmaf(v0, h0.x, acc1.x); acc1.y = fmaf(v0, h0.y, acc1.y);
        acc1.z = fmaf(v0, h0.z, acc1.z); acc1.w = fmaf(v0, h0.w, acc1.w);
    }

    float4 bb = __ldg(&((const float4*)bias)[lane]);
    // row 0
    {
        float4 o;
        o.x = fmaxf(acc0.x + bb.x, 0.f);
        o.y = fmaxf(acc0.y + bb.y, 0.f);
        o.z = fmaxf(acc0.z + bb.z, 0.f);
        o.w = fmaxf(acc0.w + bb.w, 0.f);
        size_t vb4 = (size_t)r0 * 32 + lane;
        if (res) {
            float4 rv = __ldg(&((const float4*)res)[vb4]);
            o.x += rv.x; o.y += rv.y; o.z += rv.z; o.w += rv.w;
        }
        ((float4*)out)[vb4] = o;
    }
    // row 1
    if (r1 < N_NODES) {
        float4 o;
        o.x = fmaxf(acc1.x + bb.x, 0.f);
        o.y = fmaxf(acc1.y + bb.y, 0.f);
        o.z = fmaxf(acc1.z + bb.z, 0.f);
        o.w = fmaxf(acc1.w + bb.w, 0.f);
        size_t vb4 = (size_t)r1 * 32 + lane;
        if (res) {
            float4 rv = __ldg(&((const float4*)res)[vb4]);
            o.x += rv.x; o.y += rv.y; o.z += rv.z; o.w += rv.w;
        }
        ((float4*)out)[vb4] = o;
    }
}

// ------------------------------------------------------------------
// Bilinear stage 1: split-bf16 3-MMA, cp.async double-buffered W.
// KC=2 k-slices per CTA (grid.y=16) for better wave balance.
// ------------------------------------------------------------------
#define KC 2
#define WBUF_WORDS (2 * 16 * 132)
#define BIL_SMEM_WORDS (2 * 128 * 68 + 2 * WBUF_WORDS)
#define BIL_SMEM_BYTES (BIL_SMEM_WORDS * 4)

__global__ __launch_bounds__(256, 2) void bilinear_kernel(
    const float* __restrict__ latent, const int* __restrict__ idx,
    const uint32_t* __restrict__ bilWb, const uint32_t* __restrict__ bilWs,
    float* __restrict__ feat)
{
    extern __shared__ uint32_t smem[];
    uint32_t* sAb = smem;                      // [128][68] big plane
    uint32_t* sAs = sAb + 128 * 68;            // [128][68] small plane
    uint32_t* sWbase = sAs + 128 * 68;         // 2 x {sWb[16*132], sWs[16*132]}

    int tid  = threadIdx.x;
    int lane = tid & 31, warp = tid >> 5;
    int p0 = blockIdx.x * 128;
    int g = lane >> 2, t4 = lane & 3;
    int r0 = warp * 16 + g;

    int pg0 = p0 + r0, pg1 = p0 + r0 + 8;
    int pc0 = pg0 < NPAIRS ? pg0 : NPAIRS - 1;
    int pc1 = pg1 < NPAIRS ? pg1 : NPAIRS - 1;
    const float* Brow0 = latent + (size_t)__ldg(&idx[NPAIRS + pc0]) * 128;
    const float* Brow1 = latent + (size_t)__ldg(&idx[NPAIRS + pc1]) * 128;

    int cp_kp[2], cp_c4[2];
#pragma unroll
    for (int u = 0; u < 2; u++) {
        int i = tid + u * 256;
        cp_kp[u] = i >> 5; cp_c4[u] = (i & 31) * 4;
    }

    auto issue_chunk = [&](int gch, int buf) {
        int k = blockIdx.y * KC + (gch >> 2);
        int kpb = (gch & 3) * 16;
        const uint32_t* srcB = bilWb + ((size_t)k * 64 + kpb) * 128;
        const uint32_t* srcS = bilWs + ((size_t)k * 64 + kpb) * 128;
        uint32_t* dWb = sWbase + buf * WBUF_WORDS;
        uint32_t* dWs = dWb + 16 * 132;
        uint32_t ab = (uint32_t)__cvta_generic_to_shared(dWb);
        uint32_t as = (uint32_t)__cvta_generic_to_shared(dWs);
#pragma unroll
        for (int u = 0; u < 2; u++) {
            int off = cp_kp[u] * 132 + cp_c4[u];
            int src = cp_kp[u] * 128 + cp_c4[u];
            cp16(ab + off * 4, srcB + src);
            cp16(as + off * 4, srcS + src);
        }
        cp_commit();
    };

    for (int i = tid; i < 128 * 32; i += 256) {
        int p = i >> 5, l32 = i & 31;
        int c8 = l32 * 4, kp = l32 * 2;
        int pg = p0 + p; if (pg >= NPAIRS) pg = NPAIRS - 1;
        int na = __ldg(&idx[pg]);
        float4 v = __ldg((const float4*)(latent + (size_t)na * 128 + c8));
        uint32_t b0 = pack2bf(v.x, v.y);
        uint32_t b1 = pack2bf(v.z, v.w);
        float2 f0 = unpack_bf(b0), f1 = unpack_bf(b1);
        sAb[p * 68 + kp]     = b0;
        sAb[p * 68 + kp + 1] = b1;
        sAs[p * 68 + kp]     = pack2bf(v.x - f0.x, v.y - f0.y);
        sAs[p * 68 + kp + 1] = pack2bf(v.z - f1.x, v.w - f1.y);
    }

    issue_chunk(0, 0);   // prologue prefetch

    const int NCH = KC * 4;
    float acc[16][4];
    for (int gch = 0; gch < NCH; gch++) {
        if ((gch & 3) == 0) {
#pragma unroll
            for (int nt = 0; nt < 16; nt++)
#pragma unroll
                for (int j = 0; j < 4; j++) acc[nt][j] = 0.f;
        }
        if (gch + 1 < NCH) {
            issue_chunk(gch + 1, (gch + 1) & 1);
            asm volatile("cp.async.wait_group 1;");
        } else {
            asm volatile("cp.async.wait_group 0;");
        }
        __syncthreads();

        uint32_t* cWb = sWbase + (gch & 1) * WBUF_WORDS;
        uint32_t* cWs = cWb + 16 * 132;
        int k0 = (gch & 3) * 32;
#pragma unroll
        for (int ks = 0; ks < 2; ks++) {
            int kpg = (k0 >> 1) + ks * 8;
            uint32_t ab0 = sAb[(r0    ) * 68 + kpg + t4];
            uint32_t ab1 = sAb[(r0 + 8) * 68 + kpg + t4];
            uint32_t ab2 = sAb[(r0    ) * 68 + kpg + t4 + 4];
            uint32_t ab3 = sAb[(r0 + 8) * 68 + kpg + t4 + 4];
            uint32_t as0 = sAs[(r0    ) * 68 + kpg + t4];
            uint32_t as1 = sAs[(r0 + 8) * 68 + kpg + t4];
            uint32_t as2 = sAs[(r0    ) * 68 + kpg + t4 + 4];
            uint32_t as3 = sAs[(r0 + 8) * 68 + kpg + t4 + 4];
            int kp0 = ks * 8;
            const uint4* rb0 = (const uint4*)&cWb[(kp0 + t4    ) * 132 + g * 16];
            const uint4* rb1 = (const uint4*)&cWb[(kp0 + t4 + 4) * 132 + g * 16];
            const uint4* rs0 = (const uint4*)&cWs[(kp0 + t4    ) * 132 + g * 16];
            const uint4* rs1 = (const uint4*)&cWs[(kp0 + t4 + 4) * 132 + g * 16];
#pragma unroll
            for (int nt4 = 0; nt4 < 4; nt4++) {
                uint4 b0 = rb0[nt4], b1 = rb1[nt4];
                uint4 s0 = rs0[nt4], s1 = rs1[nt4];
                uint32_t bb0[4] = {b0.x, b0.y, b0.z, b0.w};
                uint32_t bb1[4] = {b1.x, b1.y, b1.z, b1.w};
                uint32_t bs0[4] = {s0.x, s0.y, s0.z, s0.w};
                uint32_t bs1[4] = {s1.x, s1.y, s1.z, s1.w};
#pragma unroll
                for (int q = 0; q < 4; q++) {
                    int nt = nt4 * 4 + q;
                    mma_bf16(acc[nt], ab0, ab1, ab2, ab3, bb0[q], bb1[q]);
                    mma_bf16(acc[nt], as0, as1, as2, as3, bb0[q], bb1[q]);
                    mma_bf16(acc[nt], ab0, ab1, ab2, ab3, bs0[q], bs1[q]);
                }
            }
        }

        if ((gch & 3) == 3) {
            int k = blockIdx.y * KC + (gch >> 2);
            float plo = 0.f, phi = 0.f;
#pragma unroll
            for (int nt = 0; nt < 16; nt++) {
                int c = nt * 8 + 2 * t4;
                float2 b0 = __ldg((const float2*)(Brow0 + c));
                float2 b1 = __ldg((const float2*)(Brow1 + c));
                plo = fmaf(acc[nt][0], b0.x, plo);
                plo = fmaf(acc[nt][1], b0.y, plo);
                phi = fmaf(acc[nt][2], b1.x, phi);
                phi = fmaf(acc[nt][3], b1.y, phi);
            }
            plo += __shfl_xor_sync(0xffffffffu, plo, 1);
            plo += __shfl_xor_sync(0xffffffffu, plo, 2);
            phi += __shfl_xor_sync(0xffffffffu, phi, 1);
            phi += __shfl_xor_sync(0xffffffffu, phi, 2);
            if (t4 == 0) {
                if (pg0 < NPAIRS) feat[(size_t)pg0 * ZDIM + k] = plo;
                if (pg1 < NPAIRS) feat[(size_t)pg1 * ZDIM + k] = phi;
            }
        }
        __syncthreads();
    }
}

// ------------------------------------------------------------------
// Stage 2: tiny MLP on feat -> predictions
// ------------------------------------------------------------------
__device__ __forceinline__ float elu1(float x) {
    return x > 0.f ? x : expm1f(x);
}

__global__ __launch_bounds__(256) void mlp_kernel(
    const float* __restrict__ feat, const float* __restrict__ bilb,
    const float* __restrict__ dw1, const float* __restrict__ db1,
    const float* __restrict__ dw2, const float* __restrict__ db2,
    float* __restrict__ pred)
{
    int p = blockIdx.x * blockDim.x + threadIdx.x;
    if (p >= NPAIRS) return;

    float f[ZDIM];
#pragma unroll
    for (int k = 0; k < ZDIM; k++)
        f[k] = elu1(feat[(size_t)p * ZDIM + k] + __ldg(&bilb[k]));

    float o = __ldg(&db2[0]);
#pragma unroll
    for (int kk = 0; kk < ZDIM; kk++) {
        float s = __ldg(&db1[kk]);
#pragma unroll
        for (int j = 0; j < ZDIM; j++)
            s = fmaf(f[j], __ldg(&dw1[j * ZDIM + kk]), s);
        o = fmaf(elu1(s), __ldg(&dw2[kk]), o);
    }
    pred[p] = o;
}

// ------------------------------------------------------------------
extern "C" void kernel_launch(void* const* d_in, const int* in_sizes, int n_in,
                              void* d_out, int out_size)
{
    const float* features = (const float*)d_in[0];
    const int*   adj_row  = (const int*)  d_in[1];
    const int*   adj_col  = (const int*)  d_in[2];
    const float* adj_val  = (const float*)d_in[3];
    const int*   idx      = (const int*)  d_in[4];
    const float* W0   = (const float*)d_in[5];
    const float* b0   = (const float*)d_in[6];
    const float* W1   = (const float*)d_in[7];
    const float* b1   = (const float*)d_in[8];
    const float* W2   = (const float*)d_in[9];
    const float* b2   = (const float*)d_in[10];
    const float* bilw = (const float*)d_in[11];
    const float* bilb = (const float*)d_in[12];
    const float* dw1  = (const float*)d_in[13];
    const float* db1  = (const float*)d_in[14];
    const float* dw2  = (const float*)d_in[15];
    const float* db2  = (const float*)d_in[16];

    float* out    = (float*)d_out;
    float* pred   = out;            // [NPAIRS]
    float* latent = out + NPAIRS;   // [N_NODES * NHID]

    float* h;  cudaGetSymbolAddress((void**)&h,  g_buf_h);
    float* x0; cudaGetSymbolAddress((void**)&x0, g_buf_x0);
    float* x1; cudaGetSymbolAddress((void**)&x1, g_buf_x1);
    float* ft; cudaGetSymbolAddress((void**)&ft, g_feat);
    uint32_t* wb;  cudaGetSymbolAddress((void**)&wb,  g_Wb);
    uint32_t* ws;  cudaGetSymbolAddress((void**)&ws,  g_Ws);
    uint32_t* bwb; cudaGetSymbolAddress((void**)&bwb, g_bilWb);
    uint32_t* bws; cudaGetSymbolAddress((void**)&bws, g_bilWs);

    static int smem_set = 0;
    if (!smem_set) {
        cudaFuncSetAttribute(bilinear_kernel,
                             cudaFuncAttributeMaxDynamicSharedMemorySize,
                             BIL_SMEM_BYTES);
        smem_set = 1;
    }

    presplit_kernel<<<(294912 + 255) / 256, 256>>>(W0, W1, W2, bilw);
    rowptr_kernel<<<(N_NODES + 1 + 255) / 256, 256>>>(adj_row);

    const int gemm_grid = (N_NODES + 127) / 128;
    const int spmm_grid = ((N_NODES + 1) / 2 * 32 + 255) / 256;

    gemm_bf16_n128<<<gemm_grid, 256>>>(features, wb, ws, h, N_NODES, NFEAT);
    spmm_kernel<<<spmm_grid, 256>>>(h, adj_col, adj_val, b0, nullptr, x0);

    gemm_bf16_n128<<<gemm_grid, 256>>>(x0, wb + 128 * 128, ws + 128 * 128, h, N_NODES, NHID);
    spmm_kernel<<<spmm_grid, 256>>>(h, adj_col, adj_val, b1, x0, x1);

    gemm_bf16_n128<<<gemm_grid, 256>>>(x1, wb + 192 * 128, ws + 192 * 128, h, N_NODES, NHID);
    spmm_kernel<<<spmm_grid, 256>>>(h, adj_col, adj_val, b2, x1, latent);

    dim3 bil_grid((NPAIRS + 127) / 128, ZDIM / KC);
    bilinear_kernel<<<bil_grid, 256, BIL_SMEM_BYTES>>>(latent, idx, bwb, bws, ft);
    mlp_kernel<<<(NPAIRS + 255) / 256, 256>>>(ft, bilb, dw1, db1, dw2, db2, pred);
}

// round 14
// speedup vs baseline: 1.2046x; 1.0113x over previous
#include <cuda_runtime.h>
#include <cstdint>

#define N_NODES 50000
#define N_EDGES 800000
#define NFEAT   256
#define NHID    128
#define ZDIM    32
#define NPAIRS  10000

// ---- scratch (static device globals; no allocation at runtime) ----
__device__ float    g_buf_h [(size_t)N_NODES * NHID];
__device__ float    g_buf_x0[(size_t)N_NODES * NHID];
__device__ float    g_buf_x1[(size_t)N_NODES * NHID];
__device__ int      g_rowptr[N_NODES + 1];
__device__ float    g_feat[(size_t)NPAIRS * ZDIM];
// pre-split weight planes (bf16x2 pairs along k), FRAGMENT-REMAPPED rows:
// within each 128-word row, word position = (e&7)*16 + (e>>3).
__device__ uint32_t g_Wb[256 * 128], g_Ws[256 * 128];
__device__ uint32_t g_bilWb[(size_t)ZDIM * 64 * 128];
__device__ uint32_t g_bilWs[(size_t)ZDIM * 64 * 128];

// ------------------------------------------------------------------
// bf16 split helpers
// ------------------------------------------------------------------
__device__ __forceinline__ uint32_t pack2bf(float lo, float hi) {
    uint32_t r;
    asm("cvt.rn.bf16x2.f32 %0, %1, %2;" : "=r"(r) : "f"(hi), "f"(lo));
    return r;
}
__device__ __forceinline__ float2 unpack_bf(uint32_t p) {
    return make_float2(__uint_as_float(p << 16),
                       __uint_as_float(p & 0xffff0000u));
}

__device__ __forceinline__ void mma_bf16(
    float* d, uint32_t a0, uint32_t a1, uint32_t a2, uint32_t a3,
    uint32_t b0, uint32_t b1)
{
    asm volatile(
        "mma.sync.aligned.m16n8k16.row.col.f32.bf16.bf16.f32 "
        "{%0,%1,%2,%3}, {%4,%5,%6,%7}, {%8,%9}, {%0,%1,%2,%3};\n"
        : "+f"(d[0]), "+f"(d[1]), "+f"(d[2]), "+f"(d[3])
        : "r"(a0), "r"(a1), "r"(a2), "r"(a3), "r"(b0), "r"(b1));
}

// cp.async helpers
__device__ __forceinline__ void cp16(uint32_t smem_addr, const void* gptr) {
    asm volatile("cp.async.cg.shared.global [%0], [%1], 16;"
                 :: "r"(smem_addr), "l"(gptr));
}
__device__ __forceinline__ void cp_commit() {
    asm volatile("cp.async.commit_group;");
}

// ------------------------------------------------------------------
// Fused prep kernel: weight pre-split + fragment remap (blocks < 1152)
// and rowptr binary search (blocks >= 1152).
// ------------------------------------------------------------------
#define PRESPLIT_ITEMS 294912
#define PRESPLIT_BLOCKS ((PRESPLIT_ITEMS + 255) / 256)          // 1152
#define ROWPTR_BLOCKS   ((N_NODES + 1 + 255) / 256)             // 196
#define PREP_BLOCKS     (PRESPLIT_BLOCKS + ROWPTR_BLOCKS)

__global__ void prep_kernel(const float* __restrict__ W0,
                            const float* __restrict__ W1,
                            const float* __restrict__ W2,
                            const float* __restrict__ bilw,
                            const int* __restrict__ row)
{
    if (blockIdx.x >= PRESPLIT_BLOCKS) {
        int r = (blockIdx.x - PRESPLIT_BLOCKS) * blockDim.x + threadIdx.x;
        if (r > N_NODES) return;
        int lo = 0, hi = N_EDGES;
        while (lo < hi) {
            int mid = (lo + hi) >> 1;
            if (row[mid] < r) lo = mid + 1; else hi = mid;
        }
        g_rowptr[r] = lo;
        return;
    }
    int i = blockIdx.x * blockDim.x + threadIdx.x;
    const float* src; uint32_t* dstB; uint32_t* dstS; int j;
    if (i < 16384)        { src = W0;   dstB = g_Wb;              dstS = g_Ws;              j = i; }
    else if (i < 24576)   { src = W1;   dstB = g_Wb + 128 * 128;  dstS = g_Ws + 128 * 128;  j = i - 16384; }
    else if (i < 32768)   { src = W2;   dstB = g_Wb + 192 * 128;  dstS = g_Ws + 192 * 128;  j = i - 24576; }
    else if (i < 294912)  { src = bilw; dstB = g_bilWb;           dstS = g_bilWs;           j = i - 32768; }
    else return;
    int kp = j >> 7, c = j & 127;
    float lo = src[(size_t)kp * 256 + c];
    float hi = src[(size_t)kp * 256 + 128 + c];
    uint32_t pb = pack2bf(lo, hi);
    float2 f = unpack_bf(pb);
    int jr = kp * 128 + (c & 7) * 16 + (c >> 3);   // fragment remap
    dstB[jr] = pb;
    dstS[jr] = pack2bf(lo - f.x, hi - f.y);
}

// ------------------------------------------------------------------
// Encoder GEMM (unchanged, known-good)
// ------------------------------------------------------------------
__global__ __launch_bounds__(256, 2) void gemm_bf16_n128(
    const float* __restrict__ A,
    const uint32_t* __restrict__ Wb, const uint32_t* __restrict__ Ws,
    float* __restrict__ C, int M, int K)
{
    __shared__ uint32_t sAb[128][17], sAs[128][17];
    __shared__ uint32_t sBb[16 * 132], sBs[16 * 132];

    int tid  = threadIdx.x;
    int lane = tid & 31, warp = tid >> 5;
    int g = lane >> 2, t4 = lane & 3;
    int r0 = warp * 16 + g;
    int row0 = blockIdx.x * 128;

    float acc[16][4];
#pragma unroll
    for (int nt = 0; nt < 16; nt++)
#pragma unroll
        for (int j = 0; j < 4; j++) acc[nt][j] = 0.f;

    for (int k0 = 0; k0 < K; k0 += 32) {
        __syncthreads();
#pragma unroll
        for (int u = 0; u < 4; u++) {
            int i = tid + u * 256;
            int r = i >> 3, q = i & 7;
            int gr = row0 + r;
            float4 v = (gr < M)
                ? __ldg((const float4*)(A + (size_t)gr * K + k0 + 4 * q))
                : make_float4(0.f, 0.f, 0.f, 0.f);
            uint32_t p0 = pack2bf(v.x, v.y);
            uint32_t p1 = pack2bf(v.z, v.w);
            float2 f0 = unpack_bf(p0), f1 = unpack_bf(p1);
            sAb[r][2 * q]     = p0;
            sAb[r][2 * q + 1] = p1;
            sAs[r][2 * q]     = pack2bf(v.x - f0.x, v.y - f0.y);
            sAs[r][2 * q + 1] = pack2bf(v.z - f1.x, v.w - f1.y);
        }
        {
            const uint32_t* srcB = Wb + (size_t)(k0 >> 1) * 128;
            const uint32_t* srcS = Ws + (size_t)(k0 >> 1) * 128;
#pragma unroll
            for (int u = 0; u < 2; u++) {
                int i = tid + u * 256;
                int kp = i >> 5, c4 = (i & 31) * 4;
                uint4 vb = __ldg((const uint4*)(srcB + kp * 128 + c4));
                uint4 vs = __ldg((const uint4*)(srcS + kp * 128 + c4));
                *(uint4*)&sBb[kp * 132 + c4] = vb;
                *(uint4*)&sBs[kp * 132 + c4] = vs;
            }
        }
        __syncthreads();

#pragma unroll
        for (int ks = 0; ks < 2; ks++) {
            int kp0 = ks * 8;
            uint32_t ab0 = sAb[r0    ][kp0 + t4];
            uint32_t ab1 = sAb[r0 + 8][kp0 + t4];
            uint32_t ab2 = sAb[r0    ][kp0 + t4 + 4];
            uint32_t ab3 = sAb[r0 + 8][kp0 + t4 + 4];
            uint32_t as0 = sAs[r0    ][kp0 + t4];
            uint32_t as1 = sAs[r0 + 8][kp0 + t4];
            uint32_t as2 = sAs[r0    ][kp0 + t4 + 4];
            uint32_t as3 = sAs[r0 + 8][kp0 + t4 + 4];
            const uint4* rb0 = (const uint4*)&sBb[(kp0 + t4    ) * 132 + g * 16];
            const uint4* rb1 = (const uint4*)&sBb[(kp0 + t4 + 4) * 132 + g * 16];
            const uint4* rs0 = (const uint4*)&sBs[(kp0 + t4    ) * 132 + g * 16];
            const uint4* rs1 = (const uint4*)&sBs[(kp0 + t4 + 4) * 132 + g * 16];
#pragma unroll
            for (int nt4 = 0; nt4 < 4; nt4++) {
                uint4 b0 = rb0[nt4], b1 = rb1[nt4];
                uint4 s0 = rs0[nt4], s1 = rs1[nt4];
                uint32_t bb0[4] = {b0.x, b0.y, b0.z, b0.w};
                uint32_t bb1[4] = {b1.x, b1.y, b1.z, b1.w};
                uint32_t bs0[4] = {s0.x, s0.y, s0.z, s0.w};
                uint32_t bs1[4] = {s1.x, s1.y, s1.z, s1.w};
#pragma unroll
                for (int q = 0; q < 4; q++) {
                    int nt = nt4 * 4 + q;
                    mma_bf16(acc[nt], ab0, ab1, ab2, ab3, bb0[q], bb1[q]);
                    mma_bf16(acc[nt], as0, as1, as2, as3, bb0[q], bb1[q]);
                    mma_bf16(acc[nt], ab0, ab1, ab2, ab3, bs0[q], bs1[q]);
                }
            }
        }
    }

#pragma unroll
    for (int nt = 0; nt < 16; nt++) {
        int c = nt * 8 + 2 * t4;
        int gr0 = row0 + r0, gr1 = gr0 + 8;
        if (gr0 < M)
            *(float2*)(C + (size_t)gr0 * 128 + c) = make_float2(acc[nt][0], acc[nt][1]);
        if (gr1 < M)
            *(float2*)(C + (size_t)gr1 * 128 + c) = make_float2(acc[nt][2], acc[nt][3]);
    }
}

// ------------------------------------------------------------------
// SpMM: one warp per destination row, 4-edge unroll (R11 version,
// measured 32.1us — dual-row variant regressed, reverted)
// ------------------------------------------------------------------
__global__ __launch_bounds__(256) void spmm_kernel(
    const float* __restrict__ H, const int* __restrict__ col,
    const float* __restrict__ val, const float* __restrict__ bias,
    const float* __restrict__ res, float* __restrict__ out)
{
    int w = (blockIdx.x * blockDim.x + threadIdx.x) >> 5;
    if (w >= N_NODES) return;
    int lane = threadIdx.x & 31;

    const float4* Hv = (const float4*)H;
    float4 acc = make_float4(0.f, 0.f, 0.f, 0.f);
    int s = g_rowptr[w], e = g_rowptr[w + 1];
    int i = s;
    for (; i + 3 < e; i += 4) {
        int cc[4]; float vv[4]; float4 hh[4];
#pragma unroll
        for (int u = 0; u < 4; u++) { cc[u] = __ldg(&col[i + u]); vv[u] = __ldg(&val[i + u]); }
#pragma unroll
        for (int u = 0; u < 4; u++) hh[u] = __ldg(&Hv[(size_t)cc[u] * 32 + lane]);
#pragma unroll
        for (int u = 0; u < 4; u++) {
            acc.x = fmaf(vv[u], hh[u].x, acc.x);
            acc.y = fmaf(vv[u], hh[u].y, acc.y);
            acc.z = fmaf(vv[u], hh[u].z, acc.z);
            acc.w = fmaf(vv[u], hh[u].w, acc.w);
        }
    }
    for (; i < e; i++) {
        int   c0 = __ldg(&col[i]);
        float v0 = __ldg(&val[i]);
        float4 h0 = __ldg(&Hv[(size_t)c0 * 32 + lane]);
        acc.x = fmaf(v0, h0.x, acc.x); acc.y = fmaf(v0, h0.y, acc.y);
        acc.z = fmaf(v0, h0.z, acc.z); acc.w = fmaf(v0, h0.w, acc.w);
    }

    float4 bb = __ldg(&((const float4*)bias)[lane]);
    float4 o;
    o.x = fmaxf(acc.x + bb.x, 0.f);
    o.y = fmaxf(acc.y + bb.y, 0.f);
    o.z = fmaxf(acc.z + bb.z, 0.f);
    o.w = fmaxf(acc.w + bb.w, 0.f);
    size_t vbase = (size_t)w * 32 + lane;
    if (res) {
        float4 rv = __ldg(&((const float4*)res)[vbase]);
        o.x += rv.x; o.y += rv.y; o.z += rv.z; o.w += rv.w;
    }
    ((float4*)out)[vbase] = o;
}

// ------------------------------------------------------------------
// Bilinear stage 1: split-bf16 3-MMA, cp.async double-buffered W.
// KC=2 k-slices per CTA (grid.y=16) for wave balance.
// ------------------------------------------------------------------
#define KC 2
#define WBUF_WORDS (2 * 16 * 132)
#define BIL_SMEM_WORDS (2 * 128 * 68 + 2 * WBUF_WORDS)
#define BIL_SMEM_BYTES (BIL_SMEM_WORDS * 4)

__global__ __launch_bounds__(256, 2) void bilinear_kernel(
    const float* __restrict__ latent, const int* __restrict__ idx,
    const uint32_t* __restrict__ bilWb, const uint32_t* __restrict__ bilWs,
    float* __restrict__ feat)
{
    extern __shared__ uint32_t smem[];
    uint32_t* sAb = smem;                      // [128][68] big plane
    uint32_t* sAs = sAb + 128 * 68;            // [128][68] small plane
    uint32_t* sWbase = sAs + 128 * 68;         // 2 x {sWb[16*132], sWs[16*132]}

    int tid  = threadIdx.x;
    int lane = tid & 31, warp = tid >> 5;
    int p0 = blockIdx.x * 128;
    int g = lane >> 2, t4 = lane & 3;
    int r0 = warp * 16 + g;

    int pg0 = p0 + r0, pg1 = p0 + r0 + 8;
    int pc0 = pg0 < NPAIRS ? pg0 : NPAIRS - 1;
    int pc1 = pg1 < NPAIRS ? pg1 : NPAIRS - 1;
    const float* Brow0 = latent + (size_t)__ldg(&idx[NPAIRS + pc0]) * 128;
    const float* Brow1 = latent + (size_t)__ldg(&idx[NPAIRS + pc1]) * 128;

    int cp_kp[2], cp_c4[2];
#pragma unroll
    for (int u = 0; u < 2; u++) {
        int i = tid + u * 256;
        cp_kp[u] = i >> 5; cp_c4[u] = (i & 31) * 4;
    }

    auto issue_chunk = [&](int gch, int buf) {
        int k = blockIdx.y * KC + (gch >> 2);
        int kpb = (gch & 3) * 16;
        const uint32_t* srcB = bilWb + ((size_t)k * 64 + kpb) * 128;
        const uint32_t* srcS = bilWs + ((size_t)k * 64 + kpb) * 128;
        uint32_t* dWb = sWbase + buf * WBUF_WORDS;
        uint32_t* dWs = dWb + 16 * 132;
        uint32_t ab = (uint32_t)__cvta_generic_to_shared(dWb);
        uint32_t as = (uint32_t)__cvta_generic_to_shared(dWs);
#pragma unroll
        for (int u = 0; u < 2; u++) {
            int off = cp_kp[u] * 132 + cp_c4[u];
            int src = cp_kp[u] * 128 + cp_c4[u];
            cp16(ab + off * 4, srcB + src);
            cp16(as + off * 4, srcS + src);
        }
        cp_commit();
    };

    for (int i = tid; i < 128 * 32; i += 256) {
        int p = i >> 5, l32 = i & 31;
        int c8 = l32 * 4, kp = l32 * 2;
        int pg = p0 + p; if (pg >= NPAIRS) pg = NPAIRS - 1;
        int na = __ldg(&idx[pg]);
        float4 v = __ldg((const float4*)(latent + (size_t)na * 128 + c8));
        uint32_t b0 = pack2bf(v.x, v.y);
        uint32_t b1 = pack2bf(v.z, v.w);
        float2 f0 = unpack_bf(b0), f1 = unpack_bf(b1);
        sAb[p * 68 + kp]     = b0;
        sAb[p * 68 + kp + 1] = b1;
        sAs[p * 68 + kp]     = pack2bf(v.x - f0.x, v.y - f0.y);
        sAs[p * 68 + kp + 1] = pack2bf(v.z - f1.x, v.w - f1.y);
    }

    issue_chunk(0, 0);   // prologue prefetch

    const int NCH = KC * 4;
    float acc[16][4];
    for (int gch = 0; gch < NCH; gch++) {
        if ((gch & 3) == 0) {
#pragma unroll
            for (int nt = 0; nt < 16; nt++)
#pragma unroll
                for (int j = 0; j < 4; j++) acc[nt][j] = 0.f;
        }
        if (gch + 1 < NCH) {
            issue_chunk(gch + 1, (gch + 1) & 1);
            asm volatile("cp.async.wait_group 1;");
        } else {
            asm volatile("cp.async.wait_group 0;");
        }
        __syncthreads();

        uint32_t* cWb = sWbase + (gch & 1) * WBUF_WORDS;
        uint32_t* cWs = cWb + 16 * 132;
        int k0 = (gch & 3) * 32;
#pragma unroll
        for (int ks = 0; ks < 2; ks++) {
            int kpg = (k0 >> 1) + ks * 8;
            uint32_t ab0 = sAb[(r0    ) * 68 + kpg + t4];
            uint32_t ab1 = sAb[(r0 + 8) * 68 + kpg + t4];
            uint32_t ab2 = sAb[(r0    ) * 68 + kpg + t4 + 4];
            uint32_t ab3 = sAb[(r0 + 8) * 68 + kpg + t4 + 4];
            uint32_t as0 = sAs[(r0    ) * 68 + kpg + t4];
            uint32_t as1 = sAs[(r0 + 8) * 68 + kpg + t4];
            uint32_t as2 = sAs[(r0    ) * 68 + kpg + t4 + 4];
            uint32_t as3 = sAs[(r0 + 8) * 68 + kpg + t4 + 4];
            int kp0 = ks * 8;
            const uint4* rb0 = (const uint4*)&cWb[(kp0 + t4    ) * 132 + g * 16];
            const uint4* rb1 = (const uint4*)&cWb[(kp0 + t4 + 4) * 132 + g * 16];
            const uint4* rs0 = (const uint4*)&cWs[(kp0 + t4    ) * 132 + g * 16];
            const uint4* rs1 = (const uint4*)&cWs[(kp0 + t4 + 4) * 132 + g * 16];
#pragma unroll
            for (int nt4 = 0; nt4 < 4; nt4++) {
                uint4 b0 = rb0[nt4], b1 = rb1[nt4];
                uint4 s0 = rs0[nt4], s1 = rs1[nt4];
                uint32_t bb0[4] = {b0.x, b0.y, b0.z, b0.w};
                uint32_t bb1[4] = {b1.x, b1.y, b1.z, b1.w};
                uint32_t bs0[4] = {s0.x, s0.y, s0.z, s0.w};
                uint32_t bs1[4] = {s1.x, s1.y, s1.z, s1.w};
#pragma unroll
                for (int q = 0; q < 4; q++) {
                    int nt = nt4 * 4 + q;
                    mma_bf16(acc[nt], ab0, ab1, ab2, ab3, bb0[q], bb1[q]);
                    mma_bf16(acc[nt], as0, as1, as2, as3, bb0[q], bb1[q]);
                    mma_bf16(acc[nt], ab0, ab1, ab2, ab3, bs0[q], bs1[q]);
                }
            }
        }

        if ((gch & 3) == 3) {
            int k = blockIdx.y * KC + (gch >> 2);
            float plo = 0.f, phi = 0.f;
#pragma unroll
            for (int nt = 0; nt < 16; nt++) {
                int c = nt * 8 + 2 * t4;
                float2 b0 = __ldg((const float2*)(Brow0 + c));
                float2 b1 = __ldg((const float2*)(Brow1 + c));
                plo = fmaf(acc[nt][0], b0.x, plo);
                plo = fmaf(acc[nt][1], b0.y, plo);
                phi = fmaf(acc[nt][2], b1.x, phi);
                phi = fmaf(acc[nt][3], b1.y, phi);
            }
            plo += __shfl_xor_sync(0xffffffffu, plo, 1);
            plo += __shfl_xor_sync(0xffffffffu, plo, 2);
            phi += __shfl_xor_sync(0xffffffffu, phi, 1);
            phi += __shfl_xor_sync(0xffffffffu, phi, 2);
            if (t4 == 0) {
                if (pg0 < NPAIRS) feat[(size_t)pg0 * ZDIM + k] = plo;
                if (pg1 < NPAIRS) feat[(size_t)pg1 * ZDIM + k] = phi;
            }
        }
        __syncthreads();
    }
}

// ------------------------------------------------------------------
// Stage 2: tiny MLP on feat -> predictions
// ------------------------------------------------------------------
__device__ __forceinline__ float elu1(float x) {
    return x > 0.f ? x : expm1f(x);
}

__global__ __launch_bounds__(256) void mlp_kernel(
    const float* __restrict__ feat, const float* __restrict__ bilb,
    const float* __restrict__ dw1, const float* __restrict__ db1,
    const float* __restrict__ dw2, const float* __restrict__ db2,
    float* __restrict__ pred)
{
    int p = blockIdx.x * blockDim.x + threadIdx.x;
    if (p >= NPAIRS) return;

    float f[ZDIM];
#pragma unroll
    for (int k = 0; k < ZDIM; k++)
        f[k] = elu1(feat[(size_t)p * ZDIM + k] + __ldg(&bilb[k]));

    float o = __ldg(&db2[0]);
#pragma unroll
    for (int kk = 0; kk < ZDIM; kk++) {
        float s = __ldg(&db1[kk]);
#pragma unroll
        for (int j = 0; j < ZDIM; j++)
            s = fmaf(f[j], __ldg(&dw1[j * ZDIM + kk]), s);
        o = fmaf(elu1(s), __ldg(&dw2[kk]), o);
    }
    pred[p] = o;
}

// ------------------------------------------------------------------
extern "C" void kernel_launch(void* const* d_in, const int* in_sizes, int n_in,
                              void* d_out, int out_size)
{
    const float* features = (const float*)d_in[0];
    const int*   adj_row  = (const int*)  d_in[1];
    const int*   adj_col  = (const int*)  d_in[2];
    const float* adj_val  = (const float*)d_in[3];
    const int*   idx      = (const int*)  d_in[4];
    const float* W0   = (const float*)d_in[5];
    const float* b0   = (const float*)d_in[6];
    const float* W1   = (const float*)d_in[7];
    const float* b1   = (const float*)d_in[8];
    const float* W2   = (const float*)d_in[9];
    const float* b2   = (const float*)d_in[10];
    const float* bilw = (const float*)d_in[11];
    const float* bilb = (const float*)d_in[12];
    const float* dw1  = (const float*)d_in[13];
    const float* db1  = (const float*)d_in[14];
    const float* dw2  = (const float*)d_in[15];
    const float* db2  = (const float*)d_in[16];

    float* out    = (float*)d_out;
    float* pred   = out;            // [NPAIRS]
    float* latent = out + NPAIRS;   // [N_NODES * NHID]

    float* h;  cudaGetSymbolAddress((void**)&h,  g_buf_h);
    float* x0; cudaGetSymbolAddress((void**)&x0, g_buf_x0);
    float* x1; cudaGetSymbolAddress((void**)&x1, g_buf_x1);
    float* ft; cudaGetSymbolAddress((void**)&ft, g_feat);
    uint32_t* wb;  cudaGetSymbolAddress((void**)&wb,  g_Wb);
    uint32_t* ws;  cudaGetSymbolAddress((void**)&ws,  g_Ws);
    uint32_t* bwb; cudaGetSymbolAddress((void**)&bwb, g_bilWb);
    uint32_t* bws; cudaGetSymbolAddress((void**)&bws, g_bilWs);

    static int smem_set = 0;
    if (!smem_set) {
        cudaFuncSetAttribute(bilinear_kernel,
                             cudaFuncAttributeMaxDynamicSharedMemorySize,
                             BIL_SMEM_BYTES);
        smem_set = 1;
    }

    prep_kernel<<<PREP_BLOCKS, 256>>>(W0, W1, W2, bilw, adj_row);

    const int gemm_grid = (N_NODES + 127) / 128;
    const int spmm_grid = (N_NODES * 32 + 255) / 256;

    gemm_bf16_n128<<<gemm_grid, 256>>>(features, wb, ws, h, N_NODES, NFEAT);
    spmm_kernel<<<spmm_grid, 256>>>(h, adj_col, adj_val, b0, nullptr, x0);

    gemm_bf16_n128<<<gemm_grid, 256>>>(x0, wb + 128 * 128, ws + 128 * 128, h, N_NODES, NHID);
    spmm_kernel<<<spmm_grid, 256>>>(h, adj_col, adj_val, b1, x0, x1);

    gemm_bf16_n128<<<gemm_grid, 256>>>(x1, wb + 192 * 128, ws + 192 * 128, h, N_NODES, NHID);
    spmm_kernel<<<spmm_grid, 256>>>(h, adj_col, adj_val, b2, x1, latent);

    dim3 bil_grid((NPAIRS + 127) / 128, ZDIM / KC);
    bilinear_kernel<<<bil_grid, 256, BIL_SMEM_BYTES>>>(latent, idx, bwb, bws, ft);
    mlp_kernel<<<(NPAIRS + 255) / 256, 256>>>(ft, bilb, dw1, db1, dw2, db2, pred);
}

// round 15
// speedup vs baseline: 1.2059x; 1.0011x over previous
#include <cuda_runtime.h>
#include <cstdint>

#define N_NODES 50000
#define N_EDGES 800000
#define NFEAT   256
#define NHID    128
#define ZDIM    32
#define NPAIRS  10000

// ---- scratch (static device globals; no allocation at runtime) ----
__device__ float    g_buf_h [(size_t)N_NODES * NHID];
__device__ float    g_buf_x0[(size_t)N_NODES * NHID];
__device__ float    g_buf_x1[(size_t)N_NODES * NHID];
__device__ int      g_rowptr[N_NODES + 1];
__device__ float    g_feat[(size_t)NPAIRS * ZDIM];
__device__ uint32_t g_Wb[256 * 128], g_Ws[256 * 128];
__device__ uint32_t g_bilWb[(size_t)ZDIM * 64 * 128];
__device__ uint32_t g_bilWs[(size_t)ZDIM * 64 * 128];

// ------------------------------------------------------------------
__device__ __forceinline__ uint32_t pack2bf(float lo, float hi) {
    uint32_t r;
    asm("cvt.rn.bf16x2.f32 %0, %1, %2;" : "=r"(r) : "f"(hi), "f"(lo));
    return r;
}
__device__ __forceinline__ float2 unpack_bf(uint32_t p) {
    return make_float2(__uint_as_float(p << 16),
                       __uint_as_float(p & 0xffff0000u));
}

__device__ __forceinline__ void mma_bf16(
    float* d, uint32_t a0, uint32_t a1, uint32_t a2, uint32_t a3,
    uint32_t b0, uint32_t b1)
{
    asm volatile(
        "mma.sync.aligned.m16n8k16.row.col.f32.bf16.bf16.f32 "
        "{%0,%1,%2,%3}, {%4,%5,%6,%7}, {%8,%9}, {%0,%1,%2,%3};\n"
        : "+f"(d[0]), "+f"(d[1]), "+f"(d[2]), "+f"(d[3])
        : "r"(a0), "r"(a1), "r"(a2), "r"(a3), "r"(b0), "r"(b1));
}

// cp.async helpers
__device__ __forceinline__ void cp16(uint32_t smem_addr, const void* gptr) {
    asm volatile("cp.async.cg.shared.global [%0], [%1], 16;"
                 :: "r"(smem_addr), "l"(gptr));
}
__device__ __forceinline__ void cp_commit() {
    asm volatile("cp.async.commit_group;");
}

// ------------------------------------------------------------------
// Fused prep kernel: weight pre-split + fragment remap + rowptr
// ------------------------------------------------------------------
#define PRESPLIT_ITEMS 294912
#define PRESPLIT_BLOCKS ((PRESPLIT_ITEMS + 255) / 256)          // 1152
#define ROWPTR_BLOCKS   ((N_NODES + 1 + 255) / 256)             // 196
#define PREP_BLOCKS     (PRESPLIT_BLOCKS + ROWPTR_BLOCKS)

__global__ void prep_kernel(const float* __restrict__ W0,
                            const float* __restrict__ W1,
                            const float* __restrict__ W2,
                            const float* __restrict__ bilw,
                            const int* __restrict__ row)
{
    if (blockIdx.x >= PRESPLIT_BLOCKS) {
        int r = (blockIdx.x - PRESPLIT_BLOCKS) * blockDim.x + threadIdx.x;
        if (r > N_NODES) return;
        int lo = 0, hi = N_EDGES;
        while (lo < hi) {
            int mid = (lo + hi) >> 1;
            if (row[mid] < r) lo = mid + 1; else hi = mid;
        }
        g_rowptr[r] = lo;
        return;
    }
    int i = blockIdx.x * blockDim.x + threadIdx.x;
    const float* src; uint32_t* dstB; uint32_t* dstS; int j;
    if (i < 16384)        { src = W0;   dstB = g_Wb;              dstS = g_Ws;              j = i; }
    else if (i < 24576)   { src = W1;   dstB = g_Wb + 128 * 128;  dstS = g_Ws + 128 * 128;  j = i - 16384; }
    else if (i < 32768)   { src = W2;   dstB = g_Wb + 192 * 128;  dstS = g_Ws + 192 * 128;  j = i - 24576; }
    else if (i < 294912)  { src = bilw; dstB = g_bilWb;           dstS = g_bilWs;           j = i - 32768; }
    else return;
    int kp = j >> 7, c = j & 127;
    float lo = src[(size_t)kp * 256 + c];
    float hi = src[(size_t)kp * 256 + 128 + c];
    uint32_t pb = pack2bf(lo, hi);
    float2 f = unpack_bf(pb);
    int jr = kp * 128 + (c & 7) * 16 + (c >> 3);   // fragment remap
    dstB[jr] = pb;
    dstS[jr] = pack2bf(lo - f.x, hi - f.y);
}

// ------------------------------------------------------------------
// Encoder GEMM: split-bf16 3-MMA, term-major inner order (4-deep ILP)
// ------------------------------------------------------------------
__global__ __launch_bounds__(256, 2) void gemm_bf16_n128(
    const float* __restrict__ A,
    const uint32_t* __restrict__ Wb, const uint32_t* __restrict__ Ws,
    float* __restrict__ C, int M, int K)
{
    __shared__ uint32_t sAb[128][17], sAs[128][17];
    __shared__ uint32_t sBb[16 * 132], sBs[16 * 132];

    int tid  = threadIdx.x;
    int lane = tid & 31, warp = tid >> 5;
    int g = lane >> 2, t4 = lane & 3;
    int r0 = warp * 16 + g;
    int row0 = blockIdx.x * 128;

    float acc[16][4];
#pragma unroll
    for (int nt = 0; nt < 16; nt++)
#pragma unroll
        for (int j = 0; j < 4; j++) acc[nt][j] = 0.f;

    for (int k0 = 0; k0 < K; k0 += 32) {
        __syncthreads();
#pragma unroll
        for (int u = 0; u < 4; u++) {
            int i = tid + u * 256;
            int r = i >> 3, q = i & 7;
            int gr = row0 + r;
            float4 v = (gr < M)
                ? __ldg((const float4*)(A + (size_t)gr * K + k0 + 4 * q))
                : make_float4(0.f, 0.f, 0.f, 0.f);
            uint32_t p0 = pack2bf(v.x, v.y);
            uint32_t p1 = pack2bf(v.z, v.w);
            float2 f0 = unpack_bf(p0), f1 = unpack_bf(p1);
            sAb[r][2 * q]     = p0;
            sAb[r][2 * q + 1] = p1;
            sAs[r][2 * q]     = pack2bf(v.x - f0.x, v.y - f0.y);
            sAs[r][2 * q + 1] = pack2bf(v.z - f1.x, v.w - f1.y);
        }
        {
            const uint32_t* srcB = Wb + (size_t)(k0 >> 1) * 128;
            const uint32_t* srcS = Ws + (size_t)(k0 >> 1) * 128;
#pragma unroll
            for (int u = 0; u < 2; u++) {
                int i = tid + u * 256;
                int kp = i >> 5, c4 = (i & 31) * 4;
                uint4 vb = __ldg((const uint4*)(srcB + kp * 128 + c4));
                uint4 vs = __ldg((const uint4*)(srcS + kp * 128 + c4));
                *(uint4*)&sBb[kp * 132 + c4] = vb;
                *(uint4*)&sBs[kp * 132 + c4] = vs;
            }
        }
        __syncthreads();

#pragma unroll
        for (int ks = 0; ks < 2; ks++) {
            int kp0 = ks * 8;
            uint32_t ab0 = sAb[r0    ][kp0 + t4];
            uint32_t ab1 = sAb[r0 + 8][kp0 + t4];
            uint32_t ab2 = sAb[r0    ][kp0 + t4 + 4];
            uint32_t ab3 = sAb[r0 + 8][kp0 + t4 + 4];
            uint32_t as0 = sAs[r0    ][kp0 + t4];
            uint32_t as1 = sAs[r0 + 8][kp0 + t4];
            uint32_t as2 = sAs[r0    ][kp0 + t4 + 4];
            uint32_t as3 = sAs[r0 + 8][kp0 + t4 + 4];
            const uint4* rb0 = (const uint4*)&sBb[(kp0 + t4    ) * 132 + g * 16];
            const uint4* rb1 = (const uint4*)&sBb[(kp0 + t4 + 4) * 132 + g * 16];
            const uint4* rs0 = (const uint4*)&sBs[(kp0 + t4    ) * 132 + g * 16];
            const uint4* rs1 = (const uint4*)&sBs[(kp0 + t4 + 4) * 132 + g * 16];
#pragma unroll
            for (int nt4 = 0; nt4 < 4; nt4++) {
                uint4 b0 = rb0[nt4], b1 = rb1[nt4];
                uint4 s0 = rs0[nt4], s1 = rs1[nt4];
                uint32_t bb0[4] = {b0.x, b0.y, b0.z, b0.w};
                uint32_t bb1[4] = {b1.x, b1.y, b1.z, b1.w};
                uint32_t bs0[4] = {s0.x, s0.y, s0.z, s0.w};
                uint32_t bs1[4] = {s1.x, s1.y, s1.z, s1.w};
                // term-major: 4 independent MMAs per term; per-acc order
                // (t0,t1,t2) unchanged -> bit-identical results
#pragma unroll
                for (int q = 0; q < 4; q++)
                    mma_bf16(acc[nt4 * 4 + q], ab0, ab1, ab2, ab3, bb0[q], bb1[q]);
#pragma unroll
                for (int q = 0; q < 4; q++)
                    mma_bf16(acc[nt4 * 4 + q], as0, as1, as2, as3, bb0[q], bb1[q]);
#pragma unroll
                for (int q = 0; q < 4; q++)
                    mma_bf16(acc[nt4 * 4 + q], ab0, ab1, ab2, ab3, bs0[q], bs1[q]);
            }
        }
    }

#pragma unroll
    for (int nt = 0; nt < 16; nt++) {
        int c = nt * 8 + 2 * t4;
        int gr0 = row0 + r0, gr1 = gr0 + 8;
        if (gr0 < M)
            *(float2*)(C + (size_t)gr0 * 128 + c) = make_float2(acc[nt][0], acc[nt][1]);
        if (gr1 < M)
            *(float2*)(C + (size_t)gr1 * 128 + c) = make_float2(acc[nt][2], acc[nt][3]);
    }
}

// ------------------------------------------------------------------
// SpMM: one warp per destination row, 4-edge unroll (known-good)
// ------------------------------------------------------------------
__global__ __launch_bounds__(256) void spmm_kernel(
    const float* __restrict__ H, const int* __restrict__ col,
    const float* __restrict__ val, const float* __restrict__ bias,
    const float* __restrict__ res, float* __restrict__ out)
{
    int w = (blockIdx.x * blockDim.x + threadIdx.x) >> 5;
    if (w >= N_NODES) return;
    int lane = threadIdx.x & 31;

    const float4* Hv = (const float4*)H;
    float4 acc = make_float4(0.f, 0.f, 0.f, 0.f);
    int s = g_rowptr[w], e = g_rowptr[w + 1];
    int i = s;
    for (; i + 3 < e; i += 4) {
        int cc[4]; float vv[4]; float4 hh[4];
#pragma unroll
        for (int u = 0; u < 4; u++) { cc[u] = __ldg(&col[i + u]); vv[u] = __ldg(&val[i + u]); }
#pragma unroll
        for (int u = 0; u < 4; u++) hh[u] = __ldg(&Hv[(size_t)cc[u] * 32 + lane]);
#pragma unroll
        for (int u = 0; u < 4; u++) {
            acc.x = fmaf(vv[u], hh[u].x, acc.x);
            acc.y = fmaf(vv[u], hh[u].y, acc.y);
            acc.z = fmaf(vv[u], hh[u].z, acc.z);
            acc.w = fmaf(vv[u], hh[u].w, acc.w);
        }
    }
    for (; i < e; i++) {
        int   c0 = __ldg(&col[i]);
        float v0 = __ldg(&val[i]);
        float4 h0 = __ldg(&Hv[(size_t)c0 * 32 + lane]);
        acc.x = fmaf(v0, h0.x, acc.x); acc.y = fmaf(v0, h0.y, acc.y);
        acc.z = fmaf(v0, h0.z, acc.z); acc.w = fmaf(v0, h0.w, acc.w);
    }

    float4 bb = __ldg(&((const float4*)bias)[lane]);
    float4 o;
    o.x = fmaxf(acc.x + bb.x, 0.f);
    o.y = fmaxf(acc.y + bb.y, 0.f);
    o.z = fmaxf(acc.z + bb.z, 0.f);
    o.w = fmaxf(acc.w + bb.w, 0.f);
    size_t vbase = (size_t)w * 32 + lane;
    if (res) {
        float4 rv = __ldg(&((const float4*)res)[vbase]);
        o.x += rv.x; o.y += rv.y; o.z += rv.z; o.w += rv.w;
    }
    ((float4*)out)[vbase] = o;
}

// ------------------------------------------------------------------
// Bilinear stage 1: split-bf16 3-MMA, cp.async double-buffered W,
// KC=2, term-major inner order.
// ------------------------------------------------------------------
#define KC 2
#define WBUF_WORDS (2 * 16 * 132)
#define BIL_SMEM_WORDS (2 * 128 * 68 + 2 * WBUF_WORDS)
#define BIL_SMEM_BYTES (BIL_SMEM_WORDS * 4)

__global__ __launch_bounds__(256, 2) void bilinear_kernel(
    const float* __restrict__ latent, const int* __restrict__ idx,
    const uint32_t* __restrict__ bilWb, const uint32_t* __restrict__ bilWs,
    float* __restrict__ feat)
{
    extern __shared__ uint32_t smem[];
    uint32_t* sAb = smem;
    uint32_t* sAs = sAb + 128 * 68;
    uint32_t* sWbase = sAs + 128 * 68;

    int tid  = threadIdx.x;
    int lane = tid & 31, warp = tid >> 5;
    int p0 = blockIdx.x * 128;
    int g = lane >> 2, t4 = lane & 3;
    int r0 = warp * 16 + g;

    int pg0 = p0 + r0, pg1 = p0 + r0 + 8;
    int pc0 = pg0 < NPAIRS ? pg0 : NPAIRS - 1;
    int pc1 = pg1 < NPAIRS ? pg1 : NPAIRS - 1;
    const float* Brow0 = latent + (size_t)__ldg(&idx[NPAIRS + pc0]) * 128;
    const float* Brow1 = latent + (size_t)__ldg(&idx[NPAIRS + pc1]) * 128;

    int cp_kp[2], cp_c4[2];
#pragma unroll
    for (int u = 0; u < 2; u++) {
        int i = tid + u * 256;
        cp_kp[u] = i >> 5; cp_c4[u] = (i & 31) * 4;
    }

    auto issue_chunk = [&](int gch, int buf) {
        int k = blockIdx.y * KC + (gch >> 2);
        int kpb = (gch & 3) * 16;
        const uint32_t* srcB = bilWb + ((size_t)k * 64 + kpb) * 128;
        const uint32_t* srcS = bilWs + ((size_t)k * 64 + kpb) * 128;
        uint32_t* dWb = sWbase + buf * WBUF_WORDS;
        uint32_t* dWs = dWb + 16 * 132;
        uint32_t ab = (uint32_t)__cvta_generic_to_shared(dWb);
        uint32_t as = (uint32_t)__cvta_generic_to_shared(dWs);
#pragma unroll
        for (int u = 0; u < 2; u++) {
            int off = cp_kp[u] * 132 + cp_c4[u];
            int src = cp_kp[u] * 128 + cp_c4[u];
            cp16(ab + off * 4, srcB + src);
            cp16(as + off * 4, srcS + src);
        }
        cp_commit();
    };

    for (int i = tid; i < 128 * 32; i += 256) {
        int p = i >> 5, l32 = i & 31;
        int c8 = l32 * 4, kp = l32 * 2;
        int pg = p0 + p; if (pg >= NPAIRS) pg = NPAIRS - 1;
        int na = __ldg(&idx[pg]);
        float4 v = __ldg((const float4*)(latent + (size_t)na * 128 + c8));
        uint32_t b0 = pack2bf(v.x, v.y);
        uint32_t b1 = pack2bf(v.z, v.w);
        float2 f0 = unpack_bf(b0), f1 = unpack_bf(b1);
        sAb[p * 68 + kp]     = b0;
        sAb[p * 68 + kp + 1] = b1;
        sAs[p * 68 + kp]     = pack2bf(v.x - f0.x, v.y - f0.y);
        sAs[p * 68 + kp + 1] = pack2bf(v.z - f1.x, v.w - f1.y);
    }

    issue_chunk(0, 0);

    const int NCH = KC * 4;
    float acc[16][4];
    for (int gch = 0; gch < NCH; gch++) {
        if ((gch & 3) == 0) {
#pragma unroll
            for (int nt = 0; nt < 16; nt++)
#pragma unroll
                for (int j = 0; j < 4; j++) acc[nt][j] = 0.f;
        }
        if (gch + 1 < NCH) {
            issue_chunk(gch + 1, (gch + 1) & 1);
            asm volatile("cp.async.wait_group 1;");
        } else {
            asm volatile("cp.async.wait_group 0;");
        }
        __syncthreads();

        uint32_t* cWb = sWbase + (gch & 1) * WBUF_WORDS;
        uint32_t* cWs = cWb + 16 * 132;
        int k0 = (gch & 3) * 32;
#pragma unroll
        for (int ks = 0; ks < 2; ks++) {
            int kpg = (k0 >> 1) + ks * 8;
            uint32_t ab0 = sAb[(r0    ) * 68 + kpg + t4];
            uint32_t ab1 = sAb[(r0 + 8) * 68 + kpg + t4];
            uint32_t ab2 = sAb[(r0    ) * 68 + kpg + t4 + 4];
            uint32_t ab3 = sAb[(r0 + 8) * 68 + kpg + t4 + 4];
            uint32_t as0 = sAs[(r0    ) * 68 + kpg + t4];
            uint32_t as1 = sAs[(r0 + 8) * 68 + kpg + t4];
            uint32_t as2 = sAs[(r0    ) * 68 + kpg + t4 + 4];
            uint32_t as3 = sAs[(r0 + 8) * 68 + kpg + t4 + 4];
            int kp0 = ks * 8;
            const uint4* rb0 = (const uint4*)&cWb[(kp0 + t4    ) * 132 + g * 16];
            const uint4* rb1 = (const uint4*)&cWb[(kp0 + t4 + 4) * 132 + g * 16];
            const uint4* rs0 = (const uint4*)&cWs[(kp0 + t4    ) * 132 + g * 16];
            const uint4* rs1 = (const uint4*)&cWs[(kp0 + t4 + 4) * 132 + g * 16];
#pragma unroll
            for (int nt4 = 0; nt4 < 4; nt4++) {
                uint4 b0 = rb0[nt4], b1 = rb1[nt4];
                uint4 s0 = rs0[nt4], s1 = rs1[nt4];
                uint32_t bb0[4] = {b0.x, b0.y, b0.z, b0.w};
                uint32_t bb1[4] = {b1.x, b1.y, b1.z, b1.w};
                uint32_t bs0[4] = {s0.x, s0.y, s0.z, s0.w};
                uint32_t bs1[4] = {s1.x, s1.y, s1.z, s1.w};
                // term-major issue order (bit-identical per-acc sequence)
#pragma unroll
                for (int q = 0; q < 4; q++)
                    mma_bf16(acc[nt4 * 4 + q], ab0, ab1, ab2, ab3, bb0[q], bb1[q]);
#pragma unroll
                for (int q = 0; q < 4; q++)
                    mma_bf16(acc[nt4 * 4 + q], as0, as1, as2, as3, bb0[q], bb1[q]);
#pragma unroll
                for (int q = 0; q < 4; q++)
                    mma_bf16(acc[nt4 * 4 + q], ab0, ab1, ab2, ab3, bs0[q], bs1[q]);
            }
        }

        if ((gch & 3) == 3) {
            int k = blockIdx.y * KC + (gch >> 2);
            float plo = 0.f, phi = 0.f;
#pragma unroll
            for (int nt = 0; nt < 16; nt++) {
                int c = nt * 8 + 2 * t4;
                float2 b0 = __ldg((const float2*)(Brow0 + c));
                float2 b1 = __ldg((const float2*)(Brow1 + c));
                plo = fmaf(acc[nt][0], b0.x, plo);
                plo = fmaf(acc[nt][1], b0.y, plo);
                phi = fmaf(acc[nt][2], b1.x, phi);
                phi = fmaf(acc[nt][3], b1.y, phi);
            }
            plo += __shfl_xor_sync(0xffffffffu, plo, 1);
            plo += __shfl_xor_sync(0xffffffffu, plo, 2);
            phi += __shfl_xor_sync(0xffffffffu, phi, 1);
            phi += __shfl_xor_sync(0xffffffffu, phi, 2);
            if (t4 == 0) {
                if (pg0 < NPAIRS) feat[(size_t)pg0 * ZDIM + k] = plo;
                if (pg1 < NPAIRS) feat[(size_t)pg1 * ZDIM + k] = phi;
            }
        }
        __syncthreads();
    }
}

// ------------------------------------------------------------------
// Stage 2: tiny MLP on feat -> predictions
// ------------------------------------------------------------------
__device__ __forceinline__ float elu1(float x) {
    return x > 0.f ? x : expm1f(x);
}

__global__ __launch_bounds__(256) void mlp_kernel(
    const float* __restrict__ feat, const float* __restrict__ bilb,
    const float* __restrict__ dw1, const float* __restrict__ db1,
    const float* __restrict__ dw2, const float* __restrict__ db2,
    float* __restrict__ pred)
{
    int p = blockIdx.x * blockDim.x + threadIdx.x;
    if (p >= NPAIRS) return;

    float f[ZDIM];
#pragma unroll
    for (int k = 0; k < ZDIM; k++)
        f[k] = elu1(feat[(size_t)p * ZDIM + k] + __ldg(&bilb[k]));

    float o = __ldg(&db2[0]);
#pragma unroll
    for (int kk = 0; kk < ZDIM; kk++) {
        float s = __ldg(&db1[kk]);
#pragma unroll
        for (int j = 0; j < ZDIM; j++)
            s = fmaf(f[j], __ldg(&dw1[j * ZDIM + kk]), s);
        o = fmaf(elu1(s), __ldg(&dw2[kk]), o);
    }
    pred[p] = o;
}

// ------------------------------------------------------------------
extern "C" void kernel_launch(void* const* d_in, const int* in_sizes, int n_in,
                              void* d_out, int out_size)
{
    const float* features = (const float*)d_in[0];
    const int*   adj_row  = (const int*)  d_in[1];
    const int*   adj_col  = (const int*)  d_in[2];
    const float* adj_val  = (const float*)d_in[3];
    const int*   idx      = (const int*)  d_in[4];
    const float* W0   = (const float*)d_in[5];
    const float* b0   = (const float*)d_in[6];
    const float* W1   = (const float*)d_in[7];
    const float* b1   = (const float*)d_in[8];
    const float* W2   = (const float*)d_in[9];
    const float* b2   = (const float*)d_in[10];
    const float* bilw = (const float*)d_in[11];
    const float* bilb = (const float*)d_in[12];
    const float* dw1  = (const float*)d_in[13];
    const float* db1  = (const float*)d_in[14];
    const float* dw2  = (const float*)d_in[15];
    const float* db2  = (const float*)d_in[16];

    float* out    = (float*)d_out;
    float* pred   = out;            // [NPAIRS]
    float* latent = out + NPAIRS;   // [N_NODES * NHID]

    float* h;  cudaGetSymbolAddress((void**)&h,  g_buf_h);
    float* x0; cudaGetSymbolAddress((void**)&x0, g_buf_x0);
    float* x1; cudaGetSymbolAddress((void**)&x1, g_buf_x1);
    float* ft; cudaGetSymbolAddress((void**)&ft, g_feat);
    uint32_t* wb;  cudaGetSymbolAddress((void**)&wb,  g_Wb);
    uint32_t* ws;  cudaGetSymbolAddress((void**)&ws,  g_Ws);
    uint32_t* bwb; cudaGetSymbolAddress((void**)&bwb, g_bilWb);
    uint32_t* bws; cudaGetSymbolAddress((void**)&bws, g_bilWs);

    static int smem_set = 0;
    if (!smem_set) {
        cudaFuncSetAttribute(bilinear_kernel,
                             cudaFuncAttributeMaxDynamicSharedMemorySize,
                             BIL_SMEM_BYTES);
        smem_set = 1;
    }

    prep_kernel<<<PREP_BLOCKS, 256>>>(W0, W1, W2, bilw, adj_row);

    const int gemm_grid = (N_NODES + 127) / 128;
    const int spmm_grid = (N_NODES * 32 + 255) / 256;

    gemm_bf16_n128<<<gemm_grid, 256>>>(features, wb, ws, h, N_NODES, NFEAT);
    spmm_kernel<<<spmm_grid, 256>>>(h, adj_col, adj_val, b0, nullptr, x0);

    gemm_bf16_n128<<<gemm_grid, 256>>>(x0, wb + 128 * 128, ws + 128 * 128, h, N_NODES, NHID);
    spmm_kernel<<<spmm_grid, 256>>>(h, adj_col, adj_val, b1, x0, x1);

    gemm_bf16_n128<<<gemm_grid, 256>>>(x1, wb + 192 * 128, ws + 192 * 128, h, N_NODES, NHID);
    spmm_kernel<<<spmm_grid, 256>>>(h, adj_col, adj_val, b2, x1, latent);

    dim3 bil_grid((NPAIRS + 127) / 128, ZDIM / KC);
    bilinear_kernel<<<bil_grid, 256, BIL_SMEM_BYTES>>>(latent, idx, bwb, bws, ft);
    mlp_kernel<<<(NPAIRS + 255) / 256, 256>>>(ft, bilb, dw1, db1, dw2, db2, pred);
}

// round 16
// speedup vs baseline: 1.2830x; 1.0640x over previous
#include <cuda_runtime.h>
#include <cuda_fp16.h>
#include <cstdint>

#define N_NODES 50000
#define N_EDGES 800000
#define NFEAT   256
#define NHID    128
#define ZDIM    32
#define NPAIRS  10000

// ---- scratch (static device globals; no allocation at runtime) ----
__device__ float    g_buf_h [(size_t)N_NODES * NHID];
__device__ float    g_buf_x0[(size_t)N_NODES * NHID];
__device__ float    g_buf_x1[(size_t)N_NODES * NHID];
__device__ int      g_rowptr[N_NODES + 1];
__device__ float    g_feat[(size_t)NPAIRS * ZDIM];
// encoder planes: bf16x2 (3-term split, unchanged)
__device__ uint32_t g_Wb[256 * 128], g_Ws[256 * 128];
// bilinear planes: fp16x2 big + small (2-term scheme), fragment-remapped
__device__ uint32_t g_bilWb[(size_t)ZDIM * 64 * 128];
__device__ uint32_t g_bilWs[(size_t)ZDIM * 64 * 128];

// ------------------------------------------------------------------
// bf16 helpers (encoder)
// ------------------------------------------------------------------
__device__ __forceinline__ uint32_t pack2bf(float lo, float hi) {
    uint32_t r;
    asm("cvt.rn.bf16x2.f32 %0, %1, %2;" : "=r"(r) : "f"(hi), "f"(lo));
    return r;
}
__device__ __forceinline__ float2 unpack_bf(uint32_t p) {
    return make_float2(__uint_as_float(p << 16),
                       __uint_as_float(p & 0xffff0000u));
}

// fp16 helpers (bilinear)
__device__ __forceinline__ uint32_t pack2h(float lo, float hi) {
    uint32_t r;
    asm("cvt.rn.f16x2.f32 %0, %1, %2;" : "=r"(r) : "f"(hi), "f"(lo));
    return r;
}
__device__ __forceinline__ float2 unpack_h(uint32_t p) {
    return make_float2(__half2float(__ushort_as_half((unsigned short)(p & 0xffff))),
                       __half2float(__ushort_as_half((unsigned short)(p >> 16))));
}

__device__ __forceinline__ void mma_bf16(
    float* d, uint32_t a0, uint32_t a1, uint32_t a2, uint32_t a3,
    uint32_t b0, uint32_t b1)
{
    asm volatile(
        "mma.sync.aligned.m16n8k16.row.col.f32.bf16.bf16.f32 "
        "{%0,%1,%2,%3}, {%4,%5,%6,%7}, {%8,%9}, {%0,%1,%2,%3};\n"
        : "+f"(d[0]), "+f"(d[1]), "+f"(d[2]), "+f"(d[3])
        : "r"(a0), "r"(a1), "r"(a2), "r"(a3), "r"(b0), "r"(b1));
}

__device__ __forceinline__ void mma_f16(
    float* d, uint32_t a0, uint32_t a1, uint32_t a2, uint32_t a3,
    uint32_t b0, uint32_t b1)
{
    asm volatile(
        "mma.sync.aligned.m16n8k16.row.col.f32.f16.f16.f32 "
        "{%0,%1,%2,%3}, {%4,%5,%6,%7}, {%8,%9}, {%0,%1,%2,%3};\n"
        : "+f"(d[0]), "+f"(d[1]), "+f"(d[2]), "+f"(d[3])
        : "r"(a0), "r"(a1), "r"(a2), "r"(a3), "r"(b0), "r"(b1));
}

// cp.async helpers
__device__ __forceinline__ void cp16(uint32_t smem_addr, const void* gptr) {
    asm volatile("cp.async.cg.shared.global [%0], [%1], 16;"
                 :: "r"(smem_addr), "l"(gptr));
}
__device__ __forceinline__ void cp_commit() {
    asm volatile("cp.async.commit_group;");
}

// ------------------------------------------------------------------
// Fused prep kernel: encoder bf16 pre-split (unchanged) + bilinear
// fp16 big/small pre-split + rowptr.
// ------------------------------------------------------------------
#define PRESPLIT_ITEMS 294912
#define PRESPLIT_BLOCKS ((PRESPLIT_ITEMS + 255) / 256)          // 1152
#define ROWPTR_BLOCKS   ((N_NODES + 1 + 255) / 256)             // 196
#define PREP_BLOCKS     (PRESPLIT_BLOCKS + ROWPTR_BLOCKS)

__global__ void prep_kernel(const float* __restrict__ W0,
                            const float* __restrict__ W1,
                            const float* __restrict__ W2,
                            const float* __restrict__ bilw,
                            const int* __restrict__ row)
{
    if (blockIdx.x >= PRESPLIT_BLOCKS) {
        int r = (blockIdx.x - PRESPLIT_BLOCKS) * blockDim.x + threadIdx.x;
        if (r > N_NODES) return;
        int lo = 0, hi = N_EDGES;
        while (lo < hi) {
            int mid = (lo + hi) >> 1;
            if (row[mid] < r) lo = mid + 1; else hi = mid;
        }
        g_rowptr[r] = lo;
        return;
    }
    int i = blockIdx.x * blockDim.x + threadIdx.x;
    if (i < 32768) {
        // encoder weights: bf16x2 3-term planes (unchanged numerics)
        const float* src; uint32_t* dstB; uint32_t* dstS; int j;
        if (i < 16384)      { src = W0; dstB = g_Wb;             dstS = g_Ws;             j = i; }
        else if (i < 24576) { src = W1; dstB = g_Wb + 128 * 128; dstS = g_Ws + 128 * 128; j = i - 16384; }
        else                { src = W2; dstB = g_Wb + 192 * 128; dstS = g_Ws + 192 * 128; j = i - 24576; }
        int kp = j >> 7, c = j & 127;
        float lo = src[(size_t)kp * 256 + c];
        float hi = src[(size_t)kp * 256 + 128 + c];
        uint32_t pb = pack2bf(lo, hi);
        float2 f = unpack_bf(pb);
        int jr = kp * 128 + (c & 7) * 16 + (c >> 3);
        dstB[jr] = pb;
        dstS[jr] = pack2bf(lo - f.x, hi - f.y);
    } else if (i < 294912) {
        // bilinear weights: fp16x2 big + small planes
        int j = i - 32768;
        int kp = j >> 7, c = j & 127;
        float lo = bilw[(size_t)kp * 256 + c];
        float hi = bilw[(size_t)kp * 256 + 128 + c];
        uint32_t ph = pack2h(lo, hi);
        float2 f = unpack_h(ph);
        int jr = kp * 128 + (c & 7) * 16 + (c >> 3);
        g_bilWb[jr] = ph;
        g_bilWs[jr] = pack2h(lo - f.x, hi - f.y);
    }
}

// ------------------------------------------------------------------
// Encoder GEMM: split-bf16 3-MMA (unchanged, known-good)
// ------------------------------------------------------------------
__global__ __launch_bounds__(256, 2) void gemm_bf16_n128(
    const float* __restrict__ A,
    const uint32_t* __restrict__ Wb, const uint32_t* __restrict__ Ws,
    float* __restrict__ C, int M, int K)
{
    __shared__ uint32_t sAb[128][17], sAs[128][17];
    __shared__ uint32_t sBb[16 * 132], sBs[16 * 132];

    int tid  = threadIdx.x;
    int lane = tid & 31, warp = tid >> 5;
    int g = lane >> 2, t4 = lane & 3;
    int r0 = warp * 16 + g;
    int row0 = blockIdx.x * 128;

    float acc[16][4];
#pragma unroll
    for (int nt = 0; nt < 16; nt++)
#pragma unroll
        for (int j = 0; j < 4; j++) acc[nt][j] = 0.f;

    for (int k0 = 0; k0 < K; k0 += 32) {
        __syncthreads();
#pragma unroll
        for (int u = 0; u < 4; u++) {
            int i = tid + u * 256;
            int r = i >> 3, q = i & 7;
            int gr = row0 + r;
            float4 v = (gr < M)
                ? __ldg((const float4*)(A + (size_t)gr * K + k0 + 4 * q))
                : make_float4(0.f, 0.f, 0.f, 0.f);
            uint32_t p0 = pack2bf(v.x, v.y);
            uint32_t p1 = pack2bf(v.z, v.w);
            float2 f0 = unpack_bf(p0), f1 = unpack_bf(p1);
            sAb[r][2 * q]     = p0;
            sAb[r][2 * q + 1] = p1;
            sAs[r][2 * q]     = pack2bf(v.x - f0.x, v.y - f0.y);
            sAs[r][2 * q + 1] = pack2bf(v.z - f1.x, v.w - f1.y);
        }
        {
            const uint32_t* srcB = Wb + (size_t)(k0 >> 1) * 128;
            const uint32_t* srcS = Ws + (size_t)(k0 >> 1) * 128;
#pragma unroll
            for (int u = 0; u < 2; u++) {
                int i = tid + u * 256;
                int kp = i >> 5, c4 = (i & 31) * 4;
                uint4 vb = __ldg((const uint4*)(srcB + kp * 128 + c4));
                uint4 vs = __ldg((const uint4*)(srcS + kp * 128 + c4));
                *(uint4*)&sBb[kp * 132 + c4] = vb;
                *(uint4*)&sBs[kp * 132 + c4] = vs;
            }
        }
        __syncthreads();

#pragma unroll
        for (int ks = 0; ks < 2; ks++) {
            int kp0 = ks * 8;
            uint32_t ab0 = sAb[r0    ][kp0 + t4];
            uint32_t ab1 = sAb[r0 + 8][kp0 + t4];
            uint32_t ab2 = sAb[r0    ][kp0 + t4 + 4];
            uint32_t ab3 = sAb[r0 + 8][kp0 + t4 + 4];
            uint32_t as0 = sAs[r0    ][kp0 + t4];
            uint32_t as1 = sAs[r0 + 8][kp0 + t4];
            uint32_t as2 = sAs[r0    ][kp0 + t4 + 4];
            uint32_t as3 = sAs[r0 + 8][kp0 + t4 + 4];
            const uint4* rb0 = (const uint4*)&sBb[(kp0 + t4    ) * 132 + g * 16];
            const uint4* rb1 = (const uint4*)&sBb[(kp0 + t4 + 4) * 132 + g * 16];
            const uint4* rs0 = (const uint4*)&sBs[(kp0 + t4    ) * 132 + g * 16];
            const uint4* rs1 = (const uint4*)&sBs[(kp0 + t4 + 4) * 132 + g * 16];
#pragma unroll
            for (int nt4 = 0; nt4 < 4; nt4++) {
                uint4 b0 = rb0[nt4], b1 = rb1[nt4];
                uint4 s0 = rs0[nt4], s1 = rs1[nt4];
                uint32_t bb0[4] = {b0.x, b0.y, b0.z, b0.w};
                uint32_t bb1[4] = {b1.x, b1.y, b1.z, b1.w};
                uint32_t bs0[4] = {s0.x, s0.y, s0.z, s0.w};
                uint32_t bs1[4] = {s1.x, s1.y, s1.z, s1.w};
#pragma unroll
                for (int q = 0; q < 4; q++)
                    mma_bf16(acc[nt4 * 4 + q], ab0, ab1, ab2, ab3, bb0[q], bb1[q]);
#pragma unroll
                for (int q = 0; q < 4; q++)
                    mma_bf16(acc[nt4 * 4 + q], as0, as1, as2, as3, bb0[q], bb1[q]);
#pragma unroll
                for (int q = 0; q < 4; q++)
                    mma_bf16(acc[nt4 * 4 + q], ab0, ab1, ab2, ab3, bs0[q], bs1[q]);
            }
        }
    }

#pragma unroll
    for (int nt = 0; nt < 16; nt++) {
        int c = nt * 8 + 2 * t4;
        int gr0 = row0 + r0, gr1 = gr0 + 8;
        if (gr0 < M)
            *(float2*)(C + (size_t)gr0 * 128 + c) = make_float2(acc[nt][0], acc[nt][1]);
        if (gr1 < M)
            *(float2*)(C + (size_t)gr1 * 128 + c) = make_float2(acc[nt][2], acc[nt][3]);
    }
}

// ------------------------------------------------------------------
// SpMM: one warp per destination row, 4-edge unroll (known-good)
// ------------------------------------------------------------------
__global__ __launch_bounds__(256) void spmm_kernel(
    const float* __restrict__ H, const int* __restrict__ col,
    const float* __restrict__ val, const float* __restrict__ bias,
    const float* __restrict__ res, float* __restrict__ out)
{
    int w = (blockIdx.x * blockDim.x + threadIdx.x) >> 5;
    if (w >= N_NODES) return;
    int lane = threadIdx.x & 31;

    const float4* Hv = (const float4*)H;
    float4 acc = make_float4(0.f, 0.f, 0.f, 0.f);
    int s = g_rowptr[w], e = g_rowptr[w + 1];
    int i = s;
    for (; i + 3 < e; i += 4) {
        int cc[4]; float vv[4]; float4 hh[4];
#pragma unroll
        for (int u = 0; u < 4; u++) { cc[u] = __ldg(&col[i + u]); vv[u] = __ldg(&val[i + u]); }
#pragma unroll
        for (int u = 0; u < 4; u++) hh[u] = __ldg(&Hv[(size_t)cc[u] * 32 + lane]);
#pragma unroll
        for (int u = 0; u < 4; u++) {
            acc.x = fmaf(vv[u], hh[u].x, acc.x);
            acc.y = fmaf(vv[u], hh[u].y, acc.y);
            acc.z = fmaf(vv[u], hh[u].z, acc.z);
            acc.w = fmaf(vv[u], hh[u].w, acc.w);
        }
    }
    for (; i < e; i++) {
        int   c0 = __ldg(&col[i]);
        float v0 = __ldg(&val[i]);
        float4 h0 = __ldg(&Hv[(size_t)c0 * 32 + lane]);
        acc.x = fmaf(v0, h0.x, acc.x); acc.y = fmaf(v0, h0.y, acc.y);
        acc.z = fmaf(v0, h0.z, acc.z); acc.w = fmaf(v0, h0.w, acc.w);
    }

    float4 bb = __ldg(&((const float4*)bias)[lane]);
    float4 o;
    o.x = fmaxf(acc.x + bb.x, 0.f);
    o.y = fmaxf(acc.y + bb.y, 0.f);
    o.z = fmaxf(acc.z + bb.z, 0.f);
    o.w = fmaxf(acc.w + bb.w, 0.f);
    size_t vbase = (size_t)w * 32 + lane;
    if (res) {
        float4 rv = __ldg(&((const float4*)res)[vbase]);
        o.x += rv.x; o.y += rv.y; o.z += rv.z; o.w += rv.w;
    }
    ((float4*)out)[vbase] = o;
}

// ------------------------------------------------------------------
// Bilinear stage 1: fp16 2-term scheme.
// A rounded once to fp16 (single sA plane); W pre-split fp16 Wh/Ws.
// U = Ah·Wh + Ah·Ws  (error = As·W ~ 2^-12, pred rel_err ~4e-4).
// cp.async double-buffered W, KC=2.
// ------------------------------------------------------------------
#define KC 2
#define WBUF_WORDS (2 * 16 * 132)
#define BIL_SMEM_WORDS (128 * 68 + 2 * WBUF_WORDS)
#define BIL_SMEM_BYTES (BIL_SMEM_WORDS * 4)

__global__ __launch_bounds__(256, 2) void bilinear_kernel(
    const float* __restrict__ latent, const int* __restrict__ idx,
    const uint32_t* __restrict__ bilWb, const uint32_t* __restrict__ bilWs,
    float* __restrict__ feat)
{
    extern __shared__ uint32_t smem[];
    uint32_t* sAh = smem;                      // [128][68] fp16x2 A plane
    uint32_t* sWbase = sAh + 128 * 68;         // 2 x {Wh[16*132], Ws[16*132]}

    int tid  = threadIdx.x;
    int lane = tid & 31, warp = tid >> 5;
    int p0 = blockIdx.x * 128;
    int g = lane >> 2, t4 = lane & 3;
    int r0 = warp * 16 + g;

    int pg0 = p0 + r0, pg1 = p0 + r0 + 8;
    int pc0 = pg0 < NPAIRS ? pg0 : NPAIRS - 1;
    int pc1 = pg1 < NPAIRS ? pg1 : NPAIRS - 1;
    const float* Brow0 = latent + (size_t)__ldg(&idx[NPAIRS + pc0]) * 128;
    const float* Brow1 = latent + (size_t)__ldg(&idx[NPAIRS + pc1]) * 128;

    int cp_kp[2], cp_c4[2];
#pragma unroll
    for (int u = 0; u < 2; u++) {
        int i = tid + u * 256;
        cp_kp[u] = i >> 5; cp_c4[u] = (i & 31) * 4;
    }

    auto issue_chunk = [&](int gch, int buf) {
        int k = blockIdx.y * KC + (gch >> 2);
        int kpb = (gch & 3) * 16;
        const uint32_t* srcB = bilWb + ((size_t)k * 64 + kpb) * 128;
        const uint32_t* srcS = bilWs + ((size_t)k * 64 + kpb) * 128;
        uint32_t* dWb = sWbase + buf * WBUF_WORDS;
        uint32_t* dWs = dWb + 16 * 132;
        uint32_t ab = (uint32_t)__cvta_generic_to_shared(dWb);
        uint32_t as = (uint32_t)__cvta_generic_to_shared(dWs);
#pragma unroll
        for (int u = 0; u < 2; u++) {
            int off = cp_kp[u] * 132 + cp_c4[u];
            int src = cp_kp[u] * 128 + cp_c4[u];
            cp16(ab + off * 4, srcB + src);
            cp16(as + off * 4, srcS + src);
        }
        cp_commit();
    };

    // gather A pair rows, single fp16 plane
    for (int i = tid; i < 128 * 32; i += 256) {
        int p = i >> 5, l32 = i & 31;
        int c8 = l32 * 4, kp = l32 * 2;
        int pg = p0 + p; if (pg >= NPAIRS) pg = NPAIRS - 1;
        int na = __ldg(&idx[pg]);
        float4 v = __ldg((const float4*)(latent + (size_t)na * 128 + c8));
        sAh[p * 68 + kp]     = pack2h(v.x, v.y);
        sAh[p * 68 + kp + 1] = pack2h(v.z, v.w);
    }

    issue_chunk(0, 0);

    const int NCH = KC * 4;
    float acc[16][4];
    for (int gch = 0; gch < NCH; gch++) {
        if ((gch & 3) == 0) {
#pragma unroll
            for (int nt = 0; nt < 16; nt++)
#pragma unroll
                for (int j = 0; j < 4; j++) acc[nt][j] = 0.f;
        }
        if (gch + 1 < NCH) {
            issue_chunk(gch + 1, (gch + 1) & 1);
            asm volatile("cp.async.wait_group 1;");
        } else {
            asm volatile("cp.async.wait_group 0;");
        }
        __syncthreads();

        uint32_t* cWb = sWbase + (gch & 1) * WBUF_WORDS;
        uint32_t* cWs = cWb + 16 * 132;
        int k0 = (gch & 3) * 32;
#pragma unroll
        for (int ks = 0; ks < 2; ks++) {
            int kpg = (k0 >> 1) + ks * 8;
            uint32_t ah0 = sAh[(r0    ) * 68 + kpg + t4];
            uint32_t ah1 = sAh[(r0 + 8) * 68 + kpg + t4];
            uint32_t ah2 = sAh[(r0    ) * 68 + kpg + t4 + 4];
            uint32_t ah3 = sAh[(r0 + 8) * 68 + kpg + t4 + 4];
            int kp0 = ks * 8;
            const uint4* rb0 = (const uint4*)&cWb[(kp0 + t4    ) * 132 + g * 16];
            const uint4* rb1 = (const uint4*)&cWb[(kp0 + t4 + 4) * 132 + g * 16];
            const uint4* rs0 = (const uint4*)&cWs[(kp0 + t4    ) * 132 + g * 16];
            const uint4* rs1 = (const uint4*)&cWs[(kp0 + t4 + 4) * 132 + g * 16];
#pragma unroll
            for (int nt4 = 0; nt4 < 4; nt4++) {
                uint4 b0 = rb0[nt4], b1 = rb1[nt4];
                uint4 s0 = rs0[nt4], s1 = rs1[nt4];
                uint32_t bb0[4] = {b0.x, b0.y, b0.z, b0.w};
                uint32_t bb1[4] = {b1.x, b1.y, b1.z, b1.w};
                uint32_t bs0[4] = {s0.x, s0.y, s0.z, s0.w};
                uint32_t bs1[4] = {s1.x, s1.y, s1.z, s1.w};
#pragma unroll
                for (int q = 0; q < 4; q++)
                    mma_f16(acc[nt4 * 4 + q], ah0, ah1, ah2, ah3, bb0[q], bb1[q]);
#pragma unroll
                for (int q = 0; q < 4; q++)
                    mma_f16(acc[nt4 * 4 + q], ah0, ah1, ah2, ah3, bs0[q], bs1[q]);
            }
        }

        if ((gch & 3) == 3) {
            int k = blockIdx.y * KC + (gch >> 2);
            float plo = 0.f, phi = 0.f;
#pragma unroll
            for (int nt = 0; nt < 16; nt++) {
                int c = nt * 8 + 2 * t4;
                float2 b0 = __ldg((const float2*)(Brow0 + c));
                float2 b1 = __ldg((const float2*)(Brow1 + c));
                plo = fmaf(acc[nt][0], b0.x, plo);
                plo = fmaf(acc[nt][1], b0.y, plo);
                phi = fmaf(acc[nt][2], b1.x, phi);
                phi = fmaf(acc[nt][3], b1.y, phi);
            }
            plo += __shfl_xor_sync(0xffffffffu, plo, 1);
            plo += __shfl_xor_sync(0xffffffffu, plo, 2);
            phi += __shfl_xor_sync(0xffffffffu, phi, 1);
            phi += __shfl_xor_sync(0xffffffffu, phi, 2);
            if (t4 == 0) {
                if (pg0 < NPAIRS) feat[(size_t)pg0 * ZDIM + k] = plo;
                if (pg1 < NPAIRS) feat[(size_t)pg1 * ZDIM + k] = phi;
            }
        }
        __syncthreads();
    }
}

// ------------------------------------------------------------------
// Stage 2: tiny MLP on feat -> predictions
// ------------------------------------------------------------------
__device__ __forceinline__ float elu1(float x) {
    return x > 0.f ? x : expm1f(x);
}

__global__ __launch_bounds__(256) void mlp_kernel(
    const float* __restrict__ feat, const float* __restrict__ bilb,
    const float* __restrict__ dw1, const float* __restrict__ db1,
    const float* __restrict__ dw2, const float* __restrict__ db2,
    float* __restrict__ pred)
{
    int p = blockIdx.x * blockDim.x + threadIdx.x;
    if (p >= NPAIRS) return;

    float f[ZDIM];
#pragma unroll
    for (int k = 0; k < ZDIM; k++)
        f[k] = elu1(feat[(size_t)p * ZDIM + k] + __ldg(&bilb[k]));

    float o = __ldg(&db2[0]);
#pragma unroll
    for (int kk = 0; kk < ZDIM; kk++) {
        float s = __ldg(&db1[kk]);
#pragma unroll
        for (int j = 0; j < ZDIM; j++)
            s = fmaf(f[j], __ldg(&dw1[j * ZDIM + kk]), s);
        o = fmaf(elu1(s), __ldg(&dw2[kk]), o);
    }
    pred[p] = o;
}

// ------------------------------------------------------------------
extern "C" void kernel_launch(void* const* d_in, const int* in_sizes, int n_in,
                              void* d_out, int out_size)
{
    const float* features = (const float*)d_in[0];
    const int*   adj_row  = (const int*)  d_in[1];
    const int*   adj_col  = (const int*)  d_in[2];
    const float* adj_val  = (const float*)d_in[3];
    const int*   idx      = (const int*)  d_in[4];
    const float* W0   = (const float*)d_in[5];
    const float* b0   = (const float*)d_in[6];
    const float* W1   = (const float*)d_in[7];
    const float* b1   = (const float*)d_in[8];
    const float* W2   = (const float*)d_in[9];
    const float* b2   = (const float*)d_in[10];
    const float* bilw = (const float*)d_in[11];
    const float* bilb = (const float*)d_in[12];
    const float* dw1  = (const float*)d_in[13];
    const float* db1  = (const float*)d_in[14];
    const float* dw2  = (const float*)d_in[15];
    const float* db2  = (const float*)d_in[16];

    float* out    = (float*)d_out;
    float* pred   = out;            // [NPAIRS]
    float* latent = out + NPAIRS;   // [N_NODES * NHID]

    float* h;  cudaGetSymbolAddress((void**)&h,  g_buf_h);
    float* x0; cudaGetSymbolAddress((void**)&x0, g_buf_x0);
    float* x1; cudaGetSymbolAddress((void**)&x1, g_buf_x1);
    float* ft; cudaGetSymbolAddress((void**)&ft, g_feat);
    uint32_t* wb;  cudaGetSymbolAddress((void**)&wb,  g_Wb);
    uint32_t* ws;  cudaGetSymbolAddress((void**)&ws,  g_Ws);
    uint32_t* bwb; cudaGetSymbolAddress((void**)&bwb, g_bilWb);
    uint32_t* bws; cudaGetSymbolAddress((void**)&bws, g_bilWs);

    static int smem_set = 0;
    if (!smem_set) {
        cudaFuncSetAttribute(bilinear_kernel,
                             cudaFuncAttributeMaxDynamicSharedMemorySize,
                             BIL_SMEM_BYTES);
        smem_set = 1;
    }

    prep_kernel<<<PREP_BLOCKS, 256>>>(W0, W1, W2, bilw, adj_row);

    const int gemm_grid = (N_NODES + 127) / 128;
    const int spmm_grid = (N_NODES * 32 + 255) / 256;

    gemm_bf16_n128<<<gemm_grid, 256>>>(features, wb, ws, h, N_NODES, NFEAT);
    spmm_kernel<<<spmm_grid, 256>>>(h, adj_col, adj_val, b0, nullptr, x0);

    gemm_bf16_n128<<<gemm_grid, 256>>>(x0, wb + 128 * 128, ws + 128 * 128, h, N_NODES, NHID);
    spmm_kernel<<<spmm_grid, 256>>>(h, adj_col, adj_val, b1, x0, x1);

    gemm_bf16_n128<<<gemm_grid, 256>>>(x1, wb + 192 * 128, ws + 192 * 128, h, N_NODES, NHID);
    spmm_kernel<<<spmm_grid, 256>>>(h, adj_col, adj_val, b2, x1, latent);

    dim3 bil_grid((NPAIRS + 127) / 128, ZDIM / KC);
    bilinear_kernel<<<bil_grid, 256, BIL_SMEM_BYTES>>>(latent, idx, bwb, bws, ft);
    mlp_kernel<<<(NPAIRS + 255) / 256, 256>>>(ft, bilb, dw1, db1, dw2, db2, pred);
}

// round 17
// speedup vs baseline: 1.3101x; 1.0211x over previous
#include <cuda_runtime.h>
#include <cuda_fp16.h>
#include <cstdint>

#define N_NODES 50000
#define N_EDGES 800000
#define NFEAT   256
#define NHID    128
#define ZDIM    32
#define NPAIRS  10000

// ---- scratch (static device globals; no allocation at runtime) ----
__device__ float    g_buf_h [(size_t)N_NODES * NHID];
__device__ float    g_buf_x0[(size_t)N_NODES * NHID];
__device__ float    g_buf_x1[(size_t)N_NODES * NHID];
__device__ int      g_rowptr[N_NODES + 1];
__device__ float    g_feat[(size_t)NPAIRS * ZDIM];
// encoder planes: bf16x2 3-term split, fragment-remapped
__device__ uint32_t g_Wb[256 * 128], g_Ws[256 * 128];
// bilinear planes: fp16x2 big+small 2-term, fragment-remapped
__device__ uint32_t g_bilWb[(size_t)ZDIM * 64 * 128];
__device__ uint32_t g_bilWs[(size_t)ZDIM * 64 * 128];

// ------------------------------------------------------------------
__device__ __forceinline__ uint32_t pack2bf(float lo, float hi) {
    uint32_t r;
    asm("cvt.rn.bf16x2.f32 %0, %1, %2;" : "=r"(r) : "f"(hi), "f"(lo));
    return r;
}
__device__ __forceinline__ float2 unpack_bf(uint32_t p) {
    return make_float2(__uint_as_float(p << 16),
                       __uint_as_float(p & 0xffff0000u));
}
__device__ __forceinline__ uint32_t pack2h(float lo, float hi) {
    uint32_t r;
    asm("cvt.rn.f16x2.f32 %0, %1, %2;" : "=r"(r) : "f"(hi), "f"(lo));
    return r;
}
__device__ __forceinline__ float2 unpack_h(uint32_t p) {
    return make_float2(__half2float(__ushort_as_half((unsigned short)(p & 0xffff))),
                       __half2float(__ushort_as_half((unsigned short)(p >> 16))));
}

__device__ __forceinline__ void mma_bf16(
    float* d, uint32_t a0, uint32_t a1, uint32_t a2, uint32_t a3,
    uint32_t b0, uint32_t b1)
{
    asm volatile(
        "mma.sync.aligned.m16n8k16.row.col.f32.bf16.bf16.f32 "
        "{%0,%1,%2,%3}, {%4,%5,%6,%7}, {%8,%9}, {%0,%1,%2,%3};\n"
        : "+f"(d[0]), "+f"(d[1]), "+f"(d[2]), "+f"(d[3])
        : "r"(a0), "r"(a1), "r"(a2), "r"(a3), "r"(b0), "r"(b1));
}
__device__ __forceinline__ void mma_f16(
    float* d, uint32_t a0, uint32_t a1, uint32_t a2, uint32_t a3,
    uint32_t b0, uint32_t b1)
{
    asm volatile(
        "mma.sync.aligned.m16n8k16.row.col.f32.f16.f16.f32 "
        "{%0,%1,%2,%3}, {%4,%5,%6,%7}, {%8,%9}, {%0,%1,%2,%3};\n"
        : "+f"(d[0]), "+f"(d[1]), "+f"(d[2]), "+f"(d[3])
        : "r"(a0), "r"(a1), "r"(a2), "r"(a3), "r"(b0), "r"(b1));
}

// cp.async helpers
__device__ __forceinline__ void cp16(uint32_t smem_addr, const void* gptr) {
    asm volatile("cp.async.cg.shared.global [%0], [%1], 16;"
                 :: "r"(smem_addr), "l"(gptr));
}
__device__ __forceinline__ void cp_commit() {
    asm volatile("cp.async.commit_group;");
}

// ------------------------------------------------------------------
// Fused prep kernel (unchanged from R16)
// ------------------------------------------------------------------
#define PRESPLIT_ITEMS 294912
#define PRESPLIT_BLOCKS ((PRESPLIT_ITEMS + 255) / 256)
#define ROWPTR_BLOCKS   ((N_NODES + 1 + 255) / 256)
#define PREP_BLOCKS     (PRESPLIT_BLOCKS + ROWPTR_BLOCKS)

__global__ void prep_kernel(const float* __restrict__ W0,
                            const float* __restrict__ W1,
                            const float* __restrict__ W2,
                            const float* __restrict__ bilw,
                            const int* __restrict__ row)
{
    if (blockIdx.x >= PRESPLIT_BLOCKS) {
        int r = (blockIdx.x - PRESPLIT_BLOCKS) * blockDim.x + threadIdx.x;
        if (r > N_NODES) return;
        int lo = 0, hi = N_EDGES;
        while (lo < hi) {
            int mid = (lo + hi) >> 1;
            if (row[mid] < r) lo = mid + 1; else hi = mid;
        }
        g_rowptr[r] = lo;
        return;
    }
    int i = blockIdx.x * blockDim.x + threadIdx.x;
    if (i < 32768) {
        const float* src; uint32_t* dstB; uint32_t* dstS; int j;
        if (i < 16384)      { src = W0; dstB = g_Wb;             dstS = g_Ws;             j = i; }
        else if (i < 24576) { src = W1; dstB = g_Wb + 128 * 128; dstS = g_Ws + 128 * 128; j = i - 16384; }
        else                { src = W2; dstB = g_Wb + 192 * 128; dstS = g_Ws + 192 * 128; j = i - 24576; }
        int kp = j >> 7, c = j & 127;
        float lo = src[(size_t)kp * 256 + c];
        float hi = src[(size_t)kp * 256 + 128 + c];
        uint32_t pb = pack2bf(lo, hi);
        float2 f = unpack_bf(pb);
        int jr = kp * 128 + (c & 7) * 16 + (c >> 3);
        dstB[jr] = pb;
        dstS[jr] = pack2bf(lo - f.x, hi - f.y);
    } else if (i < 294912) {
        int j = i - 32768;
        int kp = j >> 7, c = j & 127;
        float lo = bilw[(size_t)kp * 256 + c];
        float hi = bilw[(size_t)kp * 256 + 128 + c];
        uint32_t ph = pack2h(lo, hi);
        float2 f = unpack_h(ph);
        int jr = kp * 128 + (c & 7) * 16 + (c >> 3);
        g_bilWb[jr] = ph;
        g_bilWs[jr] = pack2h(lo - f.x, hi - f.y);
    }
}

// ------------------------------------------------------------------
// Encoder GEMM: BM=64, 256 thr, warp = (slab, col-half), acc[8][4].
// 3 CTAs/SM (24 warps) for issue-rate headroom.
// ------------------------------------------------------------------
__global__ __launch_bounds__(256, 3) void gemm_bf16_n128(
    const float* __restrict__ A,
    const uint32_t* __restrict__ Wb, const uint32_t* __restrict__ Ws,
    float* __restrict__ C, int M, int K)
{
    __shared__ uint32_t sAb[64][17], sAs[64][17];
    __shared__ uint32_t sBb[16 * 132], sBs[16 * 132];

    int tid  = threadIdx.x;
    int lane = tid & 31, warp = tid >> 5;
    int g = lane >> 2, t4 = lane & 3;
    int slab = warp >> 1, half = warp & 1;
    int r0 = slab * 16 + g;
    int row0 = blockIdx.x * 64;

    float acc[8][4];
#pragma unroll
    for (int nt = 0; nt < 8; nt++)
#pragma unroll
        for (int j = 0; j < 4; j++) acc[nt][j] = 0.f;

    for (int k0 = 0; k0 < K; k0 += 32) {
        __syncthreads();
        // A tile: 64 rows x 32 k (512 float4 loads, 2/thread)
#pragma unroll
        for (int u = 0; u < 2; u++) {
            int i = tid + u * 256;
            int r = i >> 3, q = i & 7;
            int gr = row0 + r;
            float4 v = (gr < M)
                ? __ldg((const float4*)(A + (size_t)gr * K + k0 + 4 * q))
                : make_float4(0.f, 0.f, 0.f, 0.f);
            uint32_t p0 = pack2bf(v.x, v.y);
            uint32_t p1 = pack2bf(v.z, v.w);
            float2 f0 = unpack_bf(p0), f1 = unpack_bf(p1);
            sAb[r][2 * q]     = p0;
            sAb[r][2 * q + 1] = p1;
            sAs[r][2 * q]     = pack2bf(v.x - f0.x, v.y - f0.y);
            sAs[r][2 * q + 1] = pack2bf(v.z - f1.x, v.w - f1.y);
        }
        // B tile (full 128 cols, shared by both halves)
        {
            const uint32_t* srcB = Wb + (size_t)(k0 >> 1) * 128;
            const uint32_t* srcS = Ws + (size_t)(k0 >> 1) * 128;
#pragma unroll
            for (int u = 0; u < 2; u++) {
                int i = tid + u * 256;
                int kp = i >> 5, c4 = (i & 31) * 4;
                uint4 vb = __ldg((const uint4*)(srcB + kp * 128 + c4));
                uint4 vs = __ldg((const uint4*)(srcS + kp * 128 + c4));
                *(uint4*)&sBb[kp * 132 + c4] = vb;
                *(uint4*)&sBs[kp * 132 + c4] = vs;
            }
        }
        __syncthreads();

#pragma unroll
        for (int ks = 0; ks < 2; ks++) {
            int kp0 = ks * 8;
            uint32_t ab0 = sAb[r0    ][kp0 + t4];
            uint32_t ab1 = sAb[r0 + 8][kp0 + t4];
            uint32_t ab2 = sAb[r0    ][kp0 + t4 + 4];
            uint32_t ab3 = sAb[r0 + 8][kp0 + t4 + 4];
            uint32_t as0 = sAs[r0    ][kp0 + t4];
            uint32_t as1 = sAs[r0 + 8][kp0 + t4];
            uint32_t as2 = sAs[r0    ][kp0 + t4 + 4];
            uint32_t as3 = sAs[r0 + 8][kp0 + t4 + 4];
            // fragpos(e) = (e&7)*16 + (e>>3); e = half*64 + nt*8 + g
            // -> word = g*16 + half*8 + nt  (nt 0..7 = two uint4s)
            const uint4* rb0 = (const uint4*)&sBb[(kp0 + t4    ) * 132 + g * 16 + half * 8];
            const uint4* rb1 = (const uint4*)&sBb[(kp0 + t4 + 4) * 132 + g * 16 + half * 8];
            const uint4* rs0 = (const uint4*)&sBs[(kp0 + t4    ) * 132 + g * 16 + half * 8];
            const uint4* rs1 = (const uint4*)&sBs[(kp0 + t4 + 4) * 132 + g * 16 + half * 8];
#pragma unroll
            for (int nt4 = 0; nt4 < 2; nt4++) {
                uint4 b0 = rb0[nt4], b1 = rb1[nt4];
                uint4 s0 = rs0[nt4], s1 = rs1[nt4];
                uint32_t bb0[4] = {b0.x, b0.y, b0.z, b0.w};
                uint32_t bb1[4] = {b1.x, b1.y, b1.z, b1.w};
                uint32_t bs0[4] = {s0.x, s0.y, s0.z, s0.w};
                uint32_t bs1[4] = {s1.x, s1.y, s1.z, s1.w};
#pragma unroll
                for (int q = 0; q < 4; q++)
                    mma_bf16(acc[nt4 * 4 + q], ab0, ab1, ab2, ab3, bb0[q], bb1[q]);
#pragma unroll
                for (int q = 0; q < 4; q++)
                    mma_bf16(acc[nt4 * 4 + q], as0, as1, as2, as3, bb0[q], bb1[q]);
#pragma unroll
                for (int q = 0; q < 4; q++)
                    mma_bf16(acc[nt4 * 4 + q], ab0, ab1, ab2, ab3, bs0[q], bs1[q]);
            }
        }
    }

#pragma unroll
    for (int nt = 0; nt < 8; nt++) {
        int c = half * 64 + nt * 8 + 2 * t4;
        int gr0 = row0 + r0, gr1 = gr0 + 8;
        if (gr0 < M)
            *(float2*)(C + (size_t)gr0 * 128 + c) = make_float2(acc[nt][0], acc[nt][1]);
        if (gr1 < M)
            *(float2*)(C + (size_t)gr1 * 128 + c) = make_float2(acc[nt][2], acc[nt][3]);
    }
}

// ------------------------------------------------------------------
// SpMM: one warp per destination row, 4-edge unroll (known-good)
// ------------------------------------------------------------------
__global__ __launch_bounds__(256) void spmm_kernel(
    const float* __restrict__ H, const int* __restrict__ col,
    const float* __restrict__ val, const float* __restrict__ bias,
    const float* __restrict__ res, float* __restrict__ out)
{
    int w = (blockIdx.x * blockDim.x + threadIdx.x) >> 5;
    if (w >= N_NODES) return;
    int lane = threadIdx.x & 31;

    const float4* Hv = (const float4*)H;
    float4 acc = make_float4(0.f, 0.f, 0.f, 0.f);
    int s = g_rowptr[w], e = g_rowptr[w + 1];
    int i = s;
    for (; i + 3 < e; i += 4) {
        int cc[4]; float vv[4]; float4 hh[4];
#pragma unroll
        for (int u = 0; u < 4; u++) { cc[u] = __ldg(&col[i + u]); vv[u] = __ldg(&val[i + u]); }
#pragma unroll
        for (int u = 0; u < 4; u++) hh[u] = __ldg(&Hv[(size_t)cc[u] * 32 + lane]);
#pragma unroll
        for (int u = 0; u < 4; u++) {
            acc.x = fmaf(vv[u], hh[u].x, acc.x);
            acc.y = fmaf(vv[u], hh[u].y, acc.y);
            acc.z = fmaf(vv[u], hh[u].z, acc.z);
            acc.w = fmaf(vv[u], hh[u].w, acc.w);
        }
    }
    for (; i < e; i++) {
        int   c0 = __ldg(&col[i]);
        float v0 = __ldg(&val[i]);
        float4 h0 = __ldg(&Hv[(size_t)c0 * 32 + lane]);
        acc.x = fmaf(v0, h0.x, acc.x); acc.y = fmaf(v0, h0.y, acc.y);
        acc.z = fmaf(v0, h0.z, acc.z); acc.w = fmaf(v0, h0.w, acc.w);
    }

    float4 bb = __ldg(&((const float4*)bias)[lane]);
    float4 o;
    o.x = fmaxf(acc.x + bb.x, 0.f);
    o.y = fmaxf(acc.y + bb.y, 0.f);
    o.z = fmaxf(acc.z + bb.z, 0.f);
    o.w = fmaxf(acc.w + bb.w, 0.f);
    size_t vbase = (size_t)w * 32 + lane;
    if (res) {
        float4 rv = __ldg(&((const float4*)res)[vbase]);
        o.x += rv.x; o.y += rv.y; o.z += rv.z; o.w += rv.w;
    }
    ((float4*)out)[vbase] = o;
}

// ------------------------------------------------------------------
// Bilinear stage 1: fp16 2-term, 64 pairs/CTA, warp = (slab, col-half),
// acc[8][4]; col-half partials combined via sPart. 3 CTAs/SM.
// ------------------------------------------------------------------
#define KC 2
#define WBUF_WORDS (2 * 16 * 132)
#define BIL_SMEM_WORDS (64 * 68 + 2 * WBUF_WORDS + 128)
#define BIL_SMEM_BYTES (BIL_SMEM_WORDS * 4)

__global__ __launch_bounds__(256, 3) void bilinear_kernel(
    const float* __restrict__ latent, const int* __restrict__ idx,
    const uint32_t* __restrict__ bilWb, const uint32_t* __restrict__ bilWs,
    float* __restrict__ feat)
{
    extern __shared__ uint32_t smem[];
    uint32_t* sAh = smem;                      // [64][68] fp16x2 A plane
    uint32_t* sWbase = sAh + 64 * 68;          // 2 x {Wh[16*132], Ws[16*132]}
    float*    sPart = (float*)(sWbase + 2 * WBUF_WORDS);  // [2][64]

    int tid  = threadIdx.x;
    int lane = tid & 31, warp = tid >> 5;
    int p0 = blockIdx.x * 64;
    int g = lane >> 2, t4 = lane & 3;
    int slab = warp >> 1, half = warp & 1;
    int r0 = slab * 16 + g;

    int pg0 = p0 + r0, pg1 = p0 + r0 + 8;
    int pc0 = pg0 < NPAIRS ? pg0 : NPAIRS - 1;
    int pc1 = pg1 < NPAIRS ? pg1 : NPAIRS - 1;
    const float* Brow0 = latent + (size_t)__ldg(&idx[NPAIRS + pc0]) * 128;
    const float* Brow1 = latent + (size_t)__ldg(&idx[NPAIRS + pc1]) * 128;

    int cp_kp[2], cp_c4[2];
#pragma unroll
    for (int u = 0; u < 2; u++) {
        int i = tid + u * 256;
        cp_kp[u] = i >> 5; cp_c4[u] = (i & 31) * 4;
    }

    auto issue_chunk = [&](int gch, int buf) {
        int k = blockIdx.y * KC + (gch >> 2);
        int kpb = (gch & 3) * 16;
        const uint32_t* srcB = bilWb + ((size_t)k * 64 + kpb) * 128;
        const uint32_t* srcS = bilWs + ((size_t)k * 64 + kpb) * 128;
        uint32_t* dWb = sWbase + buf * WBUF_WORDS;
        uint32_t* dWs = dWb + 16 * 132;
        uint32_t ab = (uint32_t)__cvta_generic_to_shared(dWb);
        uint32_t as = (uint32_t)__cvta_generic_to_shared(dWs);
#pragma unroll
        for (int u = 0; u < 2; u++) {
            int off = cp_kp[u] * 132 + cp_c4[u];
            int src = cp_kp[u] * 128 + cp_c4[u];
            cp16(ab + off * 4, srcB + src);
            cp16(as + off * 4, srcS + src);
        }
        cp_commit();
    };

    // gather A pair rows (64 rows x 32 quads = 2048 items), fp16 plane
    for (int i = tid; i < 64 * 32; i += 256) {
        int p = i >> 5, l32 = i & 31;
        int c8 = l32 * 4, kp = l32 * 2;
        int pg = p0 + p; if (pg >= NPAIRS) pg = NPAIRS - 1;
        int na = __ldg(&idx[pg]);
        float4 v = __ldg((const float4*)(latent + (size_t)na * 128 + c8));
        sAh[p * 68 + kp]     = pack2h(v.x, v.y);
        sAh[p * 68 + kp + 1] = pack2h(v.z, v.w);
    }

    issue_chunk(0, 0);

    const int NCH = KC * 4;
    float acc[8][4];
    for (int gch = 0; gch < NCH; gch++) {
        if ((gch & 3) == 0) {
#pragma unroll
            for (int nt = 0; nt < 8; nt++)
#pragma unroll
                for (int j = 0; j < 4; j++) acc[nt][j] = 0.f;
        }
        if (gch + 1 < NCH) {
            issue_chunk(gch + 1, (gch + 1) & 1);
            asm volatile("cp.async.wait_group 1;");
        } else {
            asm volatile("cp.async.wait_group 0;");
        }
        __syncthreads();

        uint32_t* cWb = sWbase + (gch & 1) * WBUF_WORDS;
        uint32_t* cWs = cWb + 16 * 132;
        int k0 = (gch & 3) * 32;
#pragma unroll
        for (int ks = 0; ks < 2; ks++) {
            int kpg = (k0 >> 1) + ks * 8;
            uint32_t ah0 = sAh[(r0    ) * 68 + kpg + t4];
            uint32_t ah1 = sAh[(r0 + 8) * 68 + kpg + t4];
            uint32_t ah2 = sAh[(r0    ) * 68 + kpg + t4 + 4];
            uint32_t ah3 = sAh[(r0 + 8) * 68 + kpg + t4 + 4];
            int kp0 = ks * 8;
            const uint4* rb0 = (const uint4*)&cWb[(kp0 + t4    ) * 132 + g * 16 + half * 8];
            const uint4* rb1 = (const uint4*)&cWb[(kp0 + t4 + 4) * 132 + g * 16 + half * 8];
            const uint4* rs0 = (const uint4*)&cWs[(kp0 + t4    ) * 132 + g * 16 + half * 8];
            const uint4* rs1 = (const uint4*)&cWs[(kp0 + t4 + 4) * 132 + g * 16 + half * 8];
#pragma unroll
            for (int nt4 = 0; nt4 < 2; nt4++) {
                uint4 b0 = rb0[nt4], b1 = rb1[nt4];
                uint4 s0 = rs0[nt4], s1 = rs1[nt4];
                uint32_t bb0[4] = {b0.x, b0.y, b0.z, b0.w};
                uint32_t bb1[4] = {b1.x, b1.y, b1.z, b1.w};
                uint32_t bs0[4] = {s0.x, s0.y, s0.z, s0.w};
                uint32_t bs1[4] = {s1.x, s1.y, s1.z, s1.w};
#pragma unroll
                for (int q = 0; q < 4; q++)
                    mma_f16(acc[nt4 * 4 + q], ah0, ah1, ah2, ah3, bb0[q], bb1[q]);
#pragma unroll
                for (int q = 0; q < 4; q++)
                    mma_f16(acc[nt4 * 4 + q], ah0, ah1, ah2, ah3, bs0[q], bs1[q]);
            }
        }

        if ((gch & 3) == 3) {
            int k = blockIdx.y * KC + (gch >> 2);
            float plo = 0.f, phi = 0.f;
#pragma unroll
            for (int nt = 0; nt < 8; nt++) {
                int c = half * 64 + nt * 8 + 2 * t4;
                float2 b0 = __ldg((const float2*)(Brow0 + c));
                float2 b1 = __ldg((const float2*)(Brow1 + c));
                plo = fmaf(acc[nt][0], b0.x, plo);
                plo = fmaf(acc[nt][1], b0.y, plo);
                phi = fmaf(acc[nt][2], b1.x, phi);
                phi = fmaf(acc[nt][3], b1.y, phi);
            }
            plo += __shfl_xor_sync(0xffffffffu, plo, 1);
            plo += __shfl_xor_sync(0xffffffffu, plo, 2);
            phi += __shfl_xor_sync(0xffffffffu, phi, 1);
            phi += __shfl_xor_sync(0xffffffffu, phi, 2);
            if (t4 == 0) {
                sPart[half * 64 + r0]     = plo;
                sPart[half * 64 + r0 + 8] = phi;
            }
            __syncthreads();
            if (tid < 64) {
                int pg = p0 + tid;
                if (pg < NPAIRS)
                    feat[(size_t)pg * ZDIM + k] = sPart[tid] + sPart[64 + tid];
            }
        }
        __syncthreads();
    }
}

// ------------------------------------------------------------------
// Stage 2: tiny MLP on feat -> predictions
// ------------------------------------------------------------------
__device__ __forceinline__ float elu1(float x) {
    return x > 0.f ? x : expm1f(x);
}

__global__ __launch_bounds__(256) void mlp_kernel(
    const float* __restrict__ feat, const float* __restrict__ bilb,
    const float* __restrict__ dw1, const float* __restrict__ db1,
    const float* __restrict__ dw2, const float* __restrict__ db2,
    float* __restrict__ pred)
{
    int p = blockIdx.x * blockDim.x + threadIdx.x;
    if (p >= NPAIRS) return;

    float f[ZDIM];
#pragma unroll
    for (int k = 0; k < ZDIM; k++)
        f[k] = elu1(feat[(size_t)p * ZDIM + k] + __ldg(&bilb[k]));

    float o = __ldg(&db2[0]);
#pragma unroll
    for (int kk = 0; kk < ZDIM; kk++) {
        float s = __ldg(&db1[kk]);
#pragma unroll
        for (int j = 0; j < ZDIM; j++)
            s = fmaf(f[j], __ldg(&dw1[j * ZDIM + kk]), s);
        o = fmaf(elu1(s), __ldg(&dw2[kk]), o);
    }
    pred[p] = o;
}

// ------------------------------------------------------------------
extern "C" void kernel_launch(void* const* d_in, const int* in_sizes, int n_in,
                              void* d_out, int out_size)
{
    const float* features = (const float*)d_in[0];
    const int*   adj_row  = (const int*)  d_in[1];
    const int*   adj_col  = (const int*)  d_in[2];
    const float* adj_val  = (const float*)d_in[3];
    const int*   idx      = (const int*)  d_in[4];
    const float* W0   = (const float*)d_in[5];
    const float* b0   = (const float*)d_in[6];
    const float* W1   = (const float*)d_in[7];
    const float* b1   = (const float*)d_in[8];
    const float* W2   = (const float*)d_in[9];
    const float* b2   = (const float*)d_in[10];
    const float* bilw = (const float*)d_in[11];
    const float* bilb = (const float*)d_in[12];
    const float* dw1  = (const float*)d_in[13];
    const float* db1  = (const float*)d_in[14];
    const float* dw2  = (const float*)d_in[15];
    const float* db2  = (const float*)d_in[16];

    float* out    = (float*)d_out;
    float* pred   = out;            // [NPAIRS]
    float* latent = out + NPAIRS;   // [N_NODES * NHID]

    float* h;  cudaGetSymbolAddress((void**)&h,  g_buf_h);
    float* x0; cudaGetSymbolAddress((void**)&x0, g_buf_x0);
    float* x1; cudaGetSymbolAddress((void**)&x1, g_buf_x1);
    float* ft; cudaGetSymbolAddress((void**)&ft, g_feat);
    uint32_t* wb;  cudaGetSymbolAddress((void**)&wb,  g_Wb);
    uint32_t* ws;  cudaGetSymbolAddress((void**)&ws,  g_Ws);
    uint32_t* bwb; cudaGetSymbolAddress((void**)&bwb, g_bilWb);
    uint32_t* bws; cudaGetSymbolAddress((void**)&bws, g_bilWs);

    static int smem_set = 0;
    if (!smem_set) {
        cudaFuncSetAttribute(bilinear_kernel,
                             cudaFuncAttributeMaxDynamicSharedMemorySize,
                             BIL_SMEM_BYTES);
        smem_set = 1;
    }

    prep_kernel<<<PREP_BLOCKS, 256>>>(W0, W1, W2, bilw, adj_row);

    const int gemm_grid = (N_NODES + 63) / 64;
    const int spmm_grid = (N_NODES * 32 + 255) / 256;

    gemm_bf16_n128<<<gemm_grid, 256>>>(features, wb, ws, h, N_NODES, NFEAT);
    spmm_kernel<<<spmm_grid, 256>>>(h, adj_col, adj_val, b0, nullptr, x0);

    gemm_bf16_n128<<<gemm_grid, 256>>>(x0, wb + 128 * 128, ws + 128 * 128, h, N_NODES, NHID);
    spmm_kernel<<<spmm_grid, 256>>>(h, adj_col, adj_val, b1, x0, x1);

    gemm_bf16_n128<<<gemm_grid, 256>>>(x1, wb + 192 * 128, ws + 192 * 128, h, N_NODES, NHID);
    spmm_kernel<<<spmm_grid, 256>>>(h, adj_col, adj_val, b2, x1, latent);

    dim3 bil_grid((NPAIRS + 63) / 64, ZDIM / KC);
    bilinear_kernel<<<bil_grid, 256, BIL_SMEM_BYTES>>>(latent, idx, bwb, bws, ft);
    mlp_kernel<<<(NPAIRS + 255) / 256, 256>>>(ft, bilb, dw1, db1, dw2, db2, pred);
}